// round 7
// baseline (speedup 1.0000x reference)
#include <cuda_runtime.h>

#define NS (1<<20)

// ---- device scratch (static, allocation-free) ----
__device__ float g_T0[NS];
__device__ float g_T1[NS];
__device__ float g_A[NS];      // T2 (pair*4096) early; then A[P01][bond] 1024x1024
__device__ float g_Cm[NS];     // Ct[P23][bond]  (1024x1024, transposed C)
__device__ float g_psi[NS];    // statevector (in-place for sweeps)
__device__ float g_R[1024];    // 32x32 row-chain operator [out][in]
__device__ float g_C16[256];   // 16x16 column-chain operator
__device__ float g_K[10*4096]; // per-column pair tensors K_j
__device__ float g_KK[2*65536];// combined column-pair operators KK23 per pair

// ---- PDL helpers ----
__device__ __forceinline__ void pdl_wait(){
#if __CUDA_ARCH__ >= 900
    cudaGridDependencySynchronize();
    cudaTriggerProgrammaticLaunchCompletion();
#endif
}

// ---- packed fp32x2 helpers ----
__device__ __forceinline__ unsigned long long pk2(float x, float y){
    unsigned long long r; asm("mov.b64 %0,{%1,%2};" : "=l"(r) : "f"(x), "f"(y)); return r;
}
__device__ __forceinline__ float2 upk2(unsigned long long v){
    float2 r; asm("mov.b64 {%0,%1},%2;" : "=f"(r.x), "=f"(r.y) : "l"(v)); return r;
}
__device__ __forceinline__ unsigned long long fma2(unsigned long long a,
        unsigned long long b, unsigned long long c){
    unsigned long long d;
    asm("fma.rn.f32x2 %0,%1,%2,%3;" : "=l"(d) : "l"(a), "l"(b), "l"(c));
    return d;
}

__device__ __forceinline__ float peps_el(const float* __restrict__ peps,
                                         int i,int j,int p,int u,int d,int l,int r){
    return peps[(((((i*5+j)*2+p)*4+u)*4+d)*4+l)*4+r];
}

// ------------- prep: blocks 0..9 compute K_j; block 10 builds R and C16 -------------
__global__ void prep_kernel(const float* __restrict__ peps, const float* __restrict__ gate){
    pdl_wait();
    int t = threadIdx.x;  // 256
    if (blockIdx.x < 10){
        int blk = blockIdx.x;
        int pair = blk/5, j = blk%5;
        int L = (j==0)?1:4, R = (j==4)?1:4;
        int nk = 16*L*L*R*R;
        float* Kg = g_K + blk*4096;
        for (int e=t; e<nk; e+=256){
            int tt=e;
            int rb=tt%R; tt/=R; int ra=tt%R; tt/=R;
            int lb=tt%L; tt/=L; int la=tt%L; tt/=L;
            int mid=tt&3; tt>>=2;
            int pb=tt&1; int pa=tt>>1;
            float s=0.f;
            if (pair==0){
                #pragma unroll
                for(int m=0;m<4;m++)
                    s += peps_el(peps,0,j,pa,0,m,la,ra)*peps_el(peps,1,j,pb,m,mid,lb,rb);
            } else {
                #pragma unroll
                for(int m=0;m<4;m++)
                    s += peps_el(peps,2,j,pa,mid,m,la,ra)*peps_el(peps,3,j,pb,m,0,lb,rb);
            }
            Kg[e]=s;
        }
        return;
    }
    // ---- block 10: build R (32x32) and C16 (16x16) with 256 threads ----
    __shared__ float g[16];
    __shared__ float A0[1024];
    __shared__ float A1[1024];
    if (t<16) g[t]=gate[t];
    for (int e=t;e<1024;e+=256) A0[e] = ((e>>5)==(e&31)) ? 1.0f : 0.0f;
    __syncthreads();
    #pragma unroll
    for (int k=0;k<4;k++){
        const float* cur = (k&1)? A1 : A0;
        float* nxt       = (k&1)? A0 : A1;
        int hb=4-k, lb=3-k;
        for (int e=t;e<1024;e+=256){
            int rp=e>>5, c=e&31;
            int i1p=(rp>>hb)&1, i2p=(rp>>lb)&1;
            int base = rp & ~((1<<hb)|(1<<lb));
            float acc=0.f;
            #pragma unroll
            for(int i1=0;i1<2;i1++)
            #pragma unroll
            for(int i2=0;i2<2;i2++)
                acc += g[(i1p*2+i2p)*4+(i1*2+i2)] * cur[(base|(i1<<hb)|(i2<<lb))*32 + c];
            nxt[e]=acc;
        }
        __syncthreads();
    }
    for (int e=t;e<1024;e+=256) g_R[e]=A0[e];
    __syncthreads();
    A0[t] = ((t>>4)==(t&15)) ? 1.0f : 0.0f;
    __syncthreads();
    #pragma unroll
    for (int k=0;k<3;k++){
        const float* cur=(k&1)?A1:A0;
        float* nxt      =(k&1)?A0:A1;
        int hb=3-k, lb=2-k;
        int rp=t>>4, c=t&15;
        int i1p=(rp>>hb)&1,i2p=(rp>>lb)&1;
        int base = rp & ~((1<<hb)|(1<<lb));
        float acc=0.f;
        #pragma unroll
        for(int i1=0;i1<2;i1++)
        #pragma unroll
        for(int i2=0;i2<2;i2++)
            acc += g[(i1p*2+i2p)*4+(i1*2+i2)]*cur[(base|(i1<<hb)|(i2<<lb))*16+c];
        __syncthreads();
        nxt[t]=acc;
        __syncthreads();
    }
    g_C16[t]=A1[t];
}

// ------------- kkprep: blocks 0..255 build KK23 slices; block 256 builds T2 -------------
__global__ void kkprep_kernel(){
    pdl_wait();
    int t = threadIdx.x;          // 256
    int pair = blockIdx.y;
    const float* Kbase = g_K + pair*5*4096;
    if (blockIdx.x < 256){
        int pb = blockIdx.x;
        int pd = pb&15, pbb = (pb>>4)&3, pa = pb>>6;
        int kb2 = ((pa>>1)*2+(pbb>>1))*4+(pd>>2);
        int kb3 = ((pa&1)*2+(pbb&1))*4+(pd&3);
        __shared__ float K2s[256], K3s[256];
        K2s[t] = Kbase[2*4096 + kb2*256 + t];
        K3s[t] = Kbase[3*4096 + kb3*256 + t];
        __syncthreads();
        int l = t>>4, r = t&15;
        float acc=0.f;
        #pragma unroll
        for (int m=0;m<16;m++) acc += K2s[l*16+m]*K3s[m*16+r];
        g_KK[pair*65536 + pb*256 + t] = acc;
        return;
    }
    __shared__ float K0s[256];
    __shared__ float K1s[4096];
    K0s[t]=Kbase[t];
    for (int e=t;e<4096;e+=256) K1s[e]=Kbase[4096+e];
    __syncthreads();
    int abc = t;
    int a2=abc>>6, b2=(abc>>4)&3, c2=abc&15;
    int kb0 = ((a2>>1)*2+(b2>>1))*4 + (c2>>2);
    int kb1 = ((a2&1)*2+(b2&1))*4 + (c2&3);
    float* T2 = g_A + pair*4096;
    #pragma unroll
    for (int r=0;r<16;r++){
        float acc=0.f;
        #pragma unroll
        for (int m=0;m<16;m++) acc += K0s[kb0*16+m]*K1s[(kb1*16+m)*16+r];
        T2[abc*16+r]=acc;
    }
}

// ------------- fold23: T4 = T2 x KK23 ; grid (256, 2) -------------
__global__ __launch_bounds__(256) void fold23_kernel(){
    pdl_wait();
    int t = threadIdx.x;
    int pb = blockIdx.x, pair = blockIdx.y;
    int pd = pb&15, pbb = (pb>>4)&3, pa = pb>>6;
    __shared__ float Ts[256*20];
    __shared__ float Ks[256];
    const float* T2 = g_A + pair*4096;
    for (int e=t;e<4096;e+=256) Ts[(e>>4)*20 + (e&15)] = T2[e];
    Ks[t] = g_KK[pair*65536 + pb*256 + t];
    __syncthreads();
    float* Tout = pair? g_T1 : g_T0;
    int a2=t>>6, b2=(t>>4)&3, c2=t&15;
    float tv[16];
    #pragma unroll
    for (int l=0;l<16;l++) tv[l]=Ts[t*20+l];
    long obase = ((((long)(a2*4+pa)*16 + b2*4+pbb)*256) + c2*16+pd)*16;
    #pragma unroll
    for (int r4=0;r4<4;r4++){
        float4 o; float* po=(float*)&o;
        #pragma unroll
        for (int q=0;q<4;q++){
            int r=r4*4+q;
            float acc=0.f;
            #pragma unroll
            for (int l=0;l<16;l++) acc += tv[l]*Ks[l*16+r];
            po[q]=acc;
        }
        *(float4*)&Tout[obase + r4*4] = o;
    }
}

// ------------- fold4: final column -> A / Ct ; grid (256, 2), thread = c -------------
__global__ __launch_bounds__(256) void fold4_kernel(){
    int c = threadIdx.x;
    int a = blockIdx.x >> 4, b = blockIdx.x & 15;
    int pair = blockIdx.y;
    __shared__ float K4s[256];
    K4s[c] = g_K[(pair*5+4)*4096 + c];   // written by prep (>=2 kernels back) - prologue-safe
    __syncthreads();
    pdl_wait();
    const float* Tin = pair? g_T1 : g_T0;
    const float* tp = &Tin[(((long)(a*16+b)*256)+c)*16];
    float tv[16];
    #pragma unroll
    for (int l4=0;l4<4;l4++){
        float4 v = *(const float4*)&tp[l4*4];
        tv[l4*4+0]=v.x; tv[l4*4+1]=v.y; tv[l4*4+2]=v.z; tv[l4*4+3]=v.w;
    }
    if (pair==0){
        long base = (long)a*65536 + (long)b*2048 + c*4;
        #pragma unroll
        for (int p0=0;p0<2;p0++)
        #pragma unroll
        for (int p1=0;p1<2;p1++){
            float4 o; float* po=(float*)&o;
            #pragma unroll
            for (int d1=0;d1<4;d1++){
                int kb=(p0*2+p1)*4+d1;
                float acc=0.f;
                #pragma unroll
                for (int l=0;l<16;l++) acc += tv[l]*K4s[kb*16+l];
                po[d1]=acc;
            }
            *(float4*)&g_A[base + p0*32768 + p1*1024] = o;
        }
    } else {
        #pragma unroll
        for (int p0=0;p0<2;p0++)
        #pragma unroll
        for (int p1=0;p1<2;p1++){
            float4 o; float* po=(float*)&o;
            #pragma unroll
            for (int d1=0;d1<4;d1++){
                int kb=(p0*2+p1)*4+d1;
                float acc=0.f;
                #pragma unroll
                for (int l=0;l<16;l++) acc += tv[l]*K4s[kb*16+l];
                po[d1]=acc;
            }
            long col = (long)(a*64 + p0*32 + b*2 + p1);
            *(float4*)&g_Cm[col*1024 + c*4] = o;
        }
    }
}

// ------------- psi = A(1024x1024) @ Ct^T : packed f32x2 FFMA -------------
__global__ __launch_bounds__(256) void sgemm_kernel(const float* __restrict__ A,
        const float* __restrict__ Bt, float* __restrict__ Cout){
    __shared__ __align__(16) float As2[16][132];
    __shared__ __align__(16) float Bs[16][68];
    int bx=blockIdx.x, by=blockIdx.y;
    int tid=threadIdx.x;
    int tx=tid&15, ty=tid>>4;
    unsigned long long acc2[4][2];
    #pragma unroll
    for(int i=0;i<4;i++){ acc2[i][0]=0ull; acc2[i][1]=0ull; }
    pdl_wait();
    const float* Ablk = A + (long)(by*64)*1024;
    const float* Btblk = Bt + (long)(bx*64)*1024;
    for (int k0=0;k0<1024;k0+=16){
        #pragma unroll
        for (int e=0;e<4;e++){
            int idx = tid + e*256;
            int m = idx>>4, k = idx&15;
            float v = Ablk[(long)m*1024 + k0 + k];
            *(float2*)&As2[k][2*m] = make_float2(v,v);
        }
        #pragma unroll
        for (int e=0;e<4;e++){
            int idx = tid + e*256;
            int n = idx>>4, k = idx&15;
            Bs[k][n] = Btblk[(long)n*1024 + k0 + k];
        }
        __syncthreads();
        #pragma unroll
        for (int k=0;k<16;k++){
            ulonglong2 a01 = *(const ulonglong2*)&As2[k][ty*8];
            ulonglong2 a23 = *(const ulonglong2*)&As2[k][ty*8+4];
            ulonglong2 bb  = *(const ulonglong2*)&Bs[k][tx*4];
            acc2[0][0]=fma2(a01.x, bb.x, acc2[0][0]); acc2[0][1]=fma2(a01.x, bb.y, acc2[0][1]);
            acc2[1][0]=fma2(a01.y, bb.x, acc2[1][0]); acc2[1][1]=fma2(a01.y, bb.y, acc2[1][1]);
            acc2[2][0]=fma2(a23.x, bb.x, acc2[2][0]); acc2[2][1]=fma2(a23.x, bb.y, acc2[2][1]);
            acc2[3][0]=fma2(a23.y, bb.x, acc2[3][0]); acc2[3][1]=fma2(a23.y, bb.y, acc2[3][1]);
        }
        __syncthreads();
    }
    #pragma unroll
    for(int i=0;i<4;i++){
        float2 c0 = upk2(acc2[i][0]);
        float2 c1 = upk2(acc2[i][1]);
        float4 o = make_float4(c0.x, c0.y, c1.x, c1.y);
        *(float4*)&Cout[(long)(by*64+ty*4+i)*1024 + bx*64+tx*4] = o;
    }
}

// ------------- fused horizontal low: bits [5-9] and [0-4], in-place -------------
__global__ __launch_bounds__(256) void hlow_kernel(float* __restrict__ psi){
    __shared__ __align__(16) float T[32*36];
    __shared__ __align__(16) float Usm[32*36];
    __shared__ __align__(16) float Rs[1024];
    __shared__ float RsT[1024];
    int tid=threadIdx.x;
    for (int e=tid;e<1024;e+=256){
        float v = g_R[e];                 // prep output: prologue-safe
        Rs[e]=v;
        RsT[(e&31)*32 + (e>>5)] = v;
    }
    pdl_wait();
    unsigned base = blockIdx.x*1024u;
    #pragma unroll
    for (int it=0;it<4;it++){
        int e = tid + it*256;
        T[(e>>5)*36 + (e&31)] = psi[base+e];
    }
    __syncthreads();
    int rp = tid & 31, cq = tid >> 5;
    float4 u = make_float4(0.f,0.f,0.f,0.f);
    for (int r=0;r<32;r++){
        float rv = RsT[r*32+rp];
        float4 tr = *(const float4*)&T[r*36 + cq*4];     // broadcast LDS.128
        u.x += rv*tr.x; u.y += rv*tr.y; u.z += rv*tr.z; u.w += rv*tr.w;
    }
    *(float4*)&Usm[rp*36 + cq*4] = u;
    __syncthreads();
    float w[4];
    #pragma unroll
    for (int i=0;i<4;i++){
        int cp = cq*4+i;
        float acc0=0.f, acc1=0.f, acc2v=0.f, acc3=0.f;
        #pragma unroll
        for (int c8=0;c8<8;c8++){
            float4 rr = *(const float4*)&Rs[cp*32 + c8*4];       // broadcast LDS.128
            float4 uu = *(const float4*)&Usm[rp*36 + c8*4];      // phase-conflict-free LDS.128
            acc0 += rr.x*uu.x; acc1 += rr.y*uu.y;
            acc2v+= rr.z*uu.z; acc3 += rr.w*uu.w;
        }
        w[i]=(acc0+acc1)+(acc2v+acc3);
    }
    __syncthreads();
    *(float4*)&T[rp*36 + cq*4] = make_float4(w[0],w[1],w[2],w[3]);
    __syncthreads();
    #pragma unroll
    for (int it=0;it<4;it++){
        int e = tid + it*256;
        psi[base+e] = T[(e>>5)*36 + (e&31)];
    }
}

// ------------- fused horizontal high: bits [15-19] and [10-14], packed f32x2 -------------
__global__ __launch_bounds__(256) void hhigh_kernel(float* __restrict__ psi){
    __shared__ __align__(16) float S[8][1036];
    __shared__ __align__(16) float Rs[1024];
    __shared__ float RsT[1024];
    int tid = threadIdx.x;
    for (int e=tid;e<1024;e+=256){
        float v = g_R[e];                 // prologue-safe
        Rs[e]=v;
        RsT[(e&31)*32 + (e>>5)] = v;
    }
    pdl_wait();
    unsigned lowbase = blockIdx.x * 8u;
    for (int it=0; it<32; it++){
        int idx = tid + it*256;
        int lo = idx & 7, k = idx >> 3;
        S[lo][k] = psi[(unsigned)k*1024u + lowbase + (unsigned)lo];
    }
    __syncthreads();
    int low = tid & 7, rp = tid >> 3;
    unsigned long long U2[16];
    #pragma unroll
    for (int e=0;e<16;e++) U2[e]=0ull;
    for (int r=0;r<32;r++){
        float rv = RsT[r*32+rp];
        unsigned long long rvp = pk2(rv, rv);
        const ulonglong2* row2 = (const ulonglong2*)&S[low][r*32];
        #pragma unroll
        for (int c2=0;c2<8;c2++){
            ulonglong2 tp = row2[c2];
            U2[c2*2+0] = fma2(rvp, tp.x, U2[c2*2+0]);
            U2[c2*2+1] = fma2(rvp, tp.y, U2[c2*2+1]);
        }
    }
    float W[32];
    #pragma unroll
    for (int cp=0;cp<32;cp++){
        const ulonglong2* Rp2 = (const ulonglong2*)&Rs[cp*32];
        unsigned long long s2 = 0ull;
        #pragma unroll
        for (int c2=0;c2<8;c2++){
            ulonglong2 rr = Rp2[c2];
            s2 = fma2(rr.x, U2[c2*2+0], s2);
            s2 = fma2(rr.y, U2[c2*2+1], s2);
        }
        float2 f = upk2(s2);
        W[cp] = f.x + f.y;
    }
    __syncthreads();
    #pragma unroll
    for (int cp=0;cp<32;cp++) S[low][rp*32+cp] = W[cp];
    __syncthreads();
    for (int it=0; it<32; it++){
        int idx = tid + it*256;
        int lo = idx & 7, k = idx >> 3;
        psi[(unsigned)k*1024u + lowbase + (unsigned)lo] = S[lo][k];
    }
}

// ------------- v2: columns p=0,1, in-place -------------
__global__ __launch_bounds__(256) void v2_kernel(float* __restrict__ psi, int p){
    __shared__ float Cs[256];
    __shared__ float Tsm[8][16][17];
    __shared__ float Usm[8][16][17];
    int tid=threadIdx.x;
    Cs[tid]=g_C16[tid];                   // prologue-safe
    int w = tid>>5, l = tid&31;
    unsigned f = blockIdx.x*8u + (unsigned)w;
    unsigned tt=f;
    tt = ((tt>>p)<<(p+2))        | (tt & ((1u<<p)-1u));
    tt = ((tt>>(p+5))<<(p+7))    | (tt & ((1u<<(p+5))-1u));
    tt = ((tt>>(p+10))<<(p+12))  | (tt & ((1u<<(p+10))-1u));
    tt = ((tt>>(p+15))<<(p+17))  | (tt & ((1u<<(p+15))-1u));
    unsigned base=tt;
    pdl_wait();
    __syncthreads();
    unsigned offs[8];
    #pragma unroll
    for (int t=0;t<8;t++){
        int e = l + 32*t;
        int i0 = e & 15, i1 = e >> 4;
        unsigned off =
            (unsigned)(((i0&1)|((i1&1)<<1)) << p) |
            (unsigned)((((i0>>1)&1)|(((i1>>1)&1)<<1)) << (p+5)) |
            (unsigned)((((i0>>2)&1)|(((i1>>2)&1)<<1)) << (p+10)) |
            (unsigned)((((i0>>3)&1)|(((i1>>3)&1)<<1)) << (p+15));
        offs[t]=off;
        Tsm[w][i1][i0] = psi[base+off];
    }
    __syncwarp();
    #pragma unroll
    for (int t=0;t<8;t++){
        int e = l + 32*t;
        int c = e & 15, o = e >> 4;
        float acc=0.f;
        #pragma unroll
        for (int k=0;k<16;k++) acc += Cs[o*16+k]*Tsm[w][k][c];
        Usm[w][o][c]=acc;
    }
    __syncwarp();
    #pragma unroll
    for (int t=0;t<8;t++){
        int e = l + 32*t;
        int i0 = e & 15, i1 = e >> 4;
        float acc=0.f;
        #pragma unroll
        for (int c=0;c<16;c++) acc += Cs[i0*16+c]*Usm[w][i1][c];
        psi[base+offs[t]] = acc;
    }
}

// ------------- v3: columns p=2,3,4 in one pass, in-place -------------
__global__ __launch_bounds__(256) void v3_kernel(float* __restrict__ psi){
    __shared__ float Cs[256];
    __shared__ float S[256*17 + 16];
    int t=threadIdx.x;
    Cs[t]=g_C16[t];                       // prologue-safe
    unsigned f = blockIdx.x;
    unsigned tt=f;
    tt = ((tt>>2)<<5)   | (tt & 3u);
    tt = ((tt>>7)<<10)  | (tt & 127u);
    tt = ((tt>>12)<<15) | (tt & 4095u);
    tt = ((tt>>17)<<20) | (tt & 131071u);
    unsigned base=tt;
    pdl_wait();
    {
        int b=t>>4, c=t&15;
        unsigned offb = ((unsigned)(b&1)<<3)|((unsigned)((b>>1)&1)<<8)|((unsigned)((b>>2)&1)<<13)|((unsigned)((b>>3)&1)<<18);
        unsigned offc = ((unsigned)(c&1)<<4)|((unsigned)((c>>1)&1)<<9)|((unsigned)((c>>2)&1)<<14)|((unsigned)((c>>3)&1)<<19);
        unsigned bs = base + offb + offc;
        #pragma unroll
        for (int a=0;a<16;a++){
            unsigned offa = ((unsigned)(a&1)<<2)|((unsigned)((a>>1)&1)<<7)|((unsigned)((a>>2)&1)<<12)|((unsigned)((a>>3)&1)<<17);
            S[t*17 + a] = psi[bs + offa];
        }
    }
    __syncthreads();
    {
        float v[16], o[16];
        #pragma unroll
        for (int a=0;a<16;a++) v[a]=S[t*17+a];
        #pragma unroll
        for (int ap=0;ap<16;ap++){
            float acc=0.f;
            #pragma unroll
            for (int a=0;a<16;a++) acc += Cs[ap*16+a]*v[a];
            o[ap]=acc;
        }
        #pragma unroll
        for (int a=0;a<16;a++) S[t*17+a]=o[a];
    }
    __syncthreads();
    {
        int a=t>>4, c=t&15;
        float v[16], o[16];
        #pragma unroll
        for (int b=0;b<16;b++) v[b]=S[(b*16+c)*17 + a];
        #pragma unroll
        for (int bp=0;bp<16;bp++){
            float acc=0.f;
            #pragma unroll
            for (int b=0;b<16;b++) acc += Cs[bp*16+b]*v[b];
            o[bp]=acc;
        }
        #pragma unroll
        for (int b=0;b<16;b++) S[(b*16+c)*17 + a]=o[b];
    }
    __syncthreads();
    {
        int a=t&15, b=t>>4;
        float v[16], o[16];
        #pragma unroll
        for (int c=0;c<16;c++) v[c]=S[(b*16+c)*17 + a];
        #pragma unroll
        for (int cp=0;cp<16;cp++){
            float acc=0.f;
            #pragma unroll
            for (int c=0;c<16;c++) acc += Cs[cp*16+c]*v[c];
            o[cp]=acc;
        }
        #pragma unroll
        for (int c=0;c<16;c++) S[(b*16+c)*17 + a]=o[c];
    }
    __syncthreads();
    {
        int b=t>>4, c=t&15;
        unsigned offb = ((unsigned)(b&1)<<3)|((unsigned)((b>>1)&1)<<8)|((unsigned)((b>>2)&1)<<13)|((unsigned)((b>>3)&1)<<18);
        unsigned offc = ((unsigned)(c&1)<<4)|((unsigned)((c>>1)&1)<<9)|((unsigned)((c>>2)&1)<<14)|((unsigned)((c>>3)&1)<<19);
        unsigned bs = base + offb + offc;
        #pragma unroll
        for (int a=0;a<16;a++){
            unsigned offa = ((unsigned)(a&1)<<2)|((unsigned)((a>>1)&1)<<7)|((unsigned)((a>>2)&1)<<12)|((unsigned)((a>>3)&1)<<17);
            psi[bs + offa] = S[t*17 + a];
        }
    }
}

// ------------- gather 64 amplitudes -------------
__global__ void gather_kernel(const int* __restrict__ x, const float* __restrict__ psi,
                              float* __restrict__ out){
    int b = threadIdx.x;
    unsigned idx=0;
    #pragma unroll
    for (int j=0;j<20;j++) idx = (idx<<1) | (unsigned)x[b*20+j];
    pdl_wait();
    out[b]=psi[idx];
}

// ---- host-side PDL launcher ----
template <typename F, typename... As>
static inline void pdl_launch(F f, dim3 g, dim3 b, As... as){
    cudaLaunchConfig_t cfg = {};
    cfg.gridDim = g; cfg.blockDim = b;
    cfg.dynamicSmemBytes = 0; cfg.stream = 0;
    cudaLaunchAttribute at[1];
    at[0].id = cudaLaunchAttributeProgrammaticStreamSerialization;
    at[0].val.programmaticStreamSerializationAllowed = 1;
    cfg.attrs = at; cfg.numAttrs = 1;
    cudaLaunchKernelEx(&cfg, f, as...);
}

extern "C" void kernel_launch(void* const* d_in, const int* in_sizes, int n_in,
                              void* d_out, int out_size){
    const int*   x    = (const int*)d_in[0];
    const float* peps = (const float*)d_in[1];
    const float* gate = (const float*)d_in[2];
    float* out = (float*)d_out;

    float *A,*Cm,*psi;
    cudaGetSymbolAddress((void**)&A,    g_A);
    cudaGetSymbolAddress((void**)&Cm,   g_Cm);
    cudaGetSymbolAddress((void**)&psi,  g_psi);

    pdl_launch(prep_kernel,   dim3(11),      dim3(256), peps, gate);
    pdl_launch(kkprep_kernel, dim3(257,2),   dim3(256));
    pdl_launch(fold23_kernel, dim3(256,2),   dim3(256));
    pdl_launch(fold4_kernel,  dim3(256,2),   dim3(256));

    pdl_launch(sgemm_kernel,  dim3(16,16),   dim3(256), (const float*)A, (const float*)Cm, psi);

    for (int sweep=0; sweep<5; sweep++){
        pdl_launch(hhigh_kernel, dim3(128),  dim3(256), psi);  // bits [15-19],[10-14]
        pdl_launch(hlow_kernel,  dim3(1024), dim3(256), psi);  // bits [5-9],[0-4]
        pdl_launch(v3_kernel,    dim3(256),  dim3(256), psi);  // columns p=2,3,4
        pdl_launch(v2_kernel,    dim3(512),  dim3(256), psi, 0); // columns p=0,1
    }

    pdl_launch(gather_kernel, dim3(1), dim3(64), x, (const float*)psi, out);
}

// round 8
// speedup vs baseline: 1.9689x; 1.9689x over previous
#include <cuda_runtime.h>

#define NS (1<<20)

// ---- device scratch (static, allocation-free) ----
__device__ float g_T0[NS];     // fold23 out, pair0
__device__ float g_T1[NS];     // fold23 out, pair1
__device__ float g_A[NS];      // T2 (pair*4096) early; then A[P01][bond] 1024x1024
__device__ float g_Cm[NS];     // Ct[P23][bond]  (1024x1024, transposed C)
__device__ float g_psi[NS];    // statevector (in-place for sweeps)
__device__ float g_R[1024];    // 32x32 row-chain operator [out][in]
__device__ float g_C16[256];   // 16x16 column-chain operator
__device__ float g_K[10*4096]; // per-column pair tensors K_j
__device__ float g_KK[2*65536];// combined column-pair operators KK23 per pair

// ---- packed fp32x2 helpers ----
__device__ __forceinline__ unsigned long long pk2(float x, float y){
    unsigned long long r; asm("mov.b64 %0,{%1,%2};" : "=l"(r) : "f"(x), "f"(y)); return r;
}
__device__ __forceinline__ float2 upk2(unsigned long long v){
    float2 r; asm("mov.b64 {%0,%1},%2;" : "=f"(r.x), "=f"(r.y) : "l"(v)); return r;
}
__device__ __forceinline__ unsigned long long fma2(unsigned long long a,
        unsigned long long b, unsigned long long c){
    unsigned long long d;
    asm("fma.rn.f32x2 %0,%1,%2,%3;" : "=l"(d) : "l"(a), "l"(b), "l"(c));
    return d;
}

__device__ __forceinline__ float peps_el(const float* __restrict__ peps,
                                         int i,int j,int p,int u,int d,int l,int r){
    return peps[(((((i*5+j)*2+p)*4+u)*4+d)*4+l)*4+r];
}

// ------------- prep: blocks 0..9 compute K_j; block 10 builds R and C16 -------------
__global__ void prep_kernel(const float* __restrict__ peps, const float* __restrict__ gate){
    int t = threadIdx.x;  // 256
    if (blockIdx.x < 10){
        int blk = blockIdx.x;
        int pair = blk/5, j = blk%5;
        int L = (j==0)?1:4, R = (j==4)?1:4;
        int nk = 16*L*L*R*R;
        float* Kg = g_K + blk*4096;
        for (int e=t; e<nk; e+=256){
            int tt=e;
            int rb=tt%R; tt/=R; int ra=tt%R; tt/=R;
            int lb=tt%L; tt/=L; int la=tt%L; tt/=L;
            int mid=tt&3; tt>>=2;
            int pb=tt&1; int pa=tt>>1;
            float s=0.f;
            if (pair==0){
                #pragma unroll
                for(int m=0;m<4;m++)
                    s += peps_el(peps,0,j,pa,0,m,la,ra)*peps_el(peps,1,j,pb,m,mid,lb,rb);
            } else {
                #pragma unroll
                for(int m=0;m<4;m++)
                    s += peps_el(peps,2,j,pa,mid,m,la,ra)*peps_el(peps,3,j,pb,m,0,lb,rb);
            }
            Kg[e]=s;
        }
        return;
    }
    // ---- block 10: build R (32x32) and C16 (16x16) with 256 threads ----
    __shared__ float g[16];
    __shared__ float A0[1024];
    __shared__ float A1[1024];
    if (t<16) g[t]=gate[t];
    for (int e=t;e<1024;e+=256) A0[e] = ((e>>5)==(e&31)) ? 1.0f : 0.0f;
    __syncthreads();
    #pragma unroll
    for (int k=0;k<4;k++){
        const float* cur = (k&1)? A1 : A0;
        float* nxt       = (k&1)? A0 : A1;
        int hb=4-k, lb=3-k;
        for (int e=t;e<1024;e+=256){
            int rp=e>>5, c=e&31;
            int i1p=(rp>>hb)&1, i2p=(rp>>lb)&1;
            int base = rp & ~((1<<hb)|(1<<lb));
            float acc=0.f;
            #pragma unroll
            for(int i1=0;i1<2;i1++)
            #pragma unroll
            for(int i2=0;i2<2;i2++)
                acc += g[(i1p*2+i2p)*4+(i1*2+i2)] * cur[(base|(i1<<hb)|(i2<<lb))*32 + c];
            nxt[e]=acc;
        }
        __syncthreads();
    }
    for (int e=t;e<1024;e+=256) g_R[e]=A0[e];
    __syncthreads();
    A0[t] = ((t>>4)==(t&15)) ? 1.0f : 0.0f;
    __syncthreads();
    #pragma unroll
    for (int k=0;k<3;k++){
        const float* cur=(k&1)?A1:A0;
        float* nxt      =(k&1)?A0:A1;
        int hb=3-k, lb=2-k;
        int rp=t>>4, c=t&15;
        int i1p=(rp>>hb)&1,i2p=(rp>>lb)&1;
        int base = rp & ~((1<<hb)|(1<<lb));
        float acc=0.f;
        #pragma unroll
        for(int i1=0;i1<2;i1++)
        #pragma unroll
        for(int i2=0;i2<2;i2++)
            acc += g[(i1p*2+i2p)*4+(i1*2+i2)]*cur[(base|(i1<<hb)|(i2<<lb))*16+c];
        __syncthreads();
        nxt[t]=acc;
        __syncthreads();
    }
    g_C16[t]=A1[t];
}

// ------------- kkprep: blocks 0..255 build KK23 slices; block 256 builds T2 -------------
__global__ void kkprep_kernel(){
    int t = threadIdx.x;          // 256
    int pair = blockIdx.y;
    const float* Kbase = g_K + pair*5*4096;
    if (blockIdx.x < 256){
        int pb = blockIdx.x;
        int pd = pb&15, pbb = (pb>>4)&3, pa = pb>>6;
        int kb2 = ((pa>>1)*2+(pbb>>1))*4+(pd>>2);
        int kb3 = ((pa&1)*2+(pbb&1))*4+(pd&3);
        __shared__ float K2s[256], K3s[256];
        K2s[t] = Kbase[2*4096 + kb2*256 + t];
        K3s[t] = Kbase[3*4096 + kb3*256 + t];
        __syncthreads();
        int l = t>>4, r = t&15;
        float acc=0.f;
        #pragma unroll
        for (int m=0;m<16;m++) acc += K2s[l*16+m]*K3s[m*16+r];
        g_KK[pair*65536 + pb*256 + t] = acc;
        return;
    }
    __shared__ float K0s[256];
    __shared__ float K1s[4096];
    K0s[t]=Kbase[t];
    for (int e=t;e<4096;e+=256) K1s[e]=Kbase[4096+e];
    __syncthreads();
    int abc = t;
    int a2=abc>>6, b2=(abc>>4)&3, c2=abc&15;
    int kb0 = ((a2>>1)*2+(b2>>1))*4 + (c2>>2);
    int kb1 = ((a2&1)*2+(b2&1))*4 + (c2&3);
    float* T2 = g_A + pair*4096;
    #pragma unroll
    for (int r=0;r<16;r++){
        float acc=0.f;
        #pragma unroll
        for (int m=0;m<16;m++) acc += K0s[kb0*16+m]*K1s[(kb1*16+m)*16+r];
        T2[abc*16+r]=acc;
    }
}

// ------------- fold23: T4 = T2 x KK23 ; grid (256, 2) -------------
__global__ __launch_bounds__(256) void fold23_kernel(){
    int t = threadIdx.x;
    int pb = blockIdx.x, pair = blockIdx.y;
    int pd = pb&15, pbb = (pb>>4)&3, pa = pb>>6;
    __shared__ float Ts[256*20];
    __shared__ float Ks[256];
    const float* T2 = g_A + pair*4096;
    for (int e=t;e<4096;e+=256) Ts[(e>>4)*20 + (e&15)] = T2[e];
    Ks[t] = g_KK[pair*65536 + pb*256 + t];
    __syncthreads();
    float* Tout = pair? g_T1 : g_T0;
    int a2=t>>6, b2=(t>>4)&3, c2=t&15;
    float tv[16];
    #pragma unroll
    for (int l=0;l<16;l++) tv[l]=Ts[t*20+l];
    long obase = ((((long)(a2*4+pa)*16 + b2*4+pbb)*256) + c2*16+pd)*16;
    #pragma unroll
    for (int r4=0;r4<4;r4++){
        float4 o; float* po=(float*)&o;
        #pragma unroll
        for (int q=0;q<4;q++){
            int r=r4*4+q;
            float acc=0.f;
            #pragma unroll
            for (int l=0;l<16;l++) acc += tv[l]*Ks[l*16+r];
            po[q]=acc;
        }
        *(float4*)&Tout[obase + r4*4] = o;
    }
}

// ------------- fold4: final column -> A / Ct ; grid (256, 2), thread = c -------------
__global__ __launch_bounds__(256) void fold4_kernel(){
    int c = threadIdx.x;
    int a = blockIdx.x >> 4, b = blockIdx.x & 15;
    int pair = blockIdx.y;
    __shared__ float K4s[256];
    K4s[c] = g_K[(pair*5+4)*4096 + c];
    __syncthreads();
    const float* Tin = pair? g_T1 : g_T0;
    const float* tp = &Tin[(((long)(a*16+b)*256)+c)*16];
    float tv[16];
    #pragma unroll
    for (int l4=0;l4<4;l4++){
        float4 v = *(const float4*)&tp[l4*4];
        tv[l4*4+0]=v.x; tv[l4*4+1]=v.y; tv[l4*4+2]=v.z; tv[l4*4+3]=v.w;
    }
    if (pair==0){
        long base = (long)a*65536 + (long)b*2048 + c*4;
        #pragma unroll
        for (int p0=0;p0<2;p0++)
        #pragma unroll
        for (int p1=0;p1<2;p1++){
            float4 o; float* po=(float*)&o;
            #pragma unroll
            for (int d1=0;d1<4;d1++){
                int kb=(p0*2+p1)*4+d1;
                float acc=0.f;
                #pragma unroll
                for (int l=0;l<16;l++) acc += tv[l]*K4s[kb*16+l];
                po[d1]=acc;
            }
            *(float4*)&g_A[base + p0*32768 + p1*1024] = o;
        }
    } else {
        #pragma unroll
        for (int p0=0;p0<2;p0++)
        #pragma unroll
        for (int p1=0;p1<2;p1++){
            float4 o; float* po=(float*)&o;
            #pragma unroll
            for (int d1=0;d1<4;d1++){
                int kb=(p0*2+p1)*4+d1;
                float acc=0.f;
                #pragma unroll
                for (int l=0;l<16;l++) acc += tv[l]*K4s[kb*16+l];
                po[d1]=acc;
            }
            long col = (long)(a*64 + p0*32 + b*2 + p1);
            *(float4*)&g_Cm[col*1024 + c*4] = o;
        }
    }
}

// ------------- psi = A(1024x1024) @ Ct^T : packed f32x2 FFMA -------------
__global__ __launch_bounds__(256) void sgemm_kernel(const float* __restrict__ A,
        const float* __restrict__ Bt, float* __restrict__ Cout){
    __shared__ __align__(16) float As2[16][132];
    __shared__ __align__(16) float Bs[16][68];
    int bx=blockIdx.x, by=blockIdx.y;
    int tid=threadIdx.x;
    int tx=tid&15, ty=tid>>4;
    unsigned long long acc2[4][2];
    #pragma unroll
    for(int i=0;i<4;i++){ acc2[i][0]=0ull; acc2[i][1]=0ull; }

    const float* Ablk = A + (long)(by*64)*1024;
    const float* Btblk = Bt + (long)(bx*64)*1024;
    for (int k0=0;k0<1024;k0+=16){
        #pragma unroll
        for (int e=0;e<4;e++){
            int idx = tid + e*256;
            int m = idx>>4, k = idx&15;
            float v = Ablk[(long)m*1024 + k0 + k];
            *(float2*)&As2[k][2*m] = make_float2(v,v);
        }
        #pragma unroll
        for (int e=0;e<4;e++){
            int idx = tid + e*256;
            int n = idx>>4, k = idx&15;
            Bs[k][n] = Btblk[(long)n*1024 + k0 + k];
        }
        __syncthreads();
        #pragma unroll
        for (int k=0;k<16;k++){
            ulonglong2 a01 = *(const ulonglong2*)&As2[k][ty*8];
            ulonglong2 a23 = *(const ulonglong2*)&As2[k][ty*8+4];
            ulonglong2 bb  = *(const ulonglong2*)&Bs[k][tx*4];
            acc2[0][0]=fma2(a01.x, bb.x, acc2[0][0]); acc2[0][1]=fma2(a01.x, bb.y, acc2[0][1]);
            acc2[1][0]=fma2(a01.y, bb.x, acc2[1][0]); acc2[1][1]=fma2(a01.y, bb.y, acc2[1][1]);
            acc2[2][0]=fma2(a23.x, bb.x, acc2[2][0]); acc2[2][1]=fma2(a23.x, bb.y, acc2[2][1]);
            acc2[3][0]=fma2(a23.y, bb.x, acc2[3][0]); acc2[3][1]=fma2(a23.y, bb.y, acc2[3][1]);
        }
        __syncthreads();
    }
    #pragma unroll
    for(int i=0;i<4;i++){
        float2 c0 = upk2(acc2[i][0]);
        float2 c1 = upk2(acc2[i][1]);
        float4 o = make_float4(c0.x, c0.y, c1.x, c1.y);
        *(float4*)&Cout[(long)(by*64+ty*4+i)*1024 + bx*64+tx*4] = o;
    }
}

// ------------- fused horizontal low: bits [5-9] and [0-4], in-place, LDS.128 -------------
__global__ __launch_bounds__(256) void hlow_kernel(float* __restrict__ psi){
    __shared__ __align__(16) float T[32*36];
    __shared__ __align__(16) float Usm[32*36];
    __shared__ __align__(16) float Rs[1024];
    __shared__ float RsT[1024];
    int tid=threadIdx.x;
    for (int e=tid;e<1024;e+=256){
        float v = g_R[e];
        Rs[e]=v;
        RsT[(e&31)*32 + (e>>5)] = v;
    }
    unsigned base = blockIdx.x*1024u;
    #pragma unroll
    for (int it=0;it<4;it++){
        int e = tid + it*256;
        T[(e>>5)*36 + (e&31)] = psi[base+e];
    }
    __syncthreads();
    int rp = tid & 31, cq = tid >> 5;
    float4 u = make_float4(0.f,0.f,0.f,0.f);
    for (int r=0;r<32;r++){
        float rv = RsT[r*32+rp];
        float4 tr = *(const float4*)&T[r*36 + cq*4];     // broadcast LDS.128
        u.x += rv*tr.x; u.y += rv*tr.y; u.z += rv*tr.z; u.w += rv*tr.w;
    }
    *(float4*)&Usm[rp*36 + cq*4] = u;
    __syncthreads();
    float w[4];
    #pragma unroll
    for (int i=0;i<4;i++){
        int cp = cq*4+i;
        float acc0=0.f, acc1=0.f, acc2v=0.f, acc3=0.f;
        #pragma unroll
        for (int c8=0;c8<8;c8++){
            float4 rr = *(const float4*)&Rs[cp*32 + c8*4];     // broadcast LDS.128
            float4 uu = *(const float4*)&Usm[rp*36 + c8*4];    // phase-conflict-free LDS.128
            acc0 += rr.x*uu.x; acc1 += rr.y*uu.y;
            acc2v+= rr.z*uu.z; acc3 += rr.w*uu.w;
        }
        w[i]=(acc0+acc1)+(acc2v+acc3);
    }
    __syncthreads();
    *(float4*)&T[rp*36 + cq*4] = make_float4(w[0],w[1],w[2],w[3]);
    __syncthreads();
    #pragma unroll
    for (int it=0;it<4;it++){
        int e = tid + it*256;
        psi[base+e] = T[(e>>5)*36 + (e&31)];
    }
}

// ------------- fused horizontal high: bits [15-19] and [10-14], packed f32x2 -------------
__global__ __launch_bounds__(256) void hhigh_kernel(float* __restrict__ psi){
    __shared__ __align__(16) float S[8][1036];
    __shared__ __align__(16) float Rs[1024];
    __shared__ float RsT[1024];
    int tid = threadIdx.x;
    for (int e=tid;e<1024;e+=256){
        float v = g_R[e];
        Rs[e]=v;
        RsT[(e&31)*32 + (e>>5)] = v;
    }
    unsigned lowbase = blockIdx.x * 8u;
    for (int it=0; it<32; it++){
        int idx = tid + it*256;
        int lo = idx & 7, k = idx >> 3;
        S[lo][k] = psi[(unsigned)k*1024u + lowbase + (unsigned)lo];
    }
    __syncthreads();
    int low = tid & 7, rp = tid >> 3;
    unsigned long long U2[16];
    #pragma unroll
    for (int e=0;e<16;e++) U2[e]=0ull;
    for (int r=0;r<32;r++){
        float rv = RsT[r*32+rp];
        unsigned long long rvp = pk2(rv, rv);
        const ulonglong2* row2 = (const ulonglong2*)&S[low][r*32];
        #pragma unroll
        for (int c2=0;c2<8;c2++){
            ulonglong2 tp = row2[c2];
            U2[c2*2+0] = fma2(rvp, tp.x, U2[c2*2+0]);
            U2[c2*2+1] = fma2(rvp, tp.y, U2[c2*2+1]);
        }
    }
    float W[32];
    #pragma unroll
    for (int cp=0;cp<32;cp++){
        const ulonglong2* Rp2 = (const ulonglong2*)&Rs[cp*32];
        unsigned long long s2 = 0ull;
        #pragma unroll
        for (int c2=0;c2<8;c2++){
            ulonglong2 rr = Rp2[c2];
            s2 = fma2(rr.x, U2[c2*2+0], s2);
            s2 = fma2(rr.y, U2[c2*2+1], s2);
        }
        float2 f = upk2(s2);
        W[cp] = f.x + f.y;
    }
    __syncthreads();
    #pragma unroll
    for (int cp=0;cp<32;cp++) S[low][rp*32+cp] = W[cp];
    __syncthreads();
    for (int it=0; it<32; it++){
        int idx = tid + it*256;
        int lo = idx & 7, k = idx >> 3;
        psi[(unsigned)k*1024u + lowbase + (unsigned)lo] = S[lo][k];
    }
}

// ------------- v2: columns p=0,1, in-place -------------
__global__ __launch_bounds__(256) void v2_kernel(float* __restrict__ psi, int p){
    __shared__ float Cs[256];
    __shared__ float Tsm[8][16][17];
    __shared__ float Usm[8][16][17];
    int tid=threadIdx.x;
    Cs[tid]=g_C16[tid];
    int w = tid>>5, l = tid&31;
    unsigned f = blockIdx.x*8u + (unsigned)w;
    unsigned tt=f;
    tt = ((tt>>p)<<(p+2))        | (tt & ((1u<<p)-1u));
    tt = ((tt>>(p+5))<<(p+7))    | (tt & ((1u<<(p+5))-1u));
    tt = ((tt>>(p+10))<<(p+12))  | (tt & ((1u<<(p+10))-1u));
    tt = ((tt>>(p+15))<<(p+17))  | (tt & ((1u<<(p+15))-1u));
    unsigned base=tt;
    __syncthreads();
    unsigned offs[8];
    #pragma unroll
    for (int t=0;t<8;t++){
        int e = l + 32*t;
        int i0 = e & 15, i1 = e >> 4;
        unsigned off =
            (unsigned)(((i0&1)|((i1&1)<<1)) << p) |
            (unsigned)((((i0>>1)&1)|(((i1>>1)&1)<<1)) << (p+5)) |
            (unsigned)((((i0>>2)&1)|(((i1>>2)&1)<<1)) << (p+10)) |
            (unsigned)((((i0>>3)&1)|(((i1>>3)&1)<<1)) << (p+15));
        offs[t]=off;
        Tsm[w][i1][i0] = psi[base+off];
    }
    __syncwarp();
    #pragma unroll
    for (int t=0;t<8;t++){
        int e = l + 32*t;
        int c = e & 15, o = e >> 4;
        float acc=0.f;
        #pragma unroll
        for (int k=0;k<16;k++) acc += Cs[o*16+k]*Tsm[w][k][c];
        Usm[w][o][c]=acc;
    }
    __syncwarp();
    #pragma unroll
    for (int t=0;t<8;t++){
        int e = l + 32*t;
        int i0 = e & 15, i1 = e >> 4;
        float acc=0.f;
        #pragma unroll
        for (int c=0;c<16;c++) acc += Cs[i0*16+c]*Usm[w][i1][c];
        psi[base+offs[t]] = acc;
    }
}

// ------------- v3: columns p=2,3,4 in one pass, in-place -------------
__global__ __launch_bounds__(256) void v3_kernel(float* __restrict__ psi){
    __shared__ float Cs[256];
    __shared__ float S[256*17 + 16];
    int t=threadIdx.x;
    Cs[t]=g_C16[t];
    unsigned f = blockIdx.x;
    unsigned tt=f;
    tt = ((tt>>2)<<5)   | (tt & 3u);
    tt = ((tt>>7)<<10)  | (tt & 127u);
    tt = ((tt>>12)<<15) | (tt & 4095u);
    tt = ((tt>>17)<<20) | (tt & 131071u);
    unsigned base=tt;
    {
        int b=t>>4, c=t&15;
        unsigned offb = ((unsigned)(b&1)<<3)|((unsigned)((b>>1)&1)<<8)|((unsigned)((b>>2)&1)<<13)|((unsigned)((b>>3)&1)<<18);
        unsigned offc = ((unsigned)(c&1)<<4)|((unsigned)((c>>1)&1)<<9)|((unsigned)((c>>2)&1)<<14)|((unsigned)((c>>3)&1)<<19);
        unsigned bs = base + offb + offc;
        #pragma unroll
        for (int a=0;a<16;a++){
            unsigned offa = ((unsigned)(a&1)<<2)|((unsigned)((a>>1)&1)<<7)|((unsigned)((a>>2)&1)<<12)|((unsigned)((a>>3)&1)<<17);
            S[t*17 + a] = psi[bs + offa];
        }
    }
    __syncthreads();
    {
        float v[16], o[16];
        #pragma unroll
        for (int a=0;a<16;a++) v[a]=S[t*17+a];
        #pragma unroll
        for (int ap=0;ap<16;ap++){
            float acc=0.f;
            #pragma unroll
            for (int a=0;a<16;a++) acc += Cs[ap*16+a]*v[a];
            o[ap]=acc;
        }
        #pragma unroll
        for (int a=0;a<16;a++) S[t*17+a]=o[a];
    }
    __syncthreads();
    {
        int a=t>>4, c=t&15;
        float v[16], o[16];
        #pragma unroll
        for (int b=0;b<16;b++) v[b]=S[(b*16+c)*17 + a];
        #pragma unroll
        for (int bp=0;bp<16;bp++){
            float acc=0.f;
            #pragma unroll
            for (int b=0;b<16;b++) acc += Cs[bp*16+b]*v[b];
            o[bp]=acc;
        }
        #pragma unroll
        for (int b=0;b<16;b++) S[(b*16+c)*17 + a]=o[b];
    }
    __syncthreads();
    {
        int a=t&15, b=t>>4;
        float v[16], o[16];
        #pragma unroll
        for (int c=0;c<16;c++) v[c]=S[(b*16+c)*17 + a];
        #pragma unroll
        for (int cp=0;cp<16;cp++){
            float acc=0.f;
            #pragma unroll
            for (int c=0;c<16;c++) acc += Cs[cp*16+c]*v[c];
            o[cp]=acc;
        }
        #pragma unroll
        for (int c=0;c<16;c++) S[(b*16+c)*17 + a]=o[c];
    }
    __syncthreads();
    {
        int b=t>>4, c=t&15;
        unsigned offb = ((unsigned)(b&1)<<3)|((unsigned)((b>>1)&1)<<8)|((unsigned)((b>>2)&1)<<13)|((unsigned)((b>>3)&1)<<18);
        unsigned offc = ((unsigned)(c&1)<<4)|((unsigned)((c>>1)&1)<<9)|((unsigned)((c>>2)&1)<<14)|((unsigned)((c>>3)&1)<<19);
        unsigned bs = base + offb + offc;
        #pragma unroll
        for (int a=0;a<16;a++){
            unsigned offa = ((unsigned)(a&1)<<2)|((unsigned)((a>>1)&1)<<7)|((unsigned)((a>>2)&1)<<12)|((unsigned)((a>>3)&1)<<17);
            psi[bs + offa] = S[t*17 + a];
        }
    }
}

// ------------- gather 64 amplitudes -------------
__global__ void gather_kernel(const int* __restrict__ x, const float* __restrict__ psi,
                              float* __restrict__ out){
    int b = threadIdx.x;
    unsigned idx=0;
    #pragma unroll
    for (int j=0;j<20;j++) idx = (idx<<1) | (unsigned)x[b*20+j];
    out[b]=psi[idx];
}

extern "C" void kernel_launch(void* const* d_in, const int* in_sizes, int n_in,
                              void* d_out, int out_size){
    const int*   x    = (const int*)d_in[0];
    const float* peps = (const float*)d_in[1];
    const float* gate = (const float*)d_in[2];
    float* out = (float*)d_out;

    float *A,*Cm,*psi;
    cudaGetSymbolAddress((void**)&A,    g_A);
    cudaGetSymbolAddress((void**)&Cm,   g_Cm);
    cudaGetSymbolAddress((void**)&psi,  g_psi);

    prep_kernel<<<11,256>>>(peps, gate);
    kkprep_kernel<<<dim3(257,2),256>>>();
    fold23_kernel<<<dim3(256,2),256>>>();
    fold4_kernel<<<dim3(256,2),256>>>();

    sgemm_kernel<<<dim3(16,16),256>>>(A, Cm, psi);

    for (int sweep=0; sweep<5; sweep++){
        hhigh_kernel<<<128,256>>>(psi);   // bits [15-19] and [10-14]
        hlow_kernel<<<1024,256>>>(psi);   // bits [5-9] and [0-4]
        v3_kernel<<<256,256>>>(psi);      // columns at p=2,3,4
        v2_kernel<<<512,256>>>(psi, 0);   // columns at p=0,1
    }

    gather_kernel<<<1,64>>>(x, psi, out);
}

// round 9
// speedup vs baseline: 1.9784x; 1.0048x over previous
#include <cuda_runtime.h>

#define NS (1<<20)

// ---- device scratch (static, allocation-free) ----
__device__ float g_T0[NS];     // fold23 out, pair0
__device__ float g_T1[NS];     // fold23 out, pair1
__device__ float g_A[NS];      // A[P01][bond] 1024x1024
__device__ float g_Cm[NS];     // Ct[P23][bond]  (1024x1024, transposed C)
__device__ float g_psi[NS];    // statevector (in-place for sweeps)
__device__ float g_R[1024];    // 32x32 row-chain operator [out][in]
__device__ float g_C16[256];   // 16x16 column-chain operator
__device__ float g_K[10*4096]; // per-column pair tensors K_j

// ---- packed fp32x2 helpers ----
__device__ __forceinline__ unsigned long long pk2(float x, float y){
    unsigned long long r; asm("mov.b64 %0,{%1,%2};" : "=l"(r) : "f"(x), "f"(y)); return r;
}
__device__ __forceinline__ float2 upk2(unsigned long long v){
    float2 r; asm("mov.b64 {%0,%1},%2;" : "=f"(r.x), "=f"(r.y) : "l"(v)); return r;
}
__device__ __forceinline__ unsigned long long fma2(unsigned long long a,
        unsigned long long b, unsigned long long c){
    unsigned long long d;
    asm("fma.rn.f32x2 %0,%1,%2,%3;" : "=l"(d) : "l"(a), "l"(b), "l"(c));
    return d;
}

__device__ __forceinline__ float peps_el(const float* __restrict__ peps,
                                         int i,int j,int p,int u,int d,int l,int r){
    return peps[(((((i*5+j)*2+p)*4+u)*4+d)*4+l)*4+r];
}

// ------------- prep: blocks 0..9 compute K_j; block 10 builds R and C16 -------------
__global__ void prep_kernel(const float* __restrict__ peps, const float* __restrict__ gate){
    int t = threadIdx.x;  // 256
    if (blockIdx.x < 10){
        int blk = blockIdx.x;
        int pair = blk/5, j = blk%5;
        int L = (j==0)?1:4, R = (j==4)?1:4;
        int nk = 16*L*L*R*R;
        float* Kg = g_K + blk*4096;
        for (int e=t; e<nk; e+=256){
            int tt=e;
            int rb=tt%R; tt/=R; int ra=tt%R; tt/=R;
            int lb=tt%L; tt/=L; int la=tt%L; tt/=L;
            int mid=tt&3; tt>>=2;
            int pb=tt&1; int pa=tt>>1;
            float s=0.f;
            if (pair==0){
                #pragma unroll
                for(int m=0;m<4;m++)
                    s += peps_el(peps,0,j,pa,0,m,la,ra)*peps_el(peps,1,j,pb,m,mid,lb,rb);
            } else {
                #pragma unroll
                for(int m=0;m<4;m++)
                    s += peps_el(peps,2,j,pa,mid,m,la,ra)*peps_el(peps,3,j,pb,m,0,lb,rb);
            }
            Kg[e]=s;
        }
        return;
    }
    // ---- block 10: build R (32x32) and C16 (16x16) with 256 threads ----
    __shared__ float g[16];
    __shared__ float A0[1024];
    __shared__ float A1[1024];
    if (t<16) g[t]=gate[t];
    for (int e=t;e<1024;e+=256) A0[e] = ((e>>5)==(e&31)) ? 1.0f : 0.0f;
    __syncthreads();
    #pragma unroll
    for (int k=0;k<4;k++){
        const float* cur = (k&1)? A1 : A0;
        float* nxt       = (k&1)? A0 : A1;
        int hb=4-k, lb=3-k;
        for (int e=t;e<1024;e+=256){
            int rp=e>>5, c=e&31;
            int i1p=(rp>>hb)&1, i2p=(rp>>lb)&1;
            int base = rp & ~((1<<hb)|(1<<lb));
            float acc=0.f;
            #pragma unroll
            for(int i1=0;i1<2;i1++)
            #pragma unroll
            for(int i2=0;i2<2;i2++)
                acc += g[(i1p*2+i2p)*4+(i1*2+i2)] * cur[(base|(i1<<hb)|(i2<<lb))*32 + c];
            nxt[e]=acc;
        }
        __syncthreads();
    }
    for (int e=t;e<1024;e+=256) g_R[e]=A0[e];
    __syncthreads();
    A0[t] = ((t>>4)==(t&15)) ? 1.0f : 0.0f;
    __syncthreads();
    #pragma unroll
    for (int k=0;k<3;k++){
        const float* cur=(k&1)?A1:A0;
        float* nxt      =(k&1)?A0:A1;
        int hb=3-k, lb=2-k;
        int rp=t>>4, c=t&15;
        int i1p=(rp>>hb)&1,i2p=(rp>>lb)&1;
        int base = rp & ~((1<<hb)|(1<<lb));
        float acc=0.f;
        #pragma unroll
        for(int i1=0;i1<2;i1++)
        #pragma unroll
        for(int i2=0;i2<2;i2++)
            acc += g[(i1p*2+i2p)*4+(i1*2+i2)]*cur[(base|(i1<<hb)|(i2<<lb))*16+c];
        __syncthreads();
        nxt[t]=acc;
        __syncthreads();
    }
    g_C16[t]=A1[t];
}

// ------------- fold23 (absorbs kkprep): T4 = T2 x KK23 ; grid (256, 2) -------------
__global__ __launch_bounds__(256) void fold23_kernel(){
    int t = threadIdx.x;
    int pb = blockIdx.x, pair = blockIdx.y;
    int pd = pb&15, pbb = (pb>>4)&3, pa = pb>>6;
    const float* Kbase = g_K + pair*5*4096;
    __shared__ float K0s[256];
    __shared__ float K1s[4096];
    __shared__ float K2s[256], K3s[256];
    __shared__ float Ts[256*20];
    __shared__ float Ks[256];
    K0s[t] = Kbase[t];
    for (int e=t;e<4096;e+=256) K1s[e]=Kbase[4096+e];
    int kb2 = ((pa>>1)*2+(pbb>>1))*4+(pd>>2);
    int kb3 = ((pa&1)*2+(pbb&1))*4+(pd&3);
    K2s[t] = Kbase[2*4096 + kb2*256 + t];
    K3s[t] = Kbase[3*4096 + kb3*256 + t];
    __syncthreads();
    // T2[abc][r] into Ts (pitch 20)
    {
        int abc=t;
        int a2=abc>>6, b2=(abc>>4)&3, c2=abc&15;
        int kb0 = ((a2>>1)*2+(b2>>1))*4 + (c2>>2);
        int kb1 = ((a2&1)*2+(b2&1))*4 + (c2&3);
        #pragma unroll
        for (int r=0;r<16;r++){
            float acc=0.f;
            #pragma unroll
            for (int m=0;m<16;m++) acc += K0s[kb0*16+m]*K1s[(kb1*16+m)*16+r];
            Ts[t*20+r]=acc;
        }
    }
    // KK slice
    {
        int l=t>>4, r=t&15;
        float acc=0.f;
        #pragma unroll
        for (int m=0;m<16;m++) acc += K2s[l*16+m]*K3s[m*16+r];
        Ks[t]=acc;
    }
    __syncthreads();
    float* Tout = pair? g_T1 : g_T0;
    int a2=t>>6, b2=(t>>4)&3, c2=t&15;
    float tv[16];
    #pragma unroll
    for (int l=0;l<16;l++) tv[l]=Ts[t*20+l];
    long obase = ((((long)(a2*4+pa)*16 + b2*4+pbb)*256) + c2*16+pd)*16;
    #pragma unroll
    for (int r4=0;r4<4;r4++){
        float4 o; float* po=(float*)&o;
        #pragma unroll
        for (int q=0;q<4;q++){
            int r=r4*4+q;
            float acc=0.f;
            #pragma unroll
            for (int l=0;l<16;l++) acc += tv[l]*Ks[l*16+r];
            po[q]=acc;
        }
        *(float4*)&Tout[obase + r4*4] = o;
    }
}

// ------------- fold4: final column -> A / Ct ; grid (256, 2), thread = c -------------
__global__ __launch_bounds__(256) void fold4_kernel(){
    int c = threadIdx.x;
    int a = blockIdx.x >> 4, b = blockIdx.x & 15;
    int pair = blockIdx.y;
    __shared__ float K4s[256];
    K4s[c] = g_K[(pair*5+4)*4096 + c];
    __syncthreads();
    const float* Tin = pair? g_T1 : g_T0;
    const float* tp = &Tin[(((long)(a*16+b)*256)+c)*16];
    float tv[16];
    #pragma unroll
    for (int l4=0;l4<4;l4++){
        float4 v = *(const float4*)&tp[l4*4];
        tv[l4*4+0]=v.x; tv[l4*4+1]=v.y; tv[l4*4+2]=v.z; tv[l4*4+3]=v.w;
    }
    if (pair==0){
        long base = (long)a*65536 + (long)b*2048 + c*4;
        #pragma unroll
        for (int p0=0;p0<2;p0++)
        #pragma unroll
        for (int p1=0;p1<2;p1++){
            float4 o; float* po=(float*)&o;
            #pragma unroll
            for (int d1=0;d1<4;d1++){
                int kb=(p0*2+p1)*4+d1;
                float acc=0.f;
                #pragma unroll
                for (int l=0;l<16;l++) acc += tv[l]*K4s[kb*16+l];
                po[d1]=acc;
            }
            *(float4*)&g_A[base + p0*32768 + p1*1024] = o;
        }
    } else {
        #pragma unroll
        for (int p0=0;p0<2;p0++)
        #pragma unroll
        for (int p1=0;p1<2;p1++){
            float4 o; float* po=(float*)&o;
            #pragma unroll
            for (int d1=0;d1<4;d1++){
                int kb=(p0*2+p1)*4+d1;
                float acc=0.f;
                #pragma unroll
                for (int l=0;l<16;l++) acc += tv[l]*K4s[kb*16+l];
                po[d1]=acc;
            }
            long col = (long)(a*64 + p0*32 + b*2 + p1);
            *(float4*)&g_Cm[col*1024 + c*4] = o;
        }
    }
}

// ------------- psi = A(1024x1024) @ Ct^T : packed f32x2 FFMA -------------
__global__ __launch_bounds__(256) void sgemm_kernel(const float* __restrict__ A,
        const float* __restrict__ Bt, float* __restrict__ Cout){
    __shared__ __align__(16) float As2[16][132];
    __shared__ __align__(16) float Bs[16][68];
    int bx=blockIdx.x, by=blockIdx.y;
    int tid=threadIdx.x;
    int tx=tid&15, ty=tid>>4;
    unsigned long long acc2[4][2];
    #pragma unroll
    for(int i=0;i<4;i++){ acc2[i][0]=0ull; acc2[i][1]=0ull; }

    const float* Ablk = A + (long)(by*64)*1024;
    const float* Btblk = Bt + (long)(bx*64)*1024;
    for (int k0=0;k0<1024;k0+=16){
        #pragma unroll
        for (int e=0;e<4;e++){
            int idx = tid + e*256;
            int m = idx>>4, k = idx&15;
            float v = Ablk[(long)m*1024 + k0 + k];
            *(float2*)&As2[k][2*m] = make_float2(v,v);
        }
        #pragma unroll
        for (int e=0;e<4;e++){
            int idx = tid + e*256;
            int n = idx>>4, k = idx&15;
            Bs[k][n] = Btblk[(long)n*1024 + k0 + k];
        }
        __syncthreads();
        #pragma unroll
        for (int k=0;k<16;k++){
            ulonglong2 a01 = *(const ulonglong2*)&As2[k][ty*8];
            ulonglong2 a23 = *(const ulonglong2*)&As2[k][ty*8+4];
            ulonglong2 bb  = *(const ulonglong2*)&Bs[k][tx*4];
            acc2[0][0]=fma2(a01.x, bb.x, acc2[0][0]); acc2[0][1]=fma2(a01.x, bb.y, acc2[0][1]);
            acc2[1][0]=fma2(a01.y, bb.x, acc2[1][0]); acc2[1][1]=fma2(a01.y, bb.y, acc2[1][1]);
            acc2[2][0]=fma2(a23.x, bb.x, acc2[2][0]); acc2[2][1]=fma2(a23.x, bb.y, acc2[2][1]);
            acc2[3][0]=fma2(a23.y, bb.x, acc2[3][0]); acc2[3][1]=fma2(a23.y, bb.y, acc2[3][1]);
        }
        __syncthreads();
    }
    #pragma unroll
    for(int i=0;i<4;i++){
        float2 c0 = upk2(acc2[i][0]);
        float2 c1 = upk2(acc2[i][1]);
        float4 o = make_float4(c0.x, c0.y, c1.x, c1.y);
        *(float4*)&Cout[(long)(by*64+ty*4+i)*1024 + bx*64+tx*4] = o;
    }
}

// ------------- fused horizontal low: bits [5-9] and [0-4], in-place, LDS.128 -------------
__global__ __launch_bounds__(256) void hlow_kernel(float* __restrict__ psi){
    __shared__ __align__(16) float T[32*36];
    __shared__ __align__(16) float Usm[32*36];
    __shared__ __align__(16) float Rs[1024];
    __shared__ float RsT[1024];
    int tid=threadIdx.x;
    for (int e=tid;e<1024;e+=256){
        float v = g_R[e];
        Rs[e]=v;
        RsT[(e&31)*32 + (e>>5)] = v;
    }
    unsigned base = blockIdx.x*1024u;
    #pragma unroll
    for (int it=0;it<4;it++){
        int e = tid + it*256;
        T[(e>>5)*36 + (e&31)] = psi[base+e];
    }
    __syncthreads();
    int rp = tid & 31, cq = tid >> 5;
    float4 u = make_float4(0.f,0.f,0.f,0.f);
    for (int r=0;r<32;r++){
        float rv = RsT[r*32+rp];
        float4 tr = *(const float4*)&T[r*36 + cq*4];
        u.x += rv*tr.x; u.y += rv*tr.y; u.z += rv*tr.z; u.w += rv*tr.w;
    }
    *(float4*)&Usm[rp*36 + cq*4] = u;
    __syncthreads();
    float w[4];
    #pragma unroll
    for (int i=0;i<4;i++){
        int cp = cq*4+i;
        float acc0=0.f, acc1=0.f, acc2v=0.f, acc3=0.f;
        #pragma unroll
        for (int c8=0;c8<8;c8++){
            float4 rr = *(const float4*)&Rs[cp*32 + c8*4];
            float4 uu = *(const float4*)&Usm[rp*36 + c8*4];
            acc0 += rr.x*uu.x; acc1 += rr.y*uu.y;
            acc2v+= rr.z*uu.z; acc3 += rr.w*uu.w;
        }
        w[i]=(acc0+acc1)+(acc2v+acc3);
    }
    __syncthreads();
    *(float4*)&T[rp*36 + cq*4] = make_float4(w[0],w[1],w[2],w[3]);
    __syncthreads();
    #pragma unroll
    for (int it=0;it<4;it++){
        int e = tid + it*256;
        psi[base+e] = T[(e>>5)*36 + (e&31)];
    }
}

// ------------- fused horizontal high: bits [15-19] and [10-14], packed f32x2 -------------
__global__ __launch_bounds__(256) void hhigh_kernel(float* __restrict__ psi){
    __shared__ __align__(16) float S[8][1036];
    __shared__ __align__(16) float Rs[1024];
    __shared__ float RsT[1024];
    int tid = threadIdx.x;
    for (int e=tid;e<1024;e+=256){
        float v = g_R[e];
        Rs[e]=v;
        RsT[(e&31)*32 + (e>>5)] = v;
    }
    unsigned lowbase = blockIdx.x * 8u;
    for (int it=0; it<32; it++){
        int idx = tid + it*256;
        int lo = idx & 7, k = idx >> 3;
        S[lo][k] = psi[(unsigned)k*1024u + lowbase + (unsigned)lo];
    }
    __syncthreads();
    int low = tid & 7, rp = tid >> 3;
    unsigned long long U2[16];
    #pragma unroll
    for (int e=0;e<16;e++) U2[e]=0ull;
    for (int r=0;r<32;r++){
        float rv = RsT[r*32+rp];
        unsigned long long rvp = pk2(rv, rv);
        const ulonglong2* row2 = (const ulonglong2*)&S[low][r*32];
        #pragma unroll
        for (int c2=0;c2<8;c2++){
            ulonglong2 tp = row2[c2];
            U2[c2*2+0] = fma2(rvp, tp.x, U2[c2*2+0]);
            U2[c2*2+1] = fma2(rvp, tp.y, U2[c2*2+1]);
        }
    }
    float W[32];
    #pragma unroll
    for (int cp=0;cp<32;cp++){
        const ulonglong2* Rp2 = (const ulonglong2*)&Rs[cp*32];
        unsigned long long s2 = 0ull;
        #pragma unroll
        for (int c2=0;c2<8;c2++){
            ulonglong2 rr = Rp2[c2];
            s2 = fma2(rr.x, U2[c2*2+0], s2);
            s2 = fma2(rr.y, U2[c2*2+1], s2);
        }
        float2 f = upk2(s2);
        W[cp] = f.x + f.y;
    }
    __syncthreads();
    #pragma unroll
    for (int cp=0;cp<32;cp++) S[low][rp*32+cp] = W[cp];
    __syncthreads();
    for (int it=0; it<32; it++){
        int idx = tid + it*256;
        int lo = idx & 7, k = idx >> 3;
        psi[(unsigned)k*1024u + lowbase + (unsigned)lo] = S[lo][k];
    }
}

// ------------- v3: columns p=2,3,4, slab widened by bit 0; grid 128 -------------
__global__ __launch_bounds__(256) void v3_kernel(float* __restrict__ psi){
    __shared__ float Cs[256];
    __shared__ float S[2*4352];
    int t=threadIdx.x;
    Cs[t]=g_C16[t];
    unsigned f = blockIdx.x;   // 7 bits -> positions {1,5,6,10,11,15,16}
    unsigned tt=f;
    tt <<= 1;
    tt = ((tt>>2)<<5)   | (tt & 3u);
    tt = ((tt>>7)<<10)  | (tt & 127u);
    tt = ((tt>>12)<<15) | (tt & 4095u);
    tt = ((tt>>17)<<20) | (tt & 131071u);
    unsigned base=tt;
    // load: e = t | (it<<8), 13-bit slab index in address-ascending order
    #pragma unroll
    for (int it=0; it<32; it++){
        unsigned e = (unsigned)t | ((unsigned)it<<8);
        unsigned off = (e&1u) | (((e>>1)&7u)<<2) | (((e>>4)&7u)<<7)
                     | (((e>>7)&7u)<<12) | (((e>>10)&7u)<<17);
        int s0 = e&1;
        int a = ((e>>1)&1)|(((e>>4)&1)<<1)|(((e>>7)&1)<<2)|(((e>>10)&1)<<3);
        int b = ((e>>2)&1)|(((e>>5)&1)<<1)|(((e>>8)&1)<<2)|(((e>>11)&1)<<3);
        int c = ((e>>3)&1)|(((e>>6)&1)<<1)|(((e>>9)&1)<<2)|(((e>>12)&1)<<3);
        S[s0*4352 + (b*16+c)*17 + a] = psi[base + off];
    }
    __syncthreads();
    // stage A: transform a; thread owns row (b*16+c)=t for both sub-slabs
    #pragma unroll
    for (int s0=0;s0<2;s0++){
        float* Sp = S + s0*4352;
        float v[16], o[16];
        #pragma unroll
        for (int a=0;a<16;a++) v[a]=Sp[t*17+a];
        #pragma unroll
        for (int ap=0;ap<16;ap++){
            float acc=0.f;
            #pragma unroll
            for (int a=0;a<16;a++) acc += Cs[ap*16+a]*v[a];
            o[ap]=acc;
        }
        #pragma unroll
        for (int a=0;a<16;a++) Sp[t*17+a]=o[a];
    }
    __syncthreads();
    // stage B: transform b
    #pragma unroll
    for (int s0=0;s0<2;s0++){
        float* Sp = S + s0*4352;
        int a=t>>4, c=t&15;
        float v[16], o[16];
        #pragma unroll
        for (int b=0;b<16;b++) v[b]=Sp[(b*16+c)*17 + a];
        #pragma unroll
        for (int bp=0;bp<16;bp++){
            float acc=0.f;
            #pragma unroll
            for (int b=0;b<16;b++) acc += Cs[bp*16+b]*v[b];
            o[bp]=acc;
        }
        #pragma unroll
        for (int b=0;b<16;b++) Sp[(b*16+c)*17 + a]=o[b];
    }
    __syncthreads();
    // stage C: transform c
    #pragma unroll
    for (int s0=0;s0<2;s0++){
        float* Sp = S + s0*4352;
        int a=t&15, b=t>>4;
        float v[16], o[16];
        #pragma unroll
        for (int c=0;c<16;c++) v[c]=Sp[(b*16+c)*17 + a];
        #pragma unroll
        for (int cp=0;cp<16;cp++){
            float acc=0.f;
            #pragma unroll
            for (int c=0;c<16;c++) acc += Cs[cp*16+c]*v[c];
            o[cp]=acc;
        }
        #pragma unroll
        for (int c=0;c<16;c++) Sp[(b*16+c)*17 + a]=o[c];
    }
    __syncthreads();
    // store (mirror of load)
    #pragma unroll
    for (int it=0; it<32; it++){
        unsigned e = (unsigned)t | ((unsigned)it<<8);
        unsigned off = (e&1u) | (((e>>1)&7u)<<2) | (((e>>4)&7u)<<7)
                     | (((e>>7)&7u)<<12) | (((e>>10)&7u)<<17);
        int s0 = e&1;
        int a = ((e>>1)&1)|(((e>>4)&1)<<1)|(((e>>7)&1)<<2)|(((e>>10)&1)<<3);
        int b = ((e>>2)&1)|(((e>>5)&1)<<1)|(((e>>8)&1)<<2)|(((e>>11)&1)<<3);
        int c = ((e>>3)&1)|(((e>>6)&1)<<1)|(((e>>9)&1)<<2)|(((e>>12)&1)<<3);
        psi[base + off] = S[s0*4352 + (b*16+c)*17 + a];
    }
}

// ------------- v2: columns p=0,1, warp slab widened by bits 2,3; grid 128 -------------
__global__ __launch_bounds__(256) void v2_kernel(float* __restrict__ psi){
    __shared__ float Cs[256];
    __shared__ float Tsm[8][4][16][17];
    int tid=threadIdx.x;
    Cs[tid]=g_C16[tid];
    int w = tid>>5, l = tid&31;
    unsigned f = blockIdx.x*8u + (unsigned)w;   // 10-bit warp-task -> {4,7,8,9,12,13,14,17,18,19}
    unsigned tt = f<<4;
    tt = ((tt>>5)<<7)   | (tt & 31u);
    tt = ((tt>>10)<<12) | (tt & 1023u);
    tt = ((tt>>15)<<17) | (tt & 32767u);
    unsigned base=tt;
    __syncthreads();
    // load: e = l | (it<<5), 10-bit warp-slab index, address-ascending
    #pragma unroll
    for (int it=0; it<32; it++){
        unsigned e = (unsigned)l | ((unsigned)it<<5);
        unsigned off = (e&15u) | (((e>>4)&3u)<<5) | (((e>>6)&3u)<<10) | (((e>>8)&3u)<<15);
        int i0 = (e&1)|(((e>>4)&1)<<1)|(((e>>6)&1)<<2)|(((e>>8)&1)<<3);
        int i1 = ((e>>1)&1)|(((e>>5)&1)<<1)|(((e>>7)&1)<<2)|(((e>>9)&1)<<3);
        int q  = (e>>2)&3;
        Tsm[w][q][i1][i0] = psi[base+off];
    }
    __syncwarp();
    // stage 1: transform i1 (in-place via registers)
    {
        int c = l&15, oh = l>>4;
        float u[4][8];
        #pragma unroll
        for (int q=0;q<4;q++){
            #pragma unroll
            for (int oo=0;oo<8;oo++){
                int o = oh*8+oo;
                float acc=0.f;
                #pragma unroll
                for (int k=0;k<16;k++) acc += Cs[o*16+k]*Tsm[w][q][k][c];
                u[q][oo]=acc;
            }
        }
        __syncwarp();
        #pragma unroll
        for (int q=0;q<4;q++)
            #pragma unroll
            for (int oo=0;oo<8;oo++) Tsm[w][q][oh*8+oo][c]=u[q][oo];
    }
    __syncwarp();
    // stage 2: transform i0 (in-place via registers)
    {
        int r = l&15, half = l>>4;
        float u[4][8];
        #pragma unroll
        for (int q=0;q<4;q++){
            #pragma unroll
            for (int ii=0;ii<8;ii++){
                int i0p = half*8+ii;
                float acc=0.f;
                #pragma unroll
                for (int c=0;c<16;c++) acc += Cs[i0p*16+c]*Tsm[w][q][r][c];
                u[q][ii]=acc;
            }
        }
        __syncwarp();
        #pragma unroll
        for (int q=0;q<4;q++)
            #pragma unroll
            for (int ii=0;ii<8;ii++) Tsm[w][q][r][half*8+ii]=u[q][ii];
    }
    __syncwarp();
    // store (mirror of load)
    #pragma unroll
    for (int it=0; it<32; it++){
        unsigned e = (unsigned)l | ((unsigned)it<<5);
        unsigned off = (e&15u) | (((e>>4)&3u)<<5) | (((e>>6)&3u)<<10) | (((e>>8)&3u)<<15);
        int i0 = (e&1)|(((e>>4)&1)<<1)|(((e>>6)&1)<<2)|(((e>>8)&1)<<3);
        int i1 = ((e>>1)&1)|(((e>>5)&1)<<1)|(((e>>7)&1)<<2)|(((e>>9)&1)<<3);
        int q  = (e>>2)&3;
        psi[base+off] = Tsm[w][q][i1][i0];
    }
}

// ------------- gather 64 amplitudes -------------
__global__ void gather_kernel(const int* __restrict__ x, const float* __restrict__ psi,
                              float* __restrict__ out){
    int b = threadIdx.x;
    unsigned idx=0;
    #pragma unroll
    for (int j=0;j<20;j++) idx = (idx<<1) | (unsigned)x[b*20+j];
    out[b]=psi[idx];
}

extern "C" void kernel_launch(void* const* d_in, const int* in_sizes, int n_in,
                              void* d_out, int out_size){
    const int*   x    = (const int*)d_in[0];
    const float* peps = (const float*)d_in[1];
    const float* gate = (const float*)d_in[2];
    float* out = (float*)d_out;

    float *A,*Cm,*psi;
    cudaGetSymbolAddress((void**)&A,    g_A);
    cudaGetSymbolAddress((void**)&Cm,   g_Cm);
    cudaGetSymbolAddress((void**)&psi,  g_psi);

    prep_kernel<<<11,256>>>(peps, gate);
    fold23_kernel<<<dim3(256,2),256>>>();
    fold4_kernel<<<dim3(256,2),256>>>();

    sgemm_kernel<<<dim3(16,16),256>>>(A, Cm, psi);

    for (int sweep=0; sweep<5; sweep++){
        hhigh_kernel<<<128,256>>>(psi);   // bits [15-19] and [10-14]
        hlow_kernel<<<1024,256>>>(psi);   // bits [5-9] and [0-4]
        v3_kernel<<<128,256>>>(psi);      // columns p=2,3,4 (+bit0 slab)
        v2_kernel<<<128,256>>>(psi);      // columns p=0,1 (+bits 2,3 slab)
    }

    gather_kernel<<<1,64>>>(x, psi, out);
}

// round 10
// speedup vs baseline: 2.0315x; 1.0269x over previous
#include <cuda_runtime.h>

#define NS (1<<20)

// ---- device scratch (static, allocation-free) ----
__device__ float g_T0[NS];     // fold23 out pair0; later sgemm partial K-half 0
__device__ float g_T1[NS];     // fold23 out pair1; later sgemm partial K-half 1
__device__ float g_A[NS];      // A[P01][bond] 1024x1024
__device__ float g_Cm[NS];     // Ct[P23][bond]  (1024x1024, transposed C)
__device__ float g_psi[NS];    // statevector (in-place for sweeps)
__device__ float g_R[1024];    // 32x32 row-chain operator [out][in]
__device__ float g_C16[256];   // 16x16 column-chain operator
__device__ float g_K[10*4096]; // per-column pair tensors K_j

// ---- packed fp32x2 helpers ----
__device__ __forceinline__ unsigned long long pk2(float x, float y){
    unsigned long long r; asm("mov.b64 %0,{%1,%2};" : "=l"(r) : "f"(x), "f"(y)); return r;
}
__device__ __forceinline__ float2 upk2(unsigned long long v){
    float2 r; asm("mov.b64 {%0,%1},%2;" : "=f"(r.x), "=f"(r.y) : "l"(v)); return r;
}
__device__ __forceinline__ unsigned long long fma2(unsigned long long a,
        unsigned long long b, unsigned long long c){
    unsigned long long d;
    asm("fma.rn.f32x2 %0,%1,%2,%3;" : "=l"(d) : "l"(a), "l"(b), "l"(c));
    return d;
}

__device__ __forceinline__ float peps_el(const float* __restrict__ peps,
                                         int i,int j,int p,int u,int d,int l,int r){
    return peps[(((((i*5+j)*2+p)*4+u)*4+d)*4+l)*4+r];
}

// ------------- prep: blocks 0..9 compute K_j; block 10 builds R and C16 -------------
__global__ void prep_kernel(const float* __restrict__ peps, const float* __restrict__ gate){
    int t = threadIdx.x;  // 256
    if (blockIdx.x < 10){
        int blk = blockIdx.x;
        int pair = blk/5, j = blk%5;
        int L = (j==0)?1:4, R = (j==4)?1:4;
        int nk = 16*L*L*R*R;
        float* Kg = g_K + blk*4096;
        for (int e=t; e<nk; e+=256){
            int tt=e;
            int rb=tt%R; tt/=R; int ra=tt%R; tt/=R;
            int lb=tt%L; tt/=L; int la=tt%L; tt/=L;
            int mid=tt&3; tt>>=2;
            int pb=tt&1; int pa=tt>>1;
            float s=0.f;
            if (pair==0){
                #pragma unroll
                for(int m=0;m<4;m++)
                    s += peps_el(peps,0,j,pa,0,m,la,ra)*peps_el(peps,1,j,pb,m,mid,lb,rb);
            } else {
                #pragma unroll
                for(int m=0;m<4;m++)
                    s += peps_el(peps,2,j,pa,mid,m,la,ra)*peps_el(peps,3,j,pb,m,0,lb,rb);
            }
            Kg[e]=s;
        }
        return;
    }
    // ---- block 10: build R (32x32) and C16 (16x16) with 256 threads ----
    __shared__ float g[16];
    __shared__ float A0[1024];
    __shared__ float A1[1024];
    if (t<16) g[t]=gate[t];
    for (int e=t;e<1024;e+=256) A0[e] = ((e>>5)==(e&31)) ? 1.0f : 0.0f;
    __syncthreads();
    #pragma unroll
    for (int k=0;k<4;k++){
        const float* cur = (k&1)? A1 : A0;
        float* nxt       = (k&1)? A0 : A1;
        int hb=4-k, lb=3-k;
        for (int e=t;e<1024;e+=256){
            int rp=e>>5, c=e&31;
            int i1p=(rp>>hb)&1, i2p=(rp>>lb)&1;
            int base = rp & ~((1<<hb)|(1<<lb));
            float acc=0.f;
            #pragma unroll
            for(int i1=0;i1<2;i1++)
            #pragma unroll
            for(int i2=0;i2<2;i2++)
                acc += g[(i1p*2+i2p)*4+(i1*2+i2)] * cur[(base|(i1<<hb)|(i2<<lb))*32 + c];
            nxt[e]=acc;
        }
        __syncthreads();
    }
    for (int e=t;e<1024;e+=256) g_R[e]=A0[e];
    __syncthreads();
    A0[t] = ((t>>4)==(t&15)) ? 1.0f : 0.0f;
    __syncthreads();
    #pragma unroll
    for (int k=0;k<3;k++){
        const float* cur=(k&1)?A1:A0;
        float* nxt      =(k&1)?A0:A1;
        int hb=3-k, lb=2-k;
        int rp=t>>4, c=t&15;
        int i1p=(rp>>hb)&1,i2p=(rp>>lb)&1;
        int base = rp & ~((1<<hb)|(1<<lb));
        float acc=0.f;
        #pragma unroll
        for(int i1=0;i1<2;i1++)
        #pragma unroll
        for(int i2=0;i2<2;i2++)
            acc += g[(i1p*2+i2p)*4+(i1*2+i2)]*cur[(base|(i1<<hb)|(i2<<lb))*16+c];
        __syncthreads();
        nxt[t]=acc;
        __syncthreads();
    }
    g_C16[t]=A1[t];
}

// ------------- fold23 (absorbs kkprep): T4 = T2 x KK23 ; grid (256, 2) -------------
__global__ __launch_bounds__(256) void fold23_kernel(){
    int t = threadIdx.x;
    int pb = blockIdx.x, pair = blockIdx.y;
    int pd = pb&15, pbb = (pb>>4)&3, pa = pb>>6;
    const float* Kbase = g_K + pair*5*4096;
    __shared__ float K0s[256];
    __shared__ float K1s[4096];
    __shared__ float K2s[256], K3s[256];
    __shared__ float Ts[256*20];
    __shared__ float Ks[256];
    K0s[t] = Kbase[t];
    for (int e=t;e<4096;e+=256) K1s[e]=Kbase[4096+e];
    int kb2 = ((pa>>1)*2+(pbb>>1))*4+(pd>>2);
    int kb3 = ((pa&1)*2+(pbb&1))*4+(pd&3);
    K2s[t] = Kbase[2*4096 + kb2*256 + t];
    K3s[t] = Kbase[3*4096 + kb3*256 + t];
    __syncthreads();
    {
        int abc=t;
        int a2=abc>>6, b2=(abc>>4)&3, c2=abc&15;
        int kb0 = ((a2>>1)*2+(b2>>1))*4 + (c2>>2);
        int kb1 = ((a2&1)*2+(b2&1))*4 + (c2&3);
        #pragma unroll
        for (int r=0;r<16;r++){
            float acc=0.f;
            #pragma unroll
            for (int m=0;m<16;m++) acc += K0s[kb0*16+m]*K1s[(kb1*16+m)*16+r];
            Ts[t*20+r]=acc;
        }
    }
    {
        int l=t>>4, r=t&15;
        float acc=0.f;
        #pragma unroll
        for (int m=0;m<16;m++) acc += K2s[l*16+m]*K3s[m*16+r];
        Ks[t]=acc;
    }
    __syncthreads();
    float* Tout = pair? g_T1 : g_T0;
    int a2=t>>6, b2=(t>>4)&3, c2=t&15;
    float tv[16];
    #pragma unroll
    for (int l=0;l<16;l++) tv[l]=Ts[t*20+l];
    long obase = ((((long)(a2*4+pa)*16 + b2*4+pbb)*256) + c2*16+pd)*16;
    #pragma unroll
    for (int r4=0;r4<4;r4++){
        float4 o; float* po=(float*)&o;
        #pragma unroll
        for (int q=0;q<4;q++){
            int r=r4*4+q;
            float acc=0.f;
            #pragma unroll
            for (int l=0;l<16;l++) acc += tv[l]*Ks[l*16+r];
            po[q]=acc;
        }
        *(float4*)&Tout[obase + r4*4] = o;
    }
}

// ------------- fold4: final column -> A / Ct ; grid (256, 2), thread = c -------------
__global__ __launch_bounds__(256) void fold4_kernel(){
    int c = threadIdx.x;
    int a = blockIdx.x >> 4, b = blockIdx.x & 15;
    int pair = blockIdx.y;
    __shared__ float K4s[256];
    K4s[c] = g_K[(pair*5+4)*4096 + c];
    __syncthreads();
    const float* Tin = pair? g_T1 : g_T0;
    const float* tp = &Tin[(((long)(a*16+b)*256)+c)*16];
    float tv[16];
    #pragma unroll
    for (int l4=0;l4<4;l4++){
        float4 v = *(const float4*)&tp[l4*4];
        tv[l4*4+0]=v.x; tv[l4*4+1]=v.y; tv[l4*4+2]=v.z; tv[l4*4+3]=v.w;
    }
    if (pair==0){
        long base = (long)a*65536 + (long)b*2048 + c*4;
        #pragma unroll
        for (int p0=0;p0<2;p0++)
        #pragma unroll
        for (int p1=0;p1<2;p1++){
            float4 o; float* po=(float*)&o;
            #pragma unroll
            for (int d1=0;d1<4;d1++){
                int kb=(p0*2+p1)*4+d1;
                float acc=0.f;
                #pragma unroll
                for (int l=0;l<16;l++) acc += tv[l]*K4s[kb*16+l];
                po[d1]=acc;
            }
            *(float4*)&g_A[base + p0*32768 + p1*1024] = o;
        }
    } else {
        #pragma unroll
        for (int p0=0;p0<2;p0++)
        #pragma unroll
        for (int p1=0;p1<2;p1++){
            float4 o; float* po=(float*)&o;
            #pragma unroll
            for (int d1=0;d1<4;d1++){
                int kb=(p0*2+p1)*4+d1;
                float acc=0.f;
                #pragma unroll
                for (int l=0;l<16;l++) acc += tv[l]*K4s[kb*16+l];
                po[d1]=acc;
            }
            long col = (long)(a*64 + p0*32 + b*2 + p1);
            *(float4*)&g_Cm[col*1024 + c*4] = o;
        }
    }
}

// ------------- sgemm split-K: partial[z] = A[:,zK/2:(z+1)K/2] @ Ct^T slice -------------
// grid (8, 8, 2): 128x128 tile, 256 threads, 8x8 micro-tile, f32x2 pairs along M.
__global__ __launch_bounds__(256) void sgemm_kernel(const float* __restrict__ A,
        const float* __restrict__ Bt){
    __shared__ __align__(16) float As[16*132];
    __shared__ __align__(16) float Bs[16*132];
    int tid=threadIdx.x;
    int tx=tid&15, ty=tid>>4;          // tx: m-group (8 rows), ty: n-group (8 cols)
    unsigned long long acc[4][8];
    #pragma unroll
    for (int i=0;i<4;i++)
      #pragma unroll
      for (int j=0;j<8;j++) acc[i][j]=0ull;

    const float* Ab = A  + (long)(blockIdx.y*128)*1024 + blockIdx.z*512;
    const float* Bb = Bt + (long)(blockIdx.x*128)*1024 + blockIdx.z*512;
    float* Cp = blockIdx.z ? g_T1 : g_T0;

    for (int k0=0;k0<512;k0+=16){
        #pragma unroll
        for (int e=0;e<8;e++){
            int idx = tid + e*256;      // 0..2047
            int m = idx >> 4, k = idx & 15;
            As[k*132 + m] = Ab[(long)m*1024 + k0 + k];
        }
        #pragma unroll
        for (int e=0;e<8;e++){
            int idx = tid + e*256;
            int n = idx >> 4, k = idx & 15;
            Bs[k*132 + n] = Bb[(long)n*1024 + k0 + k];
        }
        __syncthreads();
        #pragma unroll
        for (int k=0;k<16;k++){
            ulonglong2 a01 = *(const ulonglong2*)&As[k*132 + tx*8];
            ulonglong2 a23 = *(const ulonglong2*)&As[k*132 + tx*8 + 4];
            float4 b0 = *(const float4*)&Bs[k*132 + ty*8];
            float4 b1 = *(const float4*)&Bs[k*132 + ty*8 + 4];
            unsigned long long bp[8];
            bp[0]=pk2(b0.x,b0.x); bp[1]=pk2(b0.y,b0.y);
            bp[2]=pk2(b0.z,b0.z); bp[3]=pk2(b0.w,b0.w);
            bp[4]=pk2(b1.x,b1.x); bp[5]=pk2(b1.y,b1.y);
            bp[6]=pk2(b1.z,b1.z); bp[7]=pk2(b1.w,b1.w);
            unsigned long long av[4]={a01.x,a01.y,a23.x,a23.y};
            #pragma unroll
            for (int i=0;i<4;i++)
                #pragma unroll
                for (int j=0;j<8;j++)
                    acc[i][j]=fma2(av[i], bp[j], acc[i][j]);
        }
        __syncthreads();
    }
    // store: a-pair i covers rows m0+2i, m0+2i+1 ; cols n0..n0+7
    int m0 = blockIdx.y*128 + tx*8;
    int n0 = blockIdx.x*128 + ty*8;
    #pragma unroll
    for (int i=0;i<4;i++){
        float lo[8], hi[8];
        #pragma unroll
        for (int j=0;j<8;j++){
            float2 f = upk2(acc[i][j]);
            lo[j]=f.x; hi[j]=f.y;
        }
        long r0 = (long)(m0 + 2*i)*1024 + n0;
        long r1 = r0 + 1024;
        *(float4*)&Cp[r0]   = make_float4(lo[0],lo[1],lo[2],lo[3]);
        *(float4*)&Cp[r0+4] = make_float4(lo[4],lo[5],lo[6],lo[7]);
        *(float4*)&Cp[r1]   = make_float4(hi[0],hi[1],hi[2],hi[3]);
        *(float4*)&Cp[r1+4] = make_float4(hi[4],hi[5],hi[6],hi[7]);
    }
}

// ------------- add partial K-halves into psi -------------
__global__ __launch_bounds__(256) void add_kernel(float* __restrict__ psi){
    unsigned i = (blockIdx.x*256u + threadIdx.x)*4u;
    float4 a = *(const float4*)&g_T0[i];
    float4 b = *(const float4*)&g_T1[i];
    *(float4*)&psi[i] = make_float4(a.x+b.x, a.y+b.y, a.z+b.z, a.w+b.w);
}

// ------------- fused horizontal low: bits [5-9] and [0-4], in-place, LDS.128 -------------
__global__ __launch_bounds__(256) void hlow_kernel(float* __restrict__ psi){
    __shared__ __align__(16) float T[32*36];
    __shared__ __align__(16) float Usm[32*36];
    __shared__ __align__(16) float Rs[1024];
    __shared__ float RsT[1024];
    int tid=threadIdx.x;
    for (int e=tid;e<1024;e+=256){
        float v = g_R[e];
        Rs[e]=v;
        RsT[(e&31)*32 + (e>>5)] = v;
    }
    unsigned base = blockIdx.x*1024u;
    #pragma unroll
    for (int it=0;it<4;it++){
        int e = tid + it*256;
        T[(e>>5)*36 + (e&31)] = psi[base+e];
    }
    __syncthreads();
    int rp = tid & 31, cq = tid >> 5;
    float4 u = make_float4(0.f,0.f,0.f,0.f);
    for (int r=0;r<32;r++){
        float rv = RsT[r*32+rp];
        float4 tr = *(const float4*)&T[r*36 + cq*4];
        u.x += rv*tr.x; u.y += rv*tr.y; u.z += rv*tr.z; u.w += rv*tr.w;
    }
    *(float4*)&Usm[rp*36 + cq*4] = u;
    __syncthreads();
    float w[4];
    #pragma unroll
    for (int i=0;i<4;i++){
        int cp = cq*4+i;
        float acc0=0.f, acc1=0.f, acc2v=0.f, acc3=0.f;
        #pragma unroll
        for (int c8=0;c8<8;c8++){
            float4 rr = *(const float4*)&Rs[cp*32 + c8*4];
            float4 uu = *(const float4*)&Usm[rp*36 + c8*4];
            acc0 += rr.x*uu.x; acc1 += rr.y*uu.y;
            acc2v+= rr.z*uu.z; acc3 += rr.w*uu.w;
        }
        w[i]=(acc0+acc1)+(acc2v+acc3);
    }
    __syncthreads();
    *(float4*)&T[rp*36 + cq*4] = make_float4(w[0],w[1],w[2],w[3]);
    __syncthreads();
    #pragma unroll
    for (int it=0;it<4;it++){
        int e = tid + it*256;
        psi[base+e] = T[(e>>5)*36 + (e&31)];
    }
}

// ------------- fused horizontal high: bits [15-19] and [10-14], packed f32x2 -------------
__global__ __launch_bounds__(256) void hhigh_kernel(float* __restrict__ psi){
    __shared__ __align__(16) float S[8][1036];
    __shared__ __align__(16) float Rs[1024];
    __shared__ float RsT[1024];
    int tid = threadIdx.x;
    for (int e=tid;e<1024;e+=256){
        float v = g_R[e];
        Rs[e]=v;
        RsT[(e&31)*32 + (e>>5)] = v;
    }
    unsigned lowbase = blockIdx.x * 8u;
    for (int it=0; it<32; it++){
        int idx = tid + it*256;
        int lo = idx & 7, k = idx >> 3;
        S[lo][k] = psi[(unsigned)k*1024u + lowbase + (unsigned)lo];
    }
    __syncthreads();
    int low = tid & 7, rp = tid >> 3;
    unsigned long long U2[16];
    #pragma unroll
    for (int e=0;e<16;e++) U2[e]=0ull;
    for (int r=0;r<32;r++){
        float rv = RsT[r*32+rp];
        unsigned long long rvp = pk2(rv, rv);
        const ulonglong2* row2 = (const ulonglong2*)&S[low][r*32];
        #pragma unroll
        for (int c2=0;c2<8;c2++){
            ulonglong2 tp = row2[c2];
            U2[c2*2+0] = fma2(rvp, tp.x, U2[c2*2+0]);
            U2[c2*2+1] = fma2(rvp, tp.y, U2[c2*2+1]);
        }
    }
    float W[32];
    #pragma unroll
    for (int cp=0;cp<32;cp++){
        const ulonglong2* Rp2 = (const ulonglong2*)&Rs[cp*32];
        unsigned long long s2 = 0ull;
        #pragma unroll
        for (int c2=0;c2<8;c2++){
            ulonglong2 rr = Rp2[c2];
            s2 = fma2(rr.x, U2[c2*2+0], s2);
            s2 = fma2(rr.y, U2[c2*2+1], s2);
        }
        float2 f = upk2(s2);
        W[cp] = f.x + f.y;
    }
    __syncthreads();
    #pragma unroll
    for (int cp=0;cp<32;cp++) S[low][rp*32+cp] = W[cp];
    __syncthreads();
    for (int it=0; it<32; it++){
        int idx = tid + it*256;
        int lo = idx & 7, k = idx >> 3;
        psi[(unsigned)k*1024u + lowbase + (unsigned)lo] = S[lo][k];
    }
}

// ------------- v3: columns p=2,3,4, slab widened by bit 0; grid 128 -------------
__global__ __launch_bounds__(256) void v3_kernel(float* __restrict__ psi){
    __shared__ float Cs[256];
    __shared__ float S[2*4352];
    int t=threadIdx.x;
    Cs[t]=g_C16[t];
    unsigned f = blockIdx.x;
    unsigned tt=f;
    tt <<= 1;
    tt = ((tt>>2)<<5)   | (tt & 3u);
    tt = ((tt>>7)<<10)  | (tt & 127u);
    tt = ((tt>>12)<<15) | (tt & 4095u);
    tt = ((tt>>17)<<20) | (tt & 131071u);
    unsigned base=tt;
    #pragma unroll
    for (int it=0; it<32; it++){
        unsigned e = (unsigned)t | ((unsigned)it<<8);
        unsigned off = (e&1u) | (((e>>1)&7u)<<2) | (((e>>4)&7u)<<7)
                     | (((e>>7)&7u)<<12) | (((e>>10)&7u)<<17);
        int s0 = e&1;
        int a = ((e>>1)&1)|(((e>>4)&1)<<1)|(((e>>7)&1)<<2)|(((e>>10)&1)<<3);
        int b = ((e>>2)&1)|(((e>>5)&1)<<1)|(((e>>8)&1)<<2)|(((e>>11)&1)<<3);
        int c = ((e>>3)&1)|(((e>>6)&1)<<1)|(((e>>9)&1)<<2)|(((e>>12)&1)<<3);
        S[s0*4352 + (b*16+c)*17 + a] = psi[base + off];
    }
    __syncthreads();
    #pragma unroll
    for (int s0=0;s0<2;s0++){
        float* Sp = S + s0*4352;
        float v[16], o[16];
        #pragma unroll
        for (int a=0;a<16;a++) v[a]=Sp[t*17+a];
        #pragma unroll
        for (int ap=0;ap<16;ap++){
            float acc=0.f;
            #pragma unroll
            for (int a=0;a<16;a++) acc += Cs[ap*16+a]*v[a];
            o[ap]=acc;
        }
        #pragma unroll
        for (int a=0;a<16;a++) Sp[t*17+a]=o[a];
    }
    __syncthreads();
    #pragma unroll
    for (int s0=0;s0<2;s0++){
        float* Sp = S + s0*4352;
        int a=t>>4, c=t&15;
        float v[16], o[16];
        #pragma unroll
        for (int b=0;b<16;b++) v[b]=Sp[(b*16+c)*17 + a];
        #pragma unroll
        for (int bp=0;bp<16;bp++){
            float acc=0.f;
            #pragma unroll
            for (int b=0;b<16;b++) acc += Cs[bp*16+b]*v[b];
            o[bp]=acc;
        }
        #pragma unroll
        for (int b=0;b<16;b++) Sp[(b*16+c)*17 + a]=o[b];
    }
    __syncthreads();
    #pragma unroll
    for (int s0=0;s0<2;s0++){
        float* Sp = S + s0*4352;
        int a=t&15, b=t>>4;
        float v[16], o[16];
        #pragma unroll
        for (int c=0;c<16;c++) v[c]=Sp[(b*16+c)*17 + a];
        #pragma unroll
        for (int cp=0;cp<16;cp++){
            float acc=0.f;
            #pragma unroll
            for (int c=0;c<16;c++) acc += Cs[cp*16+c]*v[c];
            o[cp]=acc;
        }
        #pragma unroll
        for (int c=0;c<16;c++) Sp[(b*16+c)*17 + a]=o[c];
    }
    __syncthreads();
    #pragma unroll
    for (int it=0; it<32; it++){
        unsigned e = (unsigned)t | ((unsigned)it<<8);
        unsigned off = (e&1u) | (((e>>1)&7u)<<2) | (((e>>4)&7u)<<7)
                     | (((e>>7)&7u)<<12) | (((e>>10)&7u)<<17);
        int s0 = e&1;
        int a = ((e>>1)&1)|(((e>>4)&1)<<1)|(((e>>7)&1)<<2)|(((e>>10)&1)<<3);
        int b = ((e>>2)&1)|(((e>>5)&1)<<1)|(((e>>8)&1)<<2)|(((e>>11)&1)<<3);
        int c = ((e>>3)&1)|(((e>>6)&1)<<1)|(((e>>9)&1)<<2)|(((e>>12)&1)<<3);
        psi[base + off] = S[s0*4352 + (b*16+c)*17 + a];
    }
}

// ------------- v2: columns p=0,1, warp slab widened by bits 2,3; grid 128 -------------
__global__ __launch_bounds__(256) void v2_kernel(float* __restrict__ psi){
    __shared__ float Cs[256];
    __shared__ float Tsm[8][4][16][17];
    int tid=threadIdx.x;
    Cs[tid]=g_C16[tid];
    int w = tid>>5, l = tid&31;
    unsigned f = blockIdx.x*8u + (unsigned)w;
    unsigned tt = f<<4;
    tt = ((tt>>5)<<7)   | (tt & 31u);
    tt = ((tt>>10)<<12) | (tt & 1023u);
    tt = ((tt>>15)<<17) | (tt & 32767u);
    unsigned base=tt;
    __syncthreads();
    #pragma unroll
    for (int it=0; it<32; it++){
        unsigned e = (unsigned)l | ((unsigned)it<<5);
        unsigned off = (e&15u) | (((e>>4)&3u)<<5) | (((e>>6)&3u)<<10) | (((e>>8)&3u)<<15);
        int i0 = (e&1)|(((e>>4)&1)<<1)|(((e>>6)&1)<<2)|(((e>>8)&1)<<3);
        int i1 = ((e>>1)&1)|(((e>>5)&1)<<1)|(((e>>7)&1)<<2)|(((e>>9)&1)<<3);
        int q  = (e>>2)&3;
        Tsm[w][q][i1][i0] = psi[base+off];
    }
    __syncwarp();
    {
        int c = l&15, oh = l>>4;
        float u[4][8];
        #pragma unroll
        for (int q=0;q<4;q++){
            #pragma unroll
            for (int oo=0;oo<8;oo++){
                int o = oh*8+oo;
                float acc=0.f;
                #pragma unroll
                for (int k=0;k<16;k++) acc += Cs[o*16+k]*Tsm[w][q][k][c];
                u[q][oo]=acc;
            }
        }
        __syncwarp();
        #pragma unroll
        for (int q=0;q<4;q++)
            #pragma unroll
            for (int oo=0;oo<8;oo++) Tsm[w][q][oh*8+oo][c]=u[q][oo];
    }
    __syncwarp();
    {
        int r = l&15, half = l>>4;
        float u[4][8];
        #pragma unroll
        for (int q=0;q<4;q++){
            #pragma unroll
            for (int ii=0;ii<8;ii++){
                int i0p = half*8+ii;
                float acc=0.f;
                #pragma unroll
                for (int c=0;c<16;c++) acc += Cs[i0p*16+c]*Tsm[w][q][r][c];
                u[q][ii]=acc;
            }
        }
        __syncwarp();
        #pragma unroll
        for (int q=0;q<4;q++)
            #pragma unroll
            for (int ii=0;ii<8;ii++) Tsm[w][q][r][half*8+ii]=u[q][ii];
    }
    __syncwarp();
    #pragma unroll
    for (int it=0; it<32; it++){
        unsigned e = (unsigned)l | ((unsigned)it<<5);
        unsigned off = (e&15u) | (((e>>4)&3u)<<5) | (((e>>6)&3u)<<10) | (((e>>8)&3u)<<15);
        int i0 = (e&1)|(((e>>4)&1)<<1)|(((e>>6)&1)<<2)|(((e>>8)&1)<<3);
        int i1 = ((e>>1)&1)|(((e>>5)&1)<<1)|(((e>>7)&1)<<2)|(((e>>9)&1)<<3);
        int q  = (e>>2)&3;
        psi[base+off] = Tsm[w][q][i1][i0];
    }
}

// ------------- gather 64 amplitudes -------------
__global__ void gather_kernel(const int* __restrict__ x, const float* __restrict__ psi,
                              float* __restrict__ out){
    int b = threadIdx.x;
    unsigned idx=0;
    #pragma unroll
    for (int j=0;j<20;j++) idx = (idx<<1) | (unsigned)x[b*20+j];
    out[b]=psi[idx];
}

extern "C" void kernel_launch(void* const* d_in, const int* in_sizes, int n_in,
                              void* d_out, int out_size){
    const int*   x    = (const int*)d_in[0];
    const float* peps = (const float*)d_in[1];
    const float* gate = (const float*)d_in[2];
    float* out = (float*)d_out;

    float *A,*Cm,*psi;
    cudaGetSymbolAddress((void**)&A,    g_A);
    cudaGetSymbolAddress((void**)&Cm,   g_Cm);
    cudaGetSymbolAddress((void**)&psi,  g_psi);

    prep_kernel<<<11,256>>>(peps, gate);
    fold23_kernel<<<dim3(256,2),256>>>();
    fold4_kernel<<<dim3(256,2),256>>>();

    sgemm_kernel<<<dim3(8,8,2),256>>>(A, Cm);
    add_kernel<<<1024,256>>>(psi);

    for (int sweep=0; sweep<5; sweep++){
        hhigh_kernel<<<128,256>>>(psi);   // bits [15-19] and [10-14]
        hlow_kernel<<<1024,256>>>(psi);   // bits [5-9] and [0-4]
        v3_kernel<<<128,256>>>(psi);      // columns p=2,3,4 (+bit0 slab)
        v2_kernel<<<128,256>>>(psi);      // columns p=0,1 (+bits 2,3 slab)
    }

    gather_kernel<<<1,64>>>(x, psi, out);
}

// round 13
// speedup vs baseline: 2.3565x; 1.1600x over previous
#include <cuda_runtime.h>
#include <cuda_bf16.h>
#include <cstdint>

#define NS (1<<20)

// ---- device scratch (static, allocation-free) ----
__device__ float g_T0[NS];     // fold23 out pair0; later bf16 A panels (hi|lo)
__device__ float g_T1[NS];     // fold23 out pair1; later bf16 B panels (hi|lo)
__device__ float g_A[NS];      // A[P01][bond] 1024x1024
__device__ float g_Cm[NS];     // Ct[P23][bond]  (1024x1024, transposed C)
__device__ float g_psi[NS];    // statevector (in-place for sweeps)
__device__ float g_R[1024];    // 32x32 row-chain operator [out][in]
__device__ float g_C16[256];   // 16x16 column-chain operator
__device__ float g_K[10*4096]; // per-column pair tensors K_j

// ---- packed fp32x2 helpers ----
__device__ __forceinline__ unsigned long long pk2(float x, float y){
    unsigned long long r; asm("mov.b64 %0,{%1,%2};" : "=l"(r) : "f"(x), "f"(y)); return r;
}
__device__ __forceinline__ float2 upk2(unsigned long long v){
    float2 r; asm("mov.b64 {%0,%1},%2;" : "=f"(r.x), "=f"(r.y) : "l"(v)); return r;
}
__device__ __forceinline__ unsigned long long fma2(unsigned long long a,
        unsigned long long b, unsigned long long c){
    unsigned long long d;
    asm("fma.rn.f32x2 %0,%1,%2,%3;" : "=l"(d) : "l"(a), "l"(b), "l"(c));
    return d;
}

__device__ __forceinline__ float peps_el(const float* __restrict__ peps,
                                         int i,int j,int p,int u,int d,int l,int r){
    return peps[(((((i*5+j)*2+p)*4+u)*4+d)*4+l)*4+r];
}

__device__ __forceinline__ unsigned smem_u32(const void* p){
    unsigned a;
    asm("{ .reg .u64 t; cvta.to.shared.u64 t, %1; cvt.u32.u64 %0, t; }" : "=r"(a) : "l"(p));
    return a;
}

#define LDSM4(R, addr) asm volatile( \
    "ldmatrix.sync.aligned.m8n8.x4.shared.b16 {%0,%1,%2,%3}, [%4];" \
    : "=r"((R)[0]),"=r"((R)[1]),"=r"((R)[2]),"=r"((R)[3]) : "r"(addr))

#define MMA_BF16(acc, a, b0, b1) asm volatile( \
    "mma.sync.aligned.m16n8k16.row.col.f32.bf16.bf16.f32 " \
    "{%0,%1,%2,%3},{%4,%5,%6,%7},{%8,%9},{%0,%1,%2,%3};" \
    : "+f"((acc)[0]),"+f"((acc)[1]),"+f"((acc)[2]),"+f"((acc)[3]) \
    : "r"((a)[0]),"r"((a)[1]),"r"((a)[2]),"r"((a)[3]), "r"(b0),"r"(b1))

// ------------- prep: blocks 0..9 compute K_j; block 10 builds R and C16 -------------
__global__ void prep_kernel(const float* __restrict__ peps, const float* __restrict__ gate){
    int t = threadIdx.x;  // 256
    if (blockIdx.x < 10){
        int blk = blockIdx.x;
        int pair = blk/5, j = blk%5;
        int L = (j==0)?1:4, R = (j==4)?1:4;
        int nk = 16*L*L*R*R;
        float* Kg = g_K + blk*4096;
        for (int e=t; e<nk; e+=256){
            int tt=e;
            int rb=tt%R; tt/=R; int ra=tt%R; tt/=R;
            int lb=tt%L; tt/=L; int la=tt%L; tt/=L;
            int mid=tt&3; tt>>=2;
            int pb=tt&1; int pa=tt>>1;
            float s=0.f;
            if (pair==0){
                #pragma unroll
                for(int m=0;m<4;m++)
                    s += peps_el(peps,0,j,pa,0,m,la,ra)*peps_el(peps,1,j,pb,m,mid,lb,rb);
            } else {
                #pragma unroll
                for(int m=0;m<4;m++)
                    s += peps_el(peps,2,j,pa,mid,m,la,ra)*peps_el(peps,3,j,pb,m,0,lb,rb);
            }
            Kg[e]=s;
        }
        return;
    }
    __shared__ float g[16];
    __shared__ float A0[1024];
    __shared__ float A1[1024];
    if (t<16) g[t]=gate[t];
    for (int e=t;e<1024;e+=256) A0[e] = ((e>>5)==(e&31)) ? 1.0f : 0.0f;
    __syncthreads();
    #pragma unroll
    for (int k=0;k<4;k++){
        const float* cur = (k&1)? A1 : A0;
        float* nxt       = (k&1)? A0 : A1;
        int hb=4-k, lb=3-k;
        for (int e=t;e<1024;e+=256){
            int rp=e>>5, c=e&31;
            int i1p=(rp>>hb)&1, i2p=(rp>>lb)&1;
            int base = rp & ~((1<<hb)|(1<<lb));
            float acc=0.f;
            #pragma unroll
            for(int i1=0;i1<2;i1++)
            #pragma unroll
            for(int i2=0;i2<2;i2++)
                acc += g[(i1p*2+i2p)*4+(i1*2+i2)] * cur[(base|(i1<<hb)|(i2<<lb))*32 + c];
            nxt[e]=acc;
        }
        __syncthreads();
    }
    for (int e=t;e<1024;e+=256) g_R[e]=A0[e];
    __syncthreads();
    A0[t] = ((t>>4)==(t&15)) ? 1.0f : 0.0f;
    __syncthreads();
    #pragma unroll
    for (int k=0;k<3;k++){
        const float* cur=(k&1)?A1:A0;
        float* nxt      =(k&1)?A0:A1;
        int hb=3-k, lb=2-k;
        int rp=t>>4, c=t&15;
        int i1p=(rp>>hb)&1,i2p=(rp>>lb)&1;
        int base = rp & ~((1<<hb)|(1<<lb));
        float acc=0.f;
        #pragma unroll
        for(int i1=0;i1<2;i1++)
        #pragma unroll
        for(int i2=0;i2<2;i2++)
            acc += g[(i1p*2+i2p)*4+(i1*2+i2)]*cur[(base|(i1<<hb)|(i2<<lb))*16+c];
        __syncthreads();
        nxt[t]=acc;
        __syncthreads();
    }
    g_C16[t]=A1[t];
}

// ------------- fold23 (absorbs kkprep): grid (256, 2) -------------
__global__ __launch_bounds__(256) void fold23_kernel(){
    int t = threadIdx.x;
    int pb = blockIdx.x, pair = blockIdx.y;
    int pd = pb&15, pbb = (pb>>4)&3, pa = pb>>6;
    const float* Kbase = g_K + pair*5*4096;
    __shared__ float K0s[256];
    __shared__ float K1s[4096];
    __shared__ float K2s[256], K3s[256];
    __shared__ float Ts[256*20];
    __shared__ float Ks[256];
    K0s[t] = Kbase[t];
    for (int e=t;e<4096;e+=256) K1s[e]=Kbase[4096+e];
    int kb2 = ((pa>>1)*2+(pbb>>1))*4+(pd>>2);
    int kb3 = ((pa&1)*2+(pbb&1))*4+(pd&3);
    K2s[t] = Kbase[2*4096 + kb2*256 + t];
    K3s[t] = Kbase[3*4096 + kb3*256 + t];
    __syncthreads();
    {
        int abc=t;
        int a2=abc>>6, b2=(abc>>4)&3, c2=abc&15;
        int kb0 = ((a2>>1)*2+(b2>>1))*4 + (c2>>2);
        int kb1 = ((a2&1)*2+(b2&1))*4 + (c2&3);
        #pragma unroll
        for (int r=0;r<16;r++){
            float acc=0.f;
            #pragma unroll
            for (int m=0;m<16;m++) acc += K0s[kb0*16+m]*K1s[(kb1*16+m)*16+r];
            Ts[t*20+r]=acc;
        }
    }
    {
        int l=t>>4, r=t&15;
        float acc=0.f;
        #pragma unroll
        for (int m=0;m<16;m++) acc += K2s[l*16+m]*K3s[m*16+r];
        Ks[t]=acc;
    }
    __syncthreads();
    float* Tout = pair? g_T1 : g_T0;
    int a2=t>>6, b2=(t>>4)&3, c2=t&15;
    float tv[16];
    #pragma unroll
    for (int l=0;l<16;l++) tv[l]=Ts[t*20+l];
    long obase = ((((long)(a2*4+pa)*16 + b2*4+pbb)*256) + c2*16+pd)*16;
    #pragma unroll
    for (int r4=0;r4<4;r4++){
        float4 o; float* po=(float*)&o;
        #pragma unroll
        for (int q=0;q<4;q++){
            int r=r4*4+q;
            float acc=0.f;
            #pragma unroll
            for (int l=0;l<16;l++) acc += tv[l]*Ks[l*16+r];
            po[q]=acc;
        }
        *(float4*)&Tout[obase + r4*4] = o;
    }
}

// ------------- fold4: final column -> A / Ct ; grid (256, 2), thread = c -------------
__global__ __launch_bounds__(256) void fold4_kernel(){
    int c = threadIdx.x;
    int a = blockIdx.x >> 4, b = blockIdx.x & 15;
    int pair = blockIdx.y;
    __shared__ float K4s[256];
    K4s[c] = g_K[(pair*5+4)*4096 + c];
    __syncthreads();
    const float* Tin = pair? g_T1 : g_T0;
    const float* tp = &Tin[(((long)(a*16+b)*256)+c)*16];
    float tv[16];
    #pragma unroll
    for (int l4=0;l4<4;l4++){
        float4 v = *(const float4*)&tp[l4*4];
        tv[l4*4+0]=v.x; tv[l4*4+1]=v.y; tv[l4*4+2]=v.z; tv[l4*4+3]=v.w;
    }
    if (pair==0){
        long base = (long)a*65536 + (long)b*2048 + c*4;
        #pragma unroll
        for (int p0=0;p0<2;p0++)
        #pragma unroll
        for (int p1=0;p1<2;p1++){
            float4 o; float* po=(float*)&o;
            #pragma unroll
            for (int d1=0;d1<4;d1++){
                int kb=(p0*2+p1)*4+d1;
                float acc=0.f;
                #pragma unroll
                for (int l=0;l<16;l++) acc += tv[l]*K4s[kb*16+l];
                po[d1]=acc;
            }
            *(float4*)&g_A[base + p0*32768 + p1*1024] = o;
        }
    } else {
        #pragma unroll
        for (int p0=0;p0<2;p0++)
        #pragma unroll
        for (int p1=0;p1<2;p1++){
            float4 o; float* po=(float*)&o;
            #pragma unroll
            for (int d1=0;d1<4;d1++){
                int kb=(p0*2+p1)*4+d1;
                float acc=0.f;
                #pragma unroll
                for (int l=0;l<16;l++) acc += tv[l]*K4s[kb*16+l];
                po[d1]=acc;
            }
            long col = (long)(a*64 + p0*32 + b*2 + p1);
            *(float4*)&g_Cm[col*1024 + c*4] = o;
        }
    }
}

// ------------- cvt: fp32 -> bf16 hi/lo panels; grid (1024, 2) -------------
__global__ __launch_bounds__(256) void cvt_kernel(){
    unsigned idx = blockIdx.x*256u + threadIdx.x;   // float4 id, 0..262143
    const float* src = blockIdx.y ? g_Cm : g_A;
    __nv_bfloat16* dstH = (__nv_bfloat16*)(blockIdx.y ? g_T1 : g_T0);
    __nv_bfloat16* dstL = dstH + NS;
    float4 v = *(const float4*)&src[(long)idx*4];
    __nv_bfloat16 h0=__float2bfloat16(v.x), h1=__float2bfloat16(v.y);
    __nv_bfloat16 h2=__float2bfloat16(v.z), h3=__float2bfloat16(v.w);
    __nv_bfloat16 l0=__float2bfloat16(v.x-__bfloat162float(h0));
    __nv_bfloat16 l1=__float2bfloat16(v.y-__bfloat162float(h1));
    __nv_bfloat16 l2=__float2bfloat16(v.z-__bfloat162float(h2));
    __nv_bfloat16 l3=__float2bfloat16(v.w-__bfloat162float(h3));
    uint2 hp, lp;
    hp.x = ((unsigned)__bfloat16_as_ushort(h1)<<16) | (unsigned)__bfloat16_as_ushort(h0);
    hp.y = ((unsigned)__bfloat16_as_ushort(h3)<<16) | (unsigned)__bfloat16_as_ushort(h2);
    lp.x = ((unsigned)__bfloat16_as_ushort(l1)<<16) | (unsigned)__bfloat16_as_ushort(l0);
    lp.y = ((unsigned)__bfloat16_as_ushort(l3)<<16) | (unsigned)__bfloat16_as_ushort(l2);
    *(uint2*)&dstH[(long)idx*4] = hp;
    *(uint2*)&dstL[(long)idx*4] = lp;
}

// ------------- bf16-split HMMA GEMM: psi = A @ Ct^T ; grid (16, 8) -------------
// CTA tile 128x64, 8 warps as 4(M) x 2(N), warp tile 32x32.
__global__ __launch_bounds__(256) void mma_gemm_kernel(float* __restrict__ psi){
    __shared__ __align__(16) __nv_bfloat16 Ah[128*40];
    __shared__ __align__(16) __nv_bfloat16 Al[128*40];
    __shared__ __align__(16) __nv_bfloat16 Bh[64*40];
    __shared__ __align__(16) __nv_bfloat16 Bl[64*40];
    int tid = threadIdx.x, lane = tid&31, w = tid>>5;
    int mrow = (w&3)*32, ncol = (w>>2)*32;
    int m0 = blockIdx.y*128, n0 = blockIdx.x*64;
    const __nv_bfloat16* gAh = (const __nv_bfloat16*)g_T0;
    const __nv_bfloat16* gAl = gAh + NS;
    const __nv_bfloat16* gBh = (const __nv_bfloat16*)g_T1;
    const __nv_bfloat16* gBl = gBh + NS;

    float acc[2][4][4];
    #pragma unroll
    for (int i=0;i<2;i++)
      #pragma unroll
      for (int j=0;j<4;j++)
        #pragma unroll
        for (int q=0;q<4;q++) acc[i][j][q]=0.f;

    unsigned aH = smem_u32(Ah), aL = smem_u32(Al);
    unsigned bH = smem_u32(Bh), bL = smem_u32(Bl);
    // per-lane ldmatrix row/col pieces
    int rA = (lane&7) + ((lane>>3)&1)*8;           // row within m16 tile
    int cAsel = ((lane>>4)&1)*8;                    // col sel within k16
    int rB = (lane&7) + ((lane>>4)&1)*8;           // row within n16 pair
    int cBsel = ((lane>>3)&1)*8;

    for (int ch=0; ch<32; ch++){
        #pragma unroll
        for (int e=0;e<2;e++){
            int idx = tid + e*256;                 // 0..511 : A uint4 tiles
            int r = idx>>2, kq = (idx&3)*8;
            long g = (long)(m0+r)*1024 + ch*32 + kq;
            *(uint4*)&Ah[r*40+kq] = *(const uint4*)&gAh[g];
            *(uint4*)&Al[r*40+kq] = *(const uint4*)&gAl[g];
        }
        {
            int r = tid>>2, kq = (tid&3)*8;
            long g = (long)(n0+r)*1024 + ch*32 + kq;
            *(uint4*)&Bh[r*40+kq] = *(const uint4*)&gBh[g];
            *(uint4*)&Bl[r*40+kq] = *(const uint4*)&gBl[g];
        }
        __syncthreads();
        #pragma unroll
        for (int ks=0; ks<2; ks++){
            int colA = ks*16 + cAsel;
            int colB = ks*16 + cBsel;
            unsigned ah[2][4], al[2][4];
            #pragma unroll
            for (int mt=0;mt<2;mt++){
                unsigned offs = (unsigned)(((mrow + mt*16 + rA)*40 + colA)*2);
                LDSM4(ah[mt], aH + offs);
                LDSM4(al[mt], aL + offs);
            }
            unsigned bh[2][4], bl[2][4];
            #pragma unroll
            for (int p=0;p<2;p++){
                unsigned offs = (unsigned)(((ncol + p*16 + rB)*40 + colB)*2);
                LDSM4(bh[p], bH + offs);
                LDSM4(bl[p], bL + offs);
            }
            #pragma unroll
            for (int mt=0;mt<2;mt++)
                #pragma unroll
                for (int nt=0;nt<4;nt++){
                    int p = nt>>1, q = (nt&1)*2;
                    MMA_BF16(acc[mt][nt], ah[mt], bh[p][q], bh[p][q+1]);
                    MMA_BF16(acc[mt][nt], ah[mt], bl[p][q], bl[p][q+1]);
                    MMA_BF16(acc[mt][nt], al[mt], bh[p][q], bh[p][q+1]);
                }
        }
        __syncthreads();
    }
    // epilogue: D m16n8 fragment -> psi
    #pragma unroll
    for (int mt=0;mt<2;mt++){
        #pragma unroll
        for (int nt=0;nt<4;nt++){
            int gr = m0 + mrow + mt*16 + (lane>>2);
            int gc = n0 + ncol + nt*8 + (lane&3)*2;
            *(float2*)&psi[(long)gr*1024 + gc] = make_float2(acc[mt][nt][0], acc[mt][nt][1]);
            *(float2*)&psi[(long)(gr+8)*1024 + gc] = make_float2(acc[mt][nt][2], acc[mt][nt][3]);
        }
    }
}

// ------------- fused horizontal low: bits [5-9] and [0-4], in-place, LDS.128 -------------
__global__ __launch_bounds__(256) void hlow_kernel(float* __restrict__ psi){
    __shared__ __align__(16) float T[32*36];
    __shared__ __align__(16) float Usm[32*36];
    __shared__ __align__(16) float Rs[1024];
    __shared__ float RsT[1024];
    int tid=threadIdx.x;
    for (int e=tid;e<1024;e+=256){
        float v = g_R[e];
        Rs[e]=v;
        RsT[(e&31)*32 + (e>>5)] = v;
    }
    unsigned base = blockIdx.x*1024u;
    #pragma unroll
    for (int it=0;it<4;it++){
        int e = tid + it*256;
        T[(e>>5)*36 + (e&31)] = psi[base+e];
    }
    __syncthreads();
    int rp = tid & 31, cq = tid >> 5;
    float4 u = make_float4(0.f,0.f,0.f,0.f);
    for (int r=0;r<32;r++){
        float rv = RsT[r*32+rp];
        float4 tr = *(const float4*)&T[r*36 + cq*4];
        u.x += rv*tr.x; u.y += rv*tr.y; u.z += rv*tr.z; u.w += rv*tr.w;
    }
    *(float4*)&Usm[rp*36 + cq*4] = u;
    __syncthreads();
    float w[4];
    #pragma unroll
    for (int i=0;i<4;i++){
        int cp = cq*4+i;
        float acc0=0.f, acc1=0.f, acc2v=0.f, acc3=0.f;
        #pragma unroll
        for (int c8=0;c8<8;c8++){
            float4 rr = *(const float4*)&Rs[cp*32 + c8*4];
            float4 uu = *(const float4*)&Usm[rp*36 + c8*4];
            acc0 += rr.x*uu.x; acc1 += rr.y*uu.y;
            acc2v+= rr.z*uu.z; acc3 += rr.w*uu.w;
        }
        w[i]=(acc0+acc1)+(acc2v+acc3);
    }
    __syncthreads();
    *(float4*)&T[rp*36 + cq*4] = make_float4(w[0],w[1],w[2],w[3]);
    __syncthreads();
    #pragma unroll
    for (int it=0;it<4;it++){
        int e = tid + it*256;
        psi[base+e] = T[(e>>5)*36 + (e&31)];
    }
}

// ------------- fused horizontal high: bits [15-19] and [10-14], packed f32x2 -------------
__global__ __launch_bounds__(256) void hhigh_kernel(float* __restrict__ psi){
    __shared__ __align__(16) float S[8][1036];
    __shared__ __align__(16) float Rs[1024];
    __shared__ float RsT[1024];
    int tid = threadIdx.x;
    for (int e=tid;e<1024;e+=256){
        float v = g_R[e];
        Rs[e]=v;
        RsT[(e&31)*32 + (e>>5)] = v;
    }
    unsigned lowbase = blockIdx.x * 8u;
    for (int it=0; it<32; it++){
        int idx = tid + it*256;
        int lo = idx & 7, k = idx >> 3;
        S[lo][k] = psi[(unsigned)k*1024u + lowbase + (unsigned)lo];
    }
    __syncthreads();
    int low = tid & 7, rp = tid >> 3;
    unsigned long long U2[16];
    #pragma unroll
    for (int e=0;e<16;e++) U2[e]=0ull;
    for (int r=0;r<32;r++){
        float rv = RsT[r*32+rp];
        unsigned long long rvp = pk2(rv, rv);
        const ulonglong2* row2 = (const ulonglong2*)&S[low][r*32];
        #pragma unroll
        for (int c2=0;c2<8;c2++){
            ulonglong2 tp = row2[c2];
            U2[c2*2+0] = fma2(rvp, tp.x, U2[c2*2+0]);
            U2[c2*2+1] = fma2(rvp, tp.y, U2[c2*2+1]);
        }
    }
    float W[32];
    #pragma unroll
    for (int cp=0;cp<32;cp++){
        const ulonglong2* Rp2 = (const ulonglong2*)&Rs[cp*32];
        unsigned long long s2 = 0ull;
        #pragma unroll
        for (int c2=0;c2<8;c2++){
            ulonglong2 rr = Rp2[c2];
            s2 = fma2(rr.x, U2[c2*2+0], s2);
            s2 = fma2(rr.y, U2[c2*2+1], s2);
        }
        float2 f = upk2(s2);
        W[cp] = f.x + f.y;
    }
    __syncthreads();
    #pragma unroll
    for (int cp=0;cp<32;cp++) S[low][rp*32+cp] = W[cp];
    __syncthreads();
    for (int it=0; it<32; it++){
        int idx = tid + it*256;
        int lo = idx & 7, k = idx >> 3;
        psi[(unsigned)k*1024u + lowbase + (unsigned)lo] = S[lo][k];
    }
}

// ------------- v3: columns p=2,3,4, slab widened by bit 0; grid 128 -------------
__global__ __launch_bounds__(256) void v3_kernel(float* __restrict__ psi){
    __shared__ float Cs[256];
    __shared__ float S[2*4352];
    int t=threadIdx.x;
    Cs[t]=g_C16[t];
    unsigned f = blockIdx.x;
    unsigned tt=f;
    tt <<= 1;
    tt = ((tt>>2)<<5)   | (tt & 3u);
    tt = ((tt>>7)<<10)  | (tt & 127u);
    tt = ((tt>>12)<<15) | (tt & 4095u);
    tt = ((tt>>17)<<20) | (tt & 131071u);
    unsigned base=tt;
    #pragma unroll
    for (int it=0; it<32; it++){
        unsigned e = (unsigned)t | ((unsigned)it<<8);
        unsigned off = (e&1u) | (((e>>1)&7u)<<2) | (((e>>4)&7u)<<7)
                     | (((e>>7)&7u)<<12) | (((e>>10)&7u)<<17);
        int s0 = e&1;
        int a = ((e>>1)&1)|(((e>>4)&1)<<1)|(((e>>7)&1)<<2)|(((e>>10)&1)<<3);
        int b = ((e>>2)&1)|(((e>>5)&1)<<1)|(((e>>8)&1)<<2)|(((e>>11)&1)<<3);
        int c = ((e>>3)&1)|(((e>>6)&1)<<1)|(((e>>9)&1)<<2)|(((e>>12)&1)<<3);
        S[s0*4352 + (b*16+c)*17 + a] = psi[base + off];
    }
    __syncthreads();
    #pragma unroll
    for (int s0=0;s0<2;s0++){
        float* Sp = S + s0*4352;
        float v[16], o[16];
        #pragma unroll
        for (int a=0;a<16;a++) v[a]=Sp[t*17+a];
        #pragma unroll
        for (int ap=0;ap<16;ap++){
            float acc=0.f;
            #pragma unroll
            for (int a=0;a<16;a++) acc += Cs[ap*16+a]*v[a];
            o[ap]=acc;
        }
        #pragma unroll
        for (int a=0;a<16;a++) Sp[t*17+a]=o[a];
    }
    __syncthreads();
    #pragma unroll
    for (int s0=0;s0<2;s0++){
        float* Sp = S + s0*4352;
        int a=t>>4, c=t&15;
        float v[16], o[16];
        #pragma unroll
        for (int b=0;b<16;b++) v[b]=Sp[(b*16+c)*17 + a];
        #pragma unroll
        for (int bp=0;bp<16;bp++){
            float acc=0.f;
            #pragma unroll
            for (int b=0;b<16;b++) acc += Cs[bp*16+b]*v[b];
            o[bp]=acc;
        }
        #pragma unroll
        for (int b=0;b<16;b++) Sp[(b*16+c)*17 + a]=o[b];
    }
    __syncthreads();
    #pragma unroll
    for (int s0=0;s0<2;s0++){
        float* Sp = S + s0*4352;
        int a=t&15, b=t>>4;
        float v[16], o[16];
        #pragma unroll
        for (int c=0;c<16;c++) v[c]=Sp[(b*16+c)*17 + a];
        #pragma unroll
        for (int cp=0;cp<16;cp++){
            float acc=0.f;
            #pragma unroll
            for (int c=0;c<16;c++) acc += Cs[cp*16+c]*v[c];
            o[cp]=acc;
        }
        #pragma unroll
        for (int c=0;c<16;c++) Sp[(b*16+c)*17 + a]=o[c];
    }
    __syncthreads();
    #pragma unroll
    for (int it=0; it<32; it++){
        unsigned e = (unsigned)t | ((unsigned)it<<8);
        unsigned off = (e&1u) | (((e>>1)&7u)<<2) | (((e>>4)&7u)<<7)
                     | (((e>>7)&7u)<<12) | (((e>>10)&7u)<<17);
        int s0 = e&1;
        int a = ((e>>1)&1)|(((e>>4)&1)<<1)|(((e>>7)&1)<<2)|(((e>>10)&1)<<3);
        int b = ((e>>2)&1)|(((e>>5)&1)<<1)|(((e>>8)&1)<<2)|(((e>>11)&1)<<3);
        int c = ((e>>3)&1)|(((e>>6)&1)<<1)|(((e>>9)&1)<<2)|(((e>>12)&1)<<3);
        psi[base + off] = S[s0*4352 + (b*16+c)*17 + a];
    }
}

// ------------- v2: columns p=0,1, warp slab widened by bits 2,3; grid 128 -------------
__global__ __launch_bounds__(256) void v2_kernel(float* __restrict__ psi){
    __shared__ float Cs[256];
    __shared__ float Tsm[8][4][16][17];
    int tid=threadIdx.x;
    Cs[tid]=g_C16[tid];
    int w = tid>>5, l = tid&31;
    unsigned f = blockIdx.x*8u + (unsigned)w;
    unsigned tt = f<<4;
    tt = ((tt>>5)<<7)   | (tt & 31u);
    tt = ((tt>>10)<<12) | (tt & 1023u);
    tt = ((tt>>15)<<17) | (tt & 32767u);
    unsigned base=tt;
    __syncthreads();
    #pragma unroll
    for (int it=0; it<32; it++){
        unsigned e = (unsigned)l | ((unsigned)it<<5);
        unsigned off = (e&15u) | (((e>>4)&3u)<<5) | (((e>>6)&3u)<<10) | (((e>>8)&3u)<<15);
        int i0 = (e&1)|(((e>>4)&1)<<1)|(((e>>6)&1)<<2)|(((e>>8)&1)<<3);
        int i1 = ((e>>1)&1)|(((e>>5)&1)<<1)|(((e>>7)&1)<<2)|(((e>>9)&1)<<3);
        int q  = (e>>2)&3;
        Tsm[w][q][i1][i0] = psi[base+off];
    }
    __syncwarp();
    {
        int c = l&15, oh = l>>4;
        float u[4][8];
        #pragma unroll
        for (int q=0;q<4;q++){
            #pragma unroll
            for (int oo=0;oo<8;oo++){
                int o = oh*8+oo;
                float acc=0.f;
                #pragma unroll
                for (int k=0;k<16;k++) acc += Cs[o*16+k]*Tsm[w][q][k][c];
                u[q][oo]=acc;
            }
        }
        __syncwarp();
        #pragma unroll
        for (int q=0;q<4;q++)
            #pragma unroll
            for (int oo=0;oo<8;oo++) Tsm[w][q][oh*8+oo][c]=u[q][oo];
    }
    __syncwarp();
    {
        int r = l&15, half = l>>4;
        float u[4][8];
        #pragma unroll
        for (int q=0;q<4;q++){
            #pragma unroll
            for (int ii=0;ii<8;ii++){
                int i0p = half*8+ii;
                float acc=0.f;
                #pragma unroll
                for (int c=0;c<16;c++) acc += Cs[i0p*16+c]*Tsm[w][q][r][c];
                u[q][ii]=acc;
            }
        }
        __syncwarp();
        #pragma unroll
        for (int q=0;q<4;q++)
            #pragma unroll
            for (int ii=0;ii<8;ii++) Tsm[w][q][r][half*8+ii]=u[q][ii];
    }
    __syncwarp();
    #pragma unroll
    for (int it=0; it<32; it++){
        unsigned e = (unsigned)l | ((unsigned)it<<5);
        unsigned off = (e&15u) | (((e>>4)&3u)<<5) | (((e>>6)&3u)<<10) | (((e>>8)&3u)<<15);
        int i0 = (e&1)|(((e>>4)&1)<<1)|(((e>>6)&1)<<2)|(((e>>8)&1)<<3);
        int i1 = ((e>>1)&1)|(((e>>5)&1)<<1)|(((e>>7)&1)<<2)|(((e>>9)&1)<<3);
        int q  = (e>>2)&3;
        psi[base+off] = Tsm[w][q][i1][i0];
    }
}

// ------------- gather 64 amplitudes -------------
__global__ void gather_kernel(const int* __restrict__ x, const float* __restrict__ psi,
                              float* __restrict__ out){
    int b = threadIdx.x;
    unsigned idx=0;
    #pragma unroll
    for (int j=0;j<20;j++) idx = (idx<<1) | (unsigned)x[b*20+j];
    out[b]=psi[idx];
}

extern "C" void kernel_launch(void* const* d_in, const int* in_sizes, int n_in,
                              void* d_out, int out_size){
    const int*   x    = (const int*)d_in[0];
    const float* peps = (const float*)d_in[1];
    const float* gate = (const float*)d_in[2];
    float* out = (float*)d_out;

    float *psi;
    cudaGetSymbolAddress((void**)&psi,  g_psi);

    prep_kernel<<<11,256>>>(peps, gate);
    fold23_kernel<<<dim3(256,2),256>>>();
    fold4_kernel<<<dim3(256,2),256>>>();

    cvt_kernel<<<dim3(1024,2),256>>>();
    mma_gemm_kernel<<<dim3(16,8),256>>>(psi);

    for (int sweep=0; sweep<5; sweep++){
        hhigh_kernel<<<128,256>>>(psi);   // bits [15-19] and [10-14]
        hlow_kernel<<<1024,256>>>(psi);   // bits [5-9] and [0-4]
        v3_kernel<<<128,256>>>(psi);      // columns p=2,3,4 (+bit0 slab)
        v2_kernel<<<128,256>>>(psi);      // columns p=0,1 (+bits 2,3 slab)
    }

    gather_kernel<<<1,64>>>(x, psi, out);
}

// round 14
// speedup vs baseline: 2.3983x; 1.0177x over previous
#include <cuda_runtime.h>
#include <cuda_bf16.h>
#include <cstdint>

#define NS (1<<20)

// ---- device scratch (static, allocation-free) ----
__device__ float g_T0[NS];     // fold23 out pair0
__device__ float g_T1[NS];     // fold23 out pair1
__device__ float g_A[NS];      // bf16 A panels: hi[NS] | lo[NS]
__device__ float g_Cm[NS];     // bf16 B(Ct) panels: hi[NS] | lo[NS]
__device__ float g_psi[NS];    // statevector (in-place for sweeps)
__device__ float g_R[1024];    // 32x32 row-chain operator [out][in]
__device__ float g_C16[256];   // 16x16 column-chain operator
__device__ float g_K[10*4096]; // per-column pair tensors K_j

// ---- packed fp32x2 helpers ----
__device__ __forceinline__ unsigned long long pk2(float x, float y){
    unsigned long long r; asm("mov.b64 %0,{%1,%2};" : "=l"(r) : "f"(x), "f"(y)); return r;
}
__device__ __forceinline__ float2 upk2(unsigned long long v){
    float2 r; asm("mov.b64 {%0,%1},%2;" : "=f"(r.x), "=f"(r.y) : "l"(v)); return r;
}
__device__ __forceinline__ unsigned long long fma2(unsigned long long a,
        unsigned long long b, unsigned long long c){
    unsigned long long d;
    asm("fma.rn.f32x2 %0,%1,%2,%3;" : "=l"(d) : "l"(a), "l"(b), "l"(c));
    return d;
}

__device__ __forceinline__ float peps_el(const float* __restrict__ peps,
                                         int i,int j,int p,int u,int d,int l,int r){
    return peps[(((((i*5+j)*2+p)*4+u)*4+d)*4+l)*4+r];
}

__device__ __forceinline__ unsigned smem_u32(const void* p){
    unsigned a;
    asm("{ .reg .u64 t; cvta.to.shared.u64 t, %1; cvt.u32.u64 %0, t; }" : "=r"(a) : "l"(p));
    return a;
}

// convert float4 -> packed bf16 hi/lo (uint2 each)
__device__ __forceinline__ void cvt4(float4 v, uint2& hp, uint2& lp){
    __nv_bfloat16 h0=__float2bfloat16(v.x), h1=__float2bfloat16(v.y);
    __nv_bfloat16 h2=__float2bfloat16(v.z), h3=__float2bfloat16(v.w);
    __nv_bfloat16 l0=__float2bfloat16(v.x-__bfloat162float(h0));
    __nv_bfloat16 l1=__float2bfloat16(v.y-__bfloat162float(h1));
    __nv_bfloat16 l2=__float2bfloat16(v.z-__bfloat162float(h2));
    __nv_bfloat16 l3=__float2bfloat16(v.w-__bfloat162float(h3));
    hp.x = ((unsigned)__bfloat16_as_ushort(h1)<<16) | (unsigned)__bfloat16_as_ushort(h0);
    hp.y = ((unsigned)__bfloat16_as_ushort(h3)<<16) | (unsigned)__bfloat16_as_ushort(h2);
    lp.x = ((unsigned)__bfloat16_as_ushort(l1)<<16) | (unsigned)__bfloat16_as_ushort(l0);
    lp.y = ((unsigned)__bfloat16_as_ushort(l3)<<16) | (unsigned)__bfloat16_as_ushort(l2);
}

#define LDSM4(R, addr) asm volatile( \
    "ldmatrix.sync.aligned.m8n8.x4.shared.b16 {%0,%1,%2,%3}, [%4];" \
    : "=r"((R)[0]),"=r"((R)[1]),"=r"((R)[2]),"=r"((R)[3]) : "r"(addr))

#define MMA_BF16(acc, a, b0, b1) asm volatile( \
    "mma.sync.aligned.m16n8k16.row.col.f32.bf16.bf16.f32 " \
    "{%0,%1,%2,%3},{%4,%5,%6,%7},{%8,%9},{%0,%1,%2,%3};" \
    : "+f"((acc)[0]),"+f"((acc)[1]),"+f"((acc)[2]),"+f"((acc)[3]) \
    : "r"((a)[0]),"r"((a)[1]),"r"((a)[2]),"r"((a)[3]), "r"(b0),"r"(b1))

// ------------- prep: blocks 0..9 compute K_j; block 10 builds R and C16 -------------
__global__ void prep_kernel(const float* __restrict__ peps, const float* __restrict__ gate){
    int t = threadIdx.x;  // 256
    if (blockIdx.x < 10){
        int blk = blockIdx.x;
        int pair = blk/5, j = blk%5;
        int L = (j==0)?1:4, R = (j==4)?1:4;
        int nk = 16*L*L*R*R;
        float* Kg = g_K + blk*4096;
        for (int e=t; e<nk; e+=256){
            int tt=e;
            int rb=tt%R; tt/=R; int ra=tt%R; tt/=R;
            int lb=tt%L; tt/=L; int la=tt%L; tt/=L;
            int mid=tt&3; tt>>=2;
            int pb=tt&1; int pa=tt>>1;
            float s=0.f;
            if (pair==0){
                #pragma unroll
                for(int m=0;m<4;m++)
                    s += peps_el(peps,0,j,pa,0,m,la,ra)*peps_el(peps,1,j,pb,m,mid,lb,rb);
            } else {
                #pragma unroll
                for(int m=0;m<4;m++)
                    s += peps_el(peps,2,j,pa,mid,m,la,ra)*peps_el(peps,3,j,pb,m,0,lb,rb);
            }
            Kg[e]=s;
        }
        return;
    }
    __shared__ float g[16];
    __shared__ float A0[1024];
    __shared__ float A1[1024];
    if (t<16) g[t]=gate[t];
    for (int e=t;e<1024;e+=256) A0[e] = ((e>>5)==(e&31)) ? 1.0f : 0.0f;
    __syncthreads();
    #pragma unroll
    for (int k=0;k<4;k++){
        const float* cur = (k&1)? A1 : A0;
        float* nxt       = (k&1)? A0 : A1;
        int hb=4-k, lb=3-k;
        for (int e=t;e<1024;e+=256){
            int rp=e>>5, c=e&31;
            int i1p=(rp>>hb)&1, i2p=(rp>>lb)&1;
            int base = rp & ~((1<<hb)|(1<<lb));
            float acc=0.f;
            #pragma unroll
            for(int i1=0;i1<2;i1++)
            #pragma unroll
            for(int i2=0;i2<2;i2++)
                acc += g[(i1p*2+i2p)*4+(i1*2+i2)] * cur[(base|(i1<<hb)|(i2<<lb))*32 + c];
            nxt[e]=acc;
        }
        __syncthreads();
    }
    for (int e=t;e<1024;e+=256) g_R[e]=A0[e];
    __syncthreads();
    A0[t] = ((t>>4)==(t&15)) ? 1.0f : 0.0f;
    __syncthreads();
    #pragma unroll
    for (int k=0;k<3;k++){
        const float* cur=(k&1)?A1:A0;
        float* nxt      =(k&1)?A0:A1;
        int hb=3-k, lb=2-k;
        int rp=t>>4, c=t&15;
        int i1p=(rp>>hb)&1,i2p=(rp>>lb)&1;
        int base = rp & ~((1<<hb)|(1<<lb));
        float acc=0.f;
        #pragma unroll
        for(int i1=0;i1<2;i1++)
        #pragma unroll
        for(int i2=0;i2<2;i2++)
            acc += g[(i1p*2+i2p)*4+(i1*2+i2)]*cur[(base|(i1<<hb)|(i2<<lb))*16+c];
        __syncthreads();
        nxt[t]=acc;
        __syncthreads();
    }
    g_C16[t]=A1[t];
}

// ------------- fold23 (absorbs kkprep): grid (256, 2) -------------
__global__ __launch_bounds__(256) void fold23_kernel(){
    int t = threadIdx.x;
    int pb = blockIdx.x, pair = blockIdx.y;
    int pd = pb&15, pbb = (pb>>4)&3, pa = pb>>6;
    const float* Kbase = g_K + pair*5*4096;
    __shared__ float K0s[256];
    __shared__ float K1s[4096];
    __shared__ float K2s[256], K3s[256];
    __shared__ float Ts[256*20];
    __shared__ float Ks[256];
    K0s[t] = Kbase[t];
    for (int e=t;e<4096;e+=256) K1s[e]=Kbase[4096+e];
    int kb2 = ((pa>>1)*2+(pbb>>1))*4+(pd>>2);
    int kb3 = ((pa&1)*2+(pbb&1))*4+(pd&3);
    K2s[t] = Kbase[2*4096 + kb2*256 + t];
    K3s[t] = Kbase[3*4096 + kb3*256 + t];
    __syncthreads();
    {
        int abc=t;
        int a2=abc>>6, b2=(abc>>4)&3, c2=abc&15;
        int kb0 = ((a2>>1)*2+(b2>>1))*4 + (c2>>2);
        int kb1 = ((a2&1)*2+(b2&1))*4 + (c2&3);
        #pragma unroll
        for (int r=0;r<16;r++){
            float acc=0.f;
            #pragma unroll
            for (int m=0;m<16;m++) acc += K0s[kb0*16+m]*K1s[(kb1*16+m)*16+r];
            Ts[t*20+r]=acc;
        }
    }
    {
        int l=t>>4, r=t&15;
        float acc=0.f;
        #pragma unroll
        for (int m=0;m<16;m++) acc += K2s[l*16+m]*K3s[m*16+r];
        Ks[t]=acc;
    }
    __syncthreads();
    float* Tout = pair? g_T1 : g_T0;
    int a2=t>>6, b2=(t>>4)&3, c2=t&15;
    float tv[16];
    #pragma unroll
    for (int l=0;l<16;l++) tv[l]=Ts[t*20+l];
    long obase = ((((long)(a2*4+pa)*16 + b2*4+pbb)*256) + c2*16+pd)*16;
    #pragma unroll
    for (int r4=0;r4<4;r4++){
        float4 o; float* po=(float*)&o;
        #pragma unroll
        for (int q=0;q<4;q++){
            int r=r4*4+q;
            float acc=0.f;
            #pragma unroll
            for (int l=0;l<16;l++) acc += tv[l]*Ks[l*16+r];
            po[q]=acc;
        }
        *(float4*)&Tout[obase + r4*4] = o;
    }
}

// ------------- fold4: final column -> bf16 hi/lo panels ; grid (256, 2) -------------
__global__ __launch_bounds__(256) void fold4_kernel(){
    int c = threadIdx.x;
    int a = blockIdx.x >> 4, b = blockIdx.x & 15;
    int pair = blockIdx.y;
    __shared__ float K4s[256];
    K4s[c] = g_K[(pair*5+4)*4096 + c];
    __syncthreads();
    const float* Tin = pair? g_T1 : g_T0;
    const float* tp = &Tin[(((long)(a*16+b)*256)+c)*16];
    float tv[16];
    #pragma unroll
    for (int l4=0;l4<4;l4++){
        float4 v = *(const float4*)&tp[l4*4];
        tv[l4*4+0]=v.x; tv[l4*4+1]=v.y; tv[l4*4+2]=v.z; tv[l4*4+3]=v.w;
    }
    __nv_bfloat16* dH = (__nv_bfloat16*)(pair? g_Cm : g_A);
    __nv_bfloat16* dL = dH + NS;
    #pragma unroll
    for (int p0=0;p0<2;p0++)
    #pragma unroll
    for (int p1=0;p1<2;p1++){
        float4 o; float* po=(float*)&o;
        #pragma unroll
        for (int d1=0;d1<4;d1++){
            int kb=(p0*2+p1)*4+d1;
            float acc=0.f;
            #pragma unroll
            for (int l=0;l<16;l++) acc += tv[l]*K4s[kb*16+l];
            po[d1]=acc;
        }
        uint2 hp, lp;
        cvt4(o, hp, lp);
        long ei;
        if (pair==0)
            ei = (long)a*65536 + (long)b*2048 + c*4 + p0*32768 + p1*1024;
        else
            ei = (long)(a*64 + p0*32 + b*2 + p1)*1024 + c*4;
        *(uint2*)&dH[ei] = hp;
        *(uint2*)&dL[ei] = lp;
    }
}

// ------------- bf16-split HMMA GEMM: psi = A @ Ct^T ; grid (16, 8) -------------
__global__ __launch_bounds__(256) void mma_gemm_kernel(float* __restrict__ psi){
    __shared__ __align__(16) __nv_bfloat16 Ah[128*40];
    __shared__ __align__(16) __nv_bfloat16 Al[128*40];
    __shared__ __align__(16) __nv_bfloat16 Bh[64*40];
    __shared__ __align__(16) __nv_bfloat16 Bl[64*40];
    int tid = threadIdx.x, lane = tid&31, w = tid>>5;
    int mrow = (w&3)*32, ncol = (w>>2)*32;
    int m0 = blockIdx.y*128, n0 = blockIdx.x*64;
    const __nv_bfloat16* gAh = (const __nv_bfloat16*)g_A;
    const __nv_bfloat16* gAl = gAh + NS;
    const __nv_bfloat16* gBh = (const __nv_bfloat16*)g_Cm;
    const __nv_bfloat16* gBl = gBh + NS;

    float acc[2][4][4];
    #pragma unroll
    for (int i=0;i<2;i++)
      #pragma unroll
      for (int j=0;j<4;j++)
        #pragma unroll
        for (int q=0;q<4;q++) acc[i][j][q]=0.f;

    unsigned aH = smem_u32(Ah), aL = smem_u32(Al);
    unsigned bH = smem_u32(Bh), bL = smem_u32(Bl);
    int rA = (lane&7) + ((lane>>3)&1)*8;
    int cAsel = ((lane>>4)&1)*8;
    int rB = (lane&7) + ((lane>>4)&1)*8;
    int cBsel = ((lane>>3)&1)*8;

    for (int ch=0; ch<32; ch++){
        #pragma unroll
        for (int e=0;e<2;e++){
            int idx = tid + e*256;
            int r = idx>>2, kq = (idx&3)*8;
            long g = (long)(m0+r)*1024 + ch*32 + kq;
            *(uint4*)&Ah[r*40+kq] = *(const uint4*)&gAh[g];
            *(uint4*)&Al[r*40+kq] = *(const uint4*)&gAl[g];
        }
        {
            int r = tid>>2, kq = (tid&3)*8;
            long g = (long)(n0+r)*1024 + ch*32 + kq;
            *(uint4*)&Bh[r*40+kq] = *(const uint4*)&gBh[g];
            *(uint4*)&Bl[r*40+kq] = *(const uint4*)&gBl[g];
        }
        __syncthreads();
        #pragma unroll
        for (int ks=0; ks<2; ks++){
            int colA = ks*16 + cAsel;
            int colB = ks*16 + cBsel;
            unsigned ah[2][4], al[2][4];
            #pragma unroll
            for (int mt=0;mt<2;mt++){
                unsigned offs = (unsigned)(((mrow + mt*16 + rA)*40 + colA)*2);
                LDSM4(ah[mt], aH + offs);
                LDSM4(al[mt], aL + offs);
            }
            unsigned bh[2][4], bl[2][4];
            #pragma unroll
            for (int p=0;p<2;p++){
                unsigned offs = (unsigned)(((ncol + p*16 + rB)*40 + colB)*2);
                LDSM4(bh[p], bH + offs);
                LDSM4(bl[p], bL + offs);
            }
            #pragma unroll
            for (int mt=0;mt<2;mt++)
                #pragma unroll
                for (int nt=0;nt<4;nt++){
                    int p = nt>>1, q = (nt&1)*2;
                    MMA_BF16(acc[mt][nt], ah[mt], bh[p][q], bh[p][q+1]);
                    MMA_BF16(acc[mt][nt], ah[mt], bl[p][q], bl[p][q+1]);
                    MMA_BF16(acc[mt][nt], al[mt], bh[p][q], bh[p][q+1]);
                }
        }
        __syncthreads();
    }
    #pragma unroll
    for (int mt=0;mt<2;mt++){
        #pragma unroll
        for (int nt=0;nt<4;nt++){
            int gr = m0 + mrow + mt*16 + (lane>>2);
            int gc = n0 + ncol + nt*8 + (lane&3)*2;
            *(float2*)&psi[(long)gr*1024 + gc] = make_float2(acc[mt][nt][0], acc[mt][nt][1]);
            *(float2*)&psi[(long)(gr+8)*1024 + gc] = make_float2(acc[mt][nt][2], acc[mt][nt][3]);
        }
    }
}

// ------------- fused horizontal low: bits [5-9] and [0-4], in-place, LDS.128 -------------
__global__ __launch_bounds__(256) void hlow_kernel(float* __restrict__ psi){
    __shared__ __align__(16) float T[32*36];
    __shared__ __align__(16) float Usm[32*36];
    __shared__ __align__(16) float Rs[1024];
    __shared__ float RsT[1024];
    int tid=threadIdx.x;
    for (int e=tid;e<1024;e+=256){
        float v = g_R[e];
        Rs[e]=v;
        RsT[(e&31)*32 + (e>>5)] = v;
    }
    unsigned base = blockIdx.x*1024u;
    #pragma unroll
    for (int it=0;it<4;it++){
        int e = tid + it*256;
        T[(e>>5)*36 + (e&31)] = psi[base+e];
    }
    __syncthreads();
    int rp = tid & 31, cq = tid >> 5;
    float4 u = make_float4(0.f,0.f,0.f,0.f);
    for (int r=0;r<32;r++){
        float rv = RsT[r*32+rp];
        float4 tr = *(const float4*)&T[r*36 + cq*4];
        u.x += rv*tr.x; u.y += rv*tr.y; u.z += rv*tr.z; u.w += rv*tr.w;
    }
    *(float4*)&Usm[rp*36 + cq*4] = u;
    __syncthreads();
    float w[4];
    #pragma unroll
    for (int i=0;i<4;i++){
        int cp = cq*4+i;
        float acc0=0.f, acc1=0.f, acc2v=0.f, acc3=0.f;
        #pragma unroll
        for (int c8=0;c8<8;c8++){
            float4 rr = *(const float4*)&Rs[cp*32 + c8*4];
            float4 uu = *(const float4*)&Usm[rp*36 + c8*4];
            acc0 += rr.x*uu.x; acc1 += rr.y*uu.y;
            acc2v+= rr.z*uu.z; acc3 += rr.w*uu.w;
        }
        w[i]=(acc0+acc1)+(acc2v+acc3);
    }
    __syncthreads();
    *(float4*)&T[rp*36 + cq*4] = make_float4(w[0],w[1],w[2],w[3]);
    __syncthreads();
    #pragma unroll
    for (int it=0;it<4;it++){
        int e = tid + it*256;
        psi[base+e] = T[(e>>5)*36 + (e&31)];
    }
}

// ------------- fused horizontal high: bits [15-19] and [10-14], packed f32x2 -------------
__global__ __launch_bounds__(256) void hhigh_kernel(float* __restrict__ psi){
    __shared__ __align__(16) float S[8][1036];
    __shared__ __align__(16) float Rs[1024];
    __shared__ float RsT[1024];
    int tid = threadIdx.x;
    for (int e=tid;e<1024;e+=256){
        float v = g_R[e];
        Rs[e]=v;
        RsT[(e&31)*32 + (e>>5)] = v;
    }
    unsigned lowbase = blockIdx.x * 8u;
    for (int it=0; it<32; it++){
        int idx = tid + it*256;
        int lo = idx & 7, k = idx >> 3;
        S[lo][k] = psi[(unsigned)k*1024u + lowbase + (unsigned)lo];
    }
    __syncthreads();
    int low = tid & 7, rp = tid >> 3;
    unsigned long long U2[16];
    #pragma unroll
    for (int e=0;e<16;e++) U2[e]=0ull;
    for (int r=0;r<32;r++){
        float rv = RsT[r*32+rp];
        unsigned long long rvp = pk2(rv, rv);
        const ulonglong2* row2 = (const ulonglong2*)&S[low][r*32];
        #pragma unroll
        for (int c2=0;c2<8;c2++){
            ulonglong2 tp = row2[c2];
            U2[c2*2+0] = fma2(rvp, tp.x, U2[c2*2+0]);
            U2[c2*2+1] = fma2(rvp, tp.y, U2[c2*2+1]);
        }
    }
    float W[32];
    #pragma unroll
    for (int cp=0;cp<32;cp++){
        const ulonglong2* Rp2 = (const ulonglong2*)&Rs[cp*32];
        unsigned long long s2 = 0ull;
        #pragma unroll
        for (int c2=0;c2<8;c2++){
            ulonglong2 rr = Rp2[c2];
            s2 = fma2(rr.x, U2[c2*2+0], s2);
            s2 = fma2(rr.y, U2[c2*2+1], s2);
        }
        float2 f = upk2(s2);
        W[cp] = f.x + f.y;
    }
    __syncthreads();
    #pragma unroll
    for (int cp=0;cp<32;cp++) S[low][rp*32+cp] = W[cp];
    __syncthreads();
    for (int it=0; it<32; it++){
        int idx = tid + it*256;
        int lo = idx & 7, k = idx >> 3;
        psi[(unsigned)k*1024u + lowbase + (unsigned)lo] = S[lo][k];
    }
}

// ------------- v3: columns p=2,3,4, slab widened by bit 0; grid 128, 512 thr -------------
__global__ __launch_bounds__(512) void v3_kernel(float* __restrict__ psi){
    __shared__ float Cs[256];
    __shared__ float S[2*4352];
    int tid=threadIdx.x;
    if (tid<256) Cs[tid]=g_C16[tid];
    unsigned f = blockIdx.x;
    unsigned tt=f;
    tt <<= 1;
    tt = ((tt>>2)<<5)   | (tt & 3u);
    tt = ((tt>>7)<<10)  | (tt & 127u);
    tt = ((tt>>12)<<15) | (tt & 4095u);
    tt = ((tt>>17)<<20) | (tt & 131071u);
    unsigned base=tt;
    #pragma unroll
    for (int it=0; it<16; it++){
        unsigned e = (unsigned)tid | ((unsigned)it<<9);
        unsigned off = (e&1u) | (((e>>1)&7u)<<2) | (((e>>4)&7u)<<7)
                     | (((e>>7)&7u)<<12) | (((e>>10)&7u)<<17);
        int s0 = e&1;
        int a = ((e>>1)&1)|(((e>>4)&1)<<1)|(((e>>7)&1)<<2)|(((e>>10)&1)<<3);
        int b = ((e>>2)&1)|(((e>>5)&1)<<1)|(((e>>8)&1)<<2)|(((e>>11)&1)<<3);
        int c = ((e>>3)&1)|(((e>>6)&1)<<1)|(((e>>9)&1)<<2)|(((e>>12)&1)<<3);
        S[s0*4352 + (b*16+c)*17 + a] = psi[base + off];
    }
    __syncthreads();
    int s0 = tid>>8, t2 = tid&255;
    float* Sp = S + s0*4352;
    // stage A: transform a; thread owns row (b*16+c)=t2 of its sub-slab
    {
        float v[16], o[16];
        #pragma unroll
        for (int a=0;a<16;a++) v[a]=Sp[t2*17+a];
        #pragma unroll
        for (int ap=0;ap<16;ap++){
            float acc=0.f;
            #pragma unroll
            for (int a=0;a<16;a++) acc += Cs[ap*16+a]*v[a];
            o[ap]=acc;
        }
        #pragma unroll
        for (int a=0;a<16;a++) Sp[t2*17+a]=o[a];
    }
    __syncthreads();
    // stage B: transform b
    {
        int a=t2>>4, c=t2&15;
        float v[16], o[16];
        #pragma unroll
        for (int b=0;b<16;b++) v[b]=Sp[(b*16+c)*17 + a];
        #pragma unroll
        for (int bp=0;bp<16;bp++){
            float acc=0.f;
            #pragma unroll
            for (int b=0;b<16;b++) acc += Cs[bp*16+b]*v[b];
            o[bp]=acc;
        }
        #pragma unroll
        for (int b=0;b<16;b++) Sp[(b*16+c)*17 + a]=o[b];
    }
    __syncthreads();
    // stage C: transform c
    {
        int a=t2&15, b=t2>>4;
        float v[16], o[16];
        #pragma unroll
        for (int c=0;c<16;c++) v[c]=Sp[(b*16+c)*17 + a];
        #pragma unroll
        for (int cp=0;cp<16;cp++){
            float acc=0.f;
            #pragma unroll
            for (int c=0;c<16;c++) acc += Cs[cp*16+c]*v[c];
            o[cp]=acc;
        }
        #pragma unroll
        for (int c=0;c<16;c++) Sp[(b*16+c)*17 + a]=o[c];
    }
    __syncthreads();
    #pragma unroll
    for (int it=0; it<16; it++){
        unsigned e = (unsigned)tid | ((unsigned)it<<9);
        unsigned off = (e&1u) | (((e>>1)&7u)<<2) | (((e>>4)&7u)<<7)
                     | (((e>>7)&7u)<<12) | (((e>>10)&7u)<<17);
        int es0 = e&1;
        int a = ((e>>1)&1)|(((e>>4)&1)<<1)|(((e>>7)&1)<<2)|(((e>>10)&1)<<3);
        int b = ((e>>2)&1)|(((e>>5)&1)<<1)|(((e>>8)&1)<<2)|(((e>>11)&1)<<3);
        int c = ((e>>3)&1)|(((e>>6)&1)<<1)|(((e>>9)&1)<<2)|(((e>>12)&1)<<3);
        psi[base + off] = S[es0*4352 + (b*16+c)*17 + a];
    }
}

// ------------- v2: columns p=0,1, warp slab widened by bits 2,3; grid 128 -------------
__global__ __launch_bounds__(256) void v2_kernel(float* __restrict__ psi){
    __shared__ float Cs[256];
    __shared__ float Tsm[8][4][16][17];
    int tid=threadIdx.x;
    Cs[tid]=g_C16[tid];
    int w = tid>>5, l = tid&31;
    unsigned f = blockIdx.x*8u + (unsigned)w;
    unsigned tt = f<<4;
    tt = ((tt>>5)<<7)   | (tt & 31u);
    tt = ((tt>>10)<<12) | (tt & 1023u);
    tt = ((tt>>15)<<17) | (tt & 32767u);
    unsigned base=tt;
    __syncthreads();
    #pragma unroll
    for (int it=0; it<32; it++){
        unsigned e = (unsigned)l | ((unsigned)it<<5);
        unsigned off = (e&15u) | (((e>>4)&3u)<<5) | (((e>>6)&3u)<<10) | (((e>>8)&3u)<<15);
        int i0 = (e&1)|(((e>>4)&1)<<1)|(((e>>6)&1)<<2)|(((e>>8)&1)<<3);
        int i1 = ((e>>1)&1)|(((e>>5)&1)<<1)|(((e>>7)&1)<<2)|(((e>>9)&1)<<3);
        int q  = (e>>2)&3;
        Tsm[w][q][i1][i0] = psi[base+off];
    }
    __syncwarp();
    {
        int c = l&15, oh = l>>4;
        float u[4][8];
        #pragma unroll
        for (int q=0;q<4;q++){
            #pragma unroll
            for (int oo=0;oo<8;oo++){
                int o = oh*8+oo;
                float acc=0.f;
                #pragma unroll
                for (int k=0;k<16;k++) acc += Cs[o*16+k]*Tsm[w][q][k][c];
                u[q][oo]=acc;
            }
        }
        __syncwarp();
        #pragma unroll
        for (int q=0;q<4;q++)
            #pragma unroll
            for (int oo=0;oo<8;oo++) Tsm[w][q][oh*8+oo][c]=u[q][oo];
    }
    __syncwarp();
    {
        int r = l&15, half = l>>4;
        float u[4][8];
        #pragma unroll
        for (int q=0;q<4;q++){
            #pragma unroll
            for (int ii=0;ii<8;ii++){
                int i0p = half*8+ii;
                float acc=0.f;
                #pragma unroll
                for (int c=0;c<16;c++) acc += Cs[i0p*16+c]*Tsm[w][q][r][c];
                u[q][ii]=acc;
            }
        }
        __syncwarp();
        #pragma unroll
        for (int q=0;q<4;q++)
            #pragma unroll
            for (int ii=0;ii<8;ii++) Tsm[w][q][r][half*8+ii]=u[q][ii];
    }
    __syncwarp();
    #pragma unroll
    for (int it=0; it<32; it++){
        unsigned e = (unsigned)l | ((unsigned)it<<5);
        unsigned off = (e&15u) | (((e>>4)&3u)<<5) | (((e>>6)&3u)<<10) | (((e>>8)&3u)<<15);
        int i0 = (e&1)|(((e>>4)&1)<<1)|(((e>>6)&1)<<2)|(((e>>8)&1)<<3);
        int i1 = ((e>>1)&1)|(((e>>5)&1)<<1)|(((e>>7)&1)<<2)|(((e>>9)&1)<<3);
        int q  = (e>>2)&3;
        psi[base+off] = Tsm[w][q][i1][i0];
    }
}

// ------------- gather 64 amplitudes -------------
__global__ void gather_kernel(const int* __restrict__ x, const float* __restrict__ psi,
                              float* __restrict__ out){
    int b = threadIdx.x;
    unsigned idx=0;
    #pragma unroll
    for (int j=0;j<20;j++) idx = (idx<<1) | (unsigned)x[b*20+j];
    out[b]=psi[idx];
}

extern "C" void kernel_launch(void* const* d_in, const int* in_sizes, int n_in,
                              void* d_out, int out_size){
    const int*   x    = (const int*)d_in[0];
    const float* peps = (const float*)d_in[1];
    const float* gate = (const float*)d_in[2];
    float* out = (float*)d_out;

    float *psi;
    cudaGetSymbolAddress((void**)&psi,  g_psi);

    prep_kernel<<<11,256>>>(peps, gate);
    fold23_kernel<<<dim3(256,2),256>>>();
    fold4_kernel<<<dim3(256,2),256>>>();

    mma_gemm_kernel<<<dim3(16,8),256>>>(psi);

    for (int sweep=0; sweep<5; sweep++){
        hhigh_kernel<<<128,256>>>(psi);   // bits [15-19] and [10-14]
        hlow_kernel<<<1024,256>>>(psi);   // bits [5-9] and [0-4]
        v3_kernel<<<128,512>>>(psi);      // columns p=2,3,4 (+bit0 slab)
        v2_kernel<<<128,256>>>(psi);      // columns p=0,1 (+bits 2,3 slab)
    }

    gather_kernel<<<1,64>>>(x, psi, out);
}

// round 15
// speedup vs baseline: 2.5219x; 1.0515x over previous
#include <cuda_runtime.h>
#include <cuda_bf16.h>
#include <cstdint>

#define NS (1<<20)

// ---- device scratch (static, allocation-free) ----
__device__ float g_T0[NS];     // fold23 out pair0
__device__ float g_T1[NS];     // fold23 out pair1
__device__ float g_A[NS];      // bf16 A panels: hi[NS] | lo[NS]
__device__ float g_Cm[NS];     // bf16 B(Ct) panels: hi[NS] | lo[NS]
__device__ float g_psi[NS];    // statevector (in-place for sweeps)
__device__ float g_R[1024];    // 32x32 row-chain operator [out][in]
__device__ float g_C16[256];   // 16x16 column-chain operator
__device__ float g_K[10*4096]; // per-column pair tensors K_j

// ---- packed fp32x2 helpers ----
__device__ __forceinline__ unsigned long long pk2(float x, float y){
    unsigned long long r; asm("mov.b64 %0,{%1,%2};" : "=l"(r) : "f"(x), "f"(y)); return r;
}
__device__ __forceinline__ float2 upk2(unsigned long long v){
    float2 r; asm("mov.b64 {%0,%1},%2;" : "=f"(r.x), "=f"(r.y) : "l"(v)); return r;
}
__device__ __forceinline__ unsigned long long fma2(unsigned long long a,
        unsigned long long b, unsigned long long c){
    unsigned long long d;
    asm("fma.rn.f32x2 %0,%1,%2,%3;" : "=l"(d) : "l"(a), "l"(b), "l"(c));
    return d;
}

__device__ __forceinline__ float peps_el(const float* __restrict__ peps,
                                         int i,int j,int p,int u,int d,int l,int r){
    return peps[(((((i*5+j)*2+p)*4+u)*4+d)*4+l)*4+r];
}

__device__ __forceinline__ unsigned smem_u32(const void* p){
    unsigned a;
    asm("{ .reg .u64 t; cvta.to.shared.u64 t, %1; cvt.u32.u64 %0, t; }" : "=r"(a) : "l"(p));
    return a;
}

__device__ __forceinline__ void cvt4(float4 v, uint2& hp, uint2& lp){
    __nv_bfloat16 h0=__float2bfloat16(v.x), h1=__float2bfloat16(v.y);
    __nv_bfloat16 h2=__float2bfloat16(v.z), h3=__float2bfloat16(v.w);
    __nv_bfloat16 l0=__float2bfloat16(v.x-__bfloat162float(h0));
    __nv_bfloat16 l1=__float2bfloat16(v.y-__bfloat162float(h1));
    __nv_bfloat16 l2=__float2bfloat16(v.z-__bfloat162float(h2));
    __nv_bfloat16 l3=__float2bfloat16(v.w-__bfloat162float(h3));
    hp.x = ((unsigned)__bfloat16_as_ushort(h1)<<16) | (unsigned)__bfloat16_as_ushort(h0);
    hp.y = ((unsigned)__bfloat16_as_ushort(h3)<<16) | (unsigned)__bfloat16_as_ushort(h2);
    lp.x = ((unsigned)__bfloat16_as_ushort(l1)<<16) | (unsigned)__bfloat16_as_ushort(l0);
    lp.y = ((unsigned)__bfloat16_as_ushort(l3)<<16) | (unsigned)__bfloat16_as_ushort(l2);
}

#define LDSM4(R, addr) asm volatile( \
    "ldmatrix.sync.aligned.m8n8.x4.shared.b16 {%0,%1,%2,%3}, [%4];" \
    : "=r"((R)[0]),"=r"((R)[1]),"=r"((R)[2]),"=r"((R)[3]) : "r"(addr))

#define MMA_BF16(acc, a, b0, b1) asm volatile( \
    "mma.sync.aligned.m16n8k16.row.col.f32.bf16.bf16.f32 " \
    "{%0,%1,%2,%3},{%4,%5,%6,%7},{%8,%9},{%0,%1,%2,%3};" \
    : "+f"((acc)[0]),"+f"((acc)[1]),"+f"((acc)[2]),"+f"((acc)[3]) \
    : "r"((a)[0]),"r"((a)[1]),"r"((a)[2]),"r"((a)[3]), "r"(b0),"r"(b1))

#define CP16(dst, src) asm volatile( \
    "cp.async.cg.shared.global [%0], [%1], 16;" :: "r"(dst), "l"(src))
#define CP_COMMIT() asm volatile("cp.async.commit_group;" ::: "memory")
#define CP_WAIT1() asm volatile("cp.async.wait_group 1;" ::: "memory")
#define CP_WAIT0() asm volatile("cp.async.wait_group 0;" ::: "memory")

// ------------- prep: blocks 0..9 compute K_j; block 10 builds R and C16 -------------
__global__ void prep_kernel(const float* __restrict__ peps, const float* __restrict__ gate){
    int t = threadIdx.x;  // 256
    if (blockIdx.x < 10){
        int blk = blockIdx.x;
        int pair = blk/5, j = blk%5;
        int L = (j==0)?1:4, R = (j==4)?1:4;
        int nk = 16*L*L*R*R;
        float* Kg = g_K + blk*4096;
        for (int e=t; e<nk; e+=256){
            int tt=e;
            int rb=tt%R; tt/=R; int ra=tt%R; tt/=R;
            int lb=tt%L; tt/=L; int la=tt%L; tt/=L;
            int mid=tt&3; tt>>=2;
            int pb=tt&1; int pa=tt>>1;
            float s=0.f;
            if (pair==0){
                #pragma unroll
                for(int m=0;m<4;m++)
                    s += peps_el(peps,0,j,pa,0,m,la,ra)*peps_el(peps,1,j,pb,m,mid,lb,rb);
            } else {
                #pragma unroll
                for(int m=0;m<4;m++)
                    s += peps_el(peps,2,j,pa,mid,m,la,ra)*peps_el(peps,3,j,pb,m,0,lb,rb);
            }
            Kg[e]=s;
        }
        return;
    }
    __shared__ float g[16];
    __shared__ float A0[1024];
    __shared__ float A1[1024];
    if (t<16) g[t]=gate[t];
    for (int e=t;e<1024;e+=256) A0[e] = ((e>>5)==(e&31)) ? 1.0f : 0.0f;
    __syncthreads();
    #pragma unroll
    for (int k=0;k<4;k++){
        const float* cur = (k&1)? A1 : A0;
        float* nxt       = (k&1)? A0 : A1;
        int hb=4-k, lb=3-k;
        for (int e=t;e<1024;e+=256){
            int rp=e>>5, c=e&31;
            int i1p=(rp>>hb)&1, i2p=(rp>>lb)&1;
            int base = rp & ~((1<<hb)|(1<<lb));
            float acc=0.f;
            #pragma unroll
            for(int i1=0;i1<2;i1++)
            #pragma unroll
            for(int i2=0;i2<2;i2++)
                acc += g[(i1p*2+i2p)*4+(i1*2+i2)] * cur[(base|(i1<<hb)|(i2<<lb))*32 + c];
            nxt[e]=acc;
        }
        __syncthreads();
    }
    for (int e=t;e<1024;e+=256) g_R[e]=A0[e];
    __syncthreads();
    A0[t] = ((t>>4)==(t&15)) ? 1.0f : 0.0f;
    __syncthreads();
    #pragma unroll
    for (int k=0;k<3;k++){
        const float* cur=(k&1)?A1:A0;
        float* nxt      =(k&1)?A0:A1;
        int hb=3-k, lb=2-k;
        int rp=t>>4, c=t&15;
        int i1p=(rp>>hb)&1,i2p=(rp>>lb)&1;
        int base = rp & ~((1<<hb)|(1<<lb));
        float acc=0.f;
        #pragma unroll
        for(int i1=0;i1<2;i1++)
        #pragma unroll
        for(int i2=0;i2<2;i2++)
            acc += g[(i1p*2+i2p)*4+(i1*2+i2)]*cur[(base|(i1<<hb)|(i2<<lb))*16+c];
        __syncthreads();
        nxt[t]=acc;
        __syncthreads();
    }
    g_C16[t]=A1[t];
}

// ------------- fold23 (absorbs kkprep): grid (256, 2) -------------
__global__ __launch_bounds__(256) void fold23_kernel(){
    int t = threadIdx.x;
    int pb = blockIdx.x, pair = blockIdx.y;
    int pd = pb&15, pbb = (pb>>4)&3, pa = pb>>6;
    const float* Kbase = g_K + pair*5*4096;
    __shared__ float K0s[256];
    __shared__ float K1s[4096];
    __shared__ float K2s[256], K3s[256];
    __shared__ float Ts[256*20];
    __shared__ float Ks[256];
    K0s[t] = Kbase[t];
    for (int e=t;e<4096;e+=256) K1s[e]=Kbase[4096+e];
    int kb2 = ((pa>>1)*2+(pbb>>1))*4+(pd>>2);
    int kb3 = ((pa&1)*2+(pbb&1))*4+(pd&3);
    K2s[t] = Kbase[2*4096 + kb2*256 + t];
    K3s[t] = Kbase[3*4096 + kb3*256 + t];
    __syncthreads();
    {
        int abc=t;
        int a2=abc>>6, b2=(abc>>4)&3, c2=abc&15;
        int kb0 = ((a2>>1)*2+(b2>>1))*4 + (c2>>2);
        int kb1 = ((a2&1)*2+(b2&1))*4 + (c2&3);
        #pragma unroll
        for (int r=0;r<16;r++){
            float acc=0.f;
            #pragma unroll
            for (int m=0;m<16;m++) acc += K0s[kb0*16+m]*K1s[(kb1*16+m)*16+r];
            Ts[t*20+r]=acc;
        }
    }
    {
        int l=t>>4, r=t&15;
        float acc=0.f;
        #pragma unroll
        for (int m=0;m<16;m++) acc += K2s[l*16+m]*K3s[m*16+r];
        Ks[t]=acc;
    }
    __syncthreads();
    float* Tout = pair? g_T1 : g_T0;
    int a2=t>>6, b2=(t>>4)&3, c2=t&15;
    float tv[16];
    #pragma unroll
    for (int l=0;l<16;l++) tv[l]=Ts[t*20+l];
    long obase = ((((long)(a2*4+pa)*16 + b2*4+pbb)*256) + c2*16+pd)*16;
    #pragma unroll
    for (int r4=0;r4<4;r4++){
        float4 o; float* po=(float*)&o;
        #pragma unroll
        for (int q=0;q<4;q++){
            int r=r4*4+q;
            float acc=0.f;
            #pragma unroll
            for (int l=0;l<16;l++) acc += tv[l]*Ks[l*16+r];
            po[q]=acc;
        }
        *(float4*)&Tout[obase + r4*4] = o;
    }
}

// ------------- fold4: final column -> bf16 hi/lo panels ; grid (256, 2) -------------
__global__ __launch_bounds__(256) void fold4_kernel(){
    int c = threadIdx.x;
    int a = blockIdx.x >> 4, b = blockIdx.x & 15;
    int pair = blockIdx.y;
    __shared__ float K4s[256];
    K4s[c] = g_K[(pair*5+4)*4096 + c];
    __syncthreads();
    const float* Tin = pair? g_T1 : g_T0;
    const float* tp = &Tin[(((long)(a*16+b)*256)+c)*16];
    float tv[16];
    #pragma unroll
    for (int l4=0;l4<4;l4++){
        float4 v = *(const float4*)&tp[l4*4];
        tv[l4*4+0]=v.x; tv[l4*4+1]=v.y; tv[l4*4+2]=v.z; tv[l4*4+3]=v.w;
    }
    __nv_bfloat16* dH = (__nv_bfloat16*)(pair? g_Cm : g_A);
    __nv_bfloat16* dL = dH + NS;
    #pragma unroll
    for (int p0=0;p0<2;p0++)
    #pragma unroll
    for (int p1=0;p1<2;p1++){
        float4 o; float* po=(float*)&o;
        #pragma unroll
        for (int d1=0;d1<4;d1++){
            int kb=(p0*2+p1)*4+d1;
            float acc=0.f;
            #pragma unroll
            for (int l=0;l<16;l++) acc += tv[l]*K4s[kb*16+l];
            po[d1]=acc;
        }
        uint2 hp, lp;
        cvt4(o, hp, lp);
        long ei;
        if (pair==0)
            ei = (long)a*65536 + (long)b*2048 + c*4 + p0*32768 + p1*1024;
        else
            ei = (long)(a*64 + p0*32 + b*2 + p1)*1024 + c*4;
        *(uint2*)&dH[ei] = hp;
        *(uint2*)&dL[ei] = lp;
    }
}

// ------------- bf16-split HMMA GEMM, cp.async double-buffered; grid (16, 8) -------------
// per-buffer half-offsets: Ah 0, Al 5120, Bh 10240, Bl 12800 ; buffer = 15360 halves
#define GB_AH 0
#define GB_AL 10240      // bytes
#define GB_BH 20480
#define GB_BL 25600
#define GB_BUF 30720     // bytes per buffer
#define SMEM_GEMM (2*GB_BUF)

__global__ __launch_bounds__(256) void mma_gemm_kernel(float* __restrict__ psi){
    extern __shared__ __align__(16) __nv_bfloat16 smg[];
    unsigned sb = smem_u32(smg);
    int tid = threadIdx.x, lane = tid&31, w = tid>>5;
    int mrow = (w&3)*32, ncol = (w>>2)*32;
    int m0 = blockIdx.y*128, n0 = blockIdx.x*64;
    const __nv_bfloat16* gAh = (const __nv_bfloat16*)g_A;
    const __nv_bfloat16* gAl = gAh + NS;
    const __nv_bfloat16* gBh = (const __nv_bfloat16*)g_Cm;
    const __nv_bfloat16* gBl = gBh + NS;

    float acc[2][4][4];
    #pragma unroll
    for (int i=0;i<2;i++)
      #pragma unroll
      for (int j=0;j<4;j++)
        #pragma unroll
        for (int q=0;q<4;q++) acc[i][j][q]=0.f;

    // per-thread load coords
    int rA0 = (tid)>>2,        kqA0 = (tid&3)*8;          // A idx = tid
    int rA1 = (tid+256)>>2,    kqA1 = (tid&3)*8;          // A idx = tid+256
    int rBt = tid>>2,          kqBt = (tid&3)*8;          // B idx = tid

    int rA = (lane&7) + ((lane>>3)&1)*8;
    int cAsel = ((lane>>4)&1)*8;
    int rB = (lane&7) + ((lane>>4)&1)*8;
    int cBsel = ((lane>>3)&1)*8;

    // ---- prologue: stage chunk 0 into buffer 0 ----
    {
        unsigned b0 = sb;
        CP16(b0 + GB_AH + (unsigned)(rA0*40+kqA0)*2, gAh + (long)(m0+rA0)*1024 + kqA0);
        CP16(b0 + GB_AH + (unsigned)(rA1*40+kqA1)*2, gAh + (long)(m0+rA1)*1024 + kqA1);
        CP16(b0 + GB_AL + (unsigned)(rA0*40+kqA0)*2, gAl + (long)(m0+rA0)*1024 + kqA0);
        CP16(b0 + GB_AL + (unsigned)(rA1*40+kqA1)*2, gAl + (long)(m0+rA1)*1024 + kqA1);
        CP16(b0 + GB_BH + (unsigned)(rBt*40+kqBt)*2, gBh + (long)(n0+rBt)*1024 + kqBt);
        CP16(b0 + GB_BL + (unsigned)(rBt*40+kqBt)*2, gBl + (long)(n0+rBt)*1024 + kqBt);
        CP_COMMIT();
    }

    for (int ch=0; ch<32; ch++){
        if (ch<31){
            unsigned bn = sb + (unsigned)((ch+1)&1)*GB_BUF;
            int ko = (ch+1)*32;
            CP16(bn + GB_AH + (unsigned)(rA0*40+kqA0)*2, gAh + (long)(m0+rA0)*1024 + ko + kqA0);
            CP16(bn + GB_AH + (unsigned)(rA1*40+kqA1)*2, gAh + (long)(m0+rA1)*1024 + ko + kqA1);
            CP16(bn + GB_AL + (unsigned)(rA0*40+kqA0)*2, gAl + (long)(m0+rA0)*1024 + ko + kqA0);
            CP16(bn + GB_AL + (unsigned)(rA1*40+kqA1)*2, gAl + (long)(m0+rA1)*1024 + ko + kqA1);
            CP16(bn + GB_BH + (unsigned)(rBt*40+kqBt)*2, gBh + (long)(n0+rBt)*1024 + ko + kqBt);
            CP16(bn + GB_BL + (unsigned)(rBt*40+kqBt)*2, gBl + (long)(n0+rBt)*1024 + ko + kqBt);
            CP_COMMIT();
            CP_WAIT1();
        } else {
            CP_WAIT0();
        }
        __syncthreads();
        unsigned bc = sb + (unsigned)(ch&1)*GB_BUF;
        unsigned aH = bc + GB_AH, aL = bc + GB_AL;
        unsigned bH = bc + GB_BH, bL = bc + GB_BL;
        #pragma unroll
        for (int ks=0; ks<2; ks++){
            int colA = ks*16 + cAsel;
            int colB = ks*16 + cBsel;
            unsigned ah[2][4], al[2][4];
            #pragma unroll
            for (int mt=0;mt<2;mt++){
                unsigned offs = (unsigned)(((mrow + mt*16 + rA)*40 + colA)*2);
                LDSM4(ah[mt], aH + offs);
                LDSM4(al[mt], aL + offs);
            }
            unsigned bh[2][4], bl[2][4];
            #pragma unroll
            for (int p=0;p<2;p++){
                unsigned offs = (unsigned)(((ncol + p*16 + rB)*40 + colB)*2);
                LDSM4(bh[p], bH + offs);
                LDSM4(bl[p], bL + offs);
            }
            #pragma unroll
            for (int mt=0;mt<2;mt++)
                #pragma unroll
                for (int nt=0;nt<4;nt++){
                    int p = nt>>1, q = (nt&1)*2;
                    MMA_BF16(acc[mt][nt], ah[mt], bh[p][q], bh[p][q+1]);
                    MMA_BF16(acc[mt][nt], ah[mt], bl[p][q], bl[p][q+1]);
                    MMA_BF16(acc[mt][nt], al[mt], bh[p][q], bh[p][q+1]);
                }
        }
        __syncthreads();
    }
    #pragma unroll
    for (int mt=0;mt<2;mt++){
        #pragma unroll
        for (int nt=0;nt<4;nt++){
            int gr = m0 + mrow + mt*16 + (lane>>2);
            int gc = n0 + ncol + nt*8 + (lane&3)*2;
            *(float2*)&psi[(long)gr*1024 + gc] = make_float2(acc[mt][nt][0], acc[mt][nt][1]);
            *(float2*)&psi[(long)(gr+8)*1024 + gc] = make_float2(acc[mt][nt][2], acc[mt][nt][3]);
        }
    }
}

// ------------- fused horizontal low: bits [5-9] and [0-4], in-place, LDS.128 -------------
__global__ __launch_bounds__(256) void hlow_kernel(float* __restrict__ psi){
    __shared__ __align__(16) float T[32*36];
    __shared__ __align__(16) float Usm[32*36];
    __shared__ __align__(16) float Rs[1024];
    __shared__ float RsT[1024];
    int tid=threadIdx.x;
    for (int e=tid;e<1024;e+=256){
        float v = g_R[e];
        Rs[e]=v;
        RsT[(e&31)*32 + (e>>5)] = v;
    }
    unsigned base = blockIdx.x*1024u;
    #pragma unroll
    for (int it=0;it<4;it++){
        int e = tid + it*256;
        T[(e>>5)*36 + (e&31)] = psi[base+e];
    }
    __syncthreads();
    int rp = tid & 31, cq = tid >> 5;
    float4 u = make_float4(0.f,0.f,0.f,0.f);
    for (int r=0;r<32;r++){
        float rv = RsT[r*32+rp];
        float4 tr = *(const float4*)&T[r*36 + cq*4];
        u.x += rv*tr.x; u.y += rv*tr.y; u.z += rv*tr.z; u.w += rv*tr.w;
    }
    *(float4*)&Usm[rp*36 + cq*4] = u;
    __syncthreads();
    float w[4];
    #pragma unroll
    for (int i=0;i<4;i++){
        int cp = cq*4+i;
        float acc0=0.f, acc1=0.f, acc2v=0.f, acc3=0.f;
        #pragma unroll
        for (int c8=0;c8<8;c8++){
            float4 rr = *(const float4*)&Rs[cp*32 + c8*4];
            float4 uu = *(const float4*)&Usm[rp*36 + c8*4];
            acc0 += rr.x*uu.x; acc1 += rr.y*uu.y;
            acc2v+= rr.z*uu.z; acc3 += rr.w*uu.w;
        }
        w[i]=(acc0+acc1)+(acc2v+acc3);
    }
    __syncthreads();
    *(float4*)&T[rp*36 + cq*4] = make_float4(w[0],w[1],w[2],w[3]);
    __syncthreads();
    #pragma unroll
    for (int it=0;it<4;it++){
        int e = tid + it*256;
        psi[base+e] = T[(e>>5)*36 + (e&31)];
    }
}

// ------------- fused horizontal high: bits [15-19] and [10-14], packed f32x2 -------------
__global__ __launch_bounds__(256) void hhigh_kernel(float* __restrict__ psi){
    __shared__ __align__(16) float S[8][1036];
    __shared__ __align__(16) float Rs[1024];
    __shared__ float RsT[1024];
    int tid = threadIdx.x;
    for (int e=tid;e<1024;e+=256){
        float v = g_R[e];
        Rs[e]=v;
        RsT[(e&31)*32 + (e>>5)] = v;
    }
    unsigned lowbase = blockIdx.x * 8u;
    for (int it=0; it<32; it++){
        int idx = tid + it*256;
        int lo = idx & 7, k = idx >> 3;
        S[lo][k] = psi[(unsigned)k*1024u + lowbase + (unsigned)lo];
    }
    __syncthreads();
    int low = tid & 7, rp = tid >> 3;
    unsigned long long U2[16];
    #pragma unroll
    for (int e=0;e<16;e++) U2[e]=0ull;
    for (int r=0;r<32;r++){
        float rv = RsT[r*32+rp];
        unsigned long long rvp = pk2(rv, rv);
        const ulonglong2* row2 = (const ulonglong2*)&S[low][r*32];
        #pragma unroll
        for (int c2=0;c2<8;c2++){
            ulonglong2 tp = row2[c2];
            U2[c2*2+0] = fma2(rvp, tp.x, U2[c2*2+0]);
            U2[c2*2+1] = fma2(rvp, tp.y, U2[c2*2+1]);
        }
    }
    float W[32];
    #pragma unroll
    for (int cp=0;cp<32;cp++){
        const ulonglong2* Rp2 = (const ulonglong2*)&Rs[cp*32];
        unsigned long long s2 = 0ull;
        #pragma unroll
        for (int c2=0;c2<8;c2++){
            ulonglong2 rr = Rp2[c2];
            s2 = fma2(rr.x, U2[c2*2+0], s2);
            s2 = fma2(rr.y, U2[c2*2+1], s2);
        }
        float2 f = upk2(s2);
        W[cp] = f.x + f.y;
    }
    __syncthreads();
    #pragma unroll
    for (int cp=0;cp<32;cp++) S[low][rp*32+cp] = W[cp];
    __syncthreads();
    for (int it=0; it<32; it++){
        int idx = tid + it*256;
        int lo = idx & 7, k = idx >> 3;
        psi[(unsigned)k*1024u + lowbase + (unsigned)lo] = S[lo][k];
    }
}

// ------------- v3: columns p=2,3,4, slab widened by bit 0; grid 128, 512 thr -------------
__global__ __launch_bounds__(512) void v3_kernel(float* __restrict__ psi){
    __shared__ float Cs[256];
    __shared__ float S[2*4352];
    int tid=threadIdx.x;
    if (tid<256) Cs[tid]=g_C16[tid];
    unsigned f = blockIdx.x;
    unsigned tt=f;
    tt <<= 1;
    tt = ((tt>>2)<<5)   | (tt & 3u);
    tt = ((tt>>7)<<10)  | (tt & 127u);
    tt = ((tt>>12)<<15) | (tt & 4095u);
    tt = ((tt>>17)<<20) | (tt & 131071u);
    unsigned base=tt;
    #pragma unroll
    for (int it=0; it<16; it++){
        unsigned e = (unsigned)tid | ((unsigned)it<<9);
        unsigned off = (e&1u) | (((e>>1)&7u)<<2) | (((e>>4)&7u)<<7)
                     | (((e>>7)&7u)<<12) | (((e>>10)&7u)<<17);
        int s0 = e&1;
        int a = ((e>>1)&1)|(((e>>4)&1)<<1)|(((e>>7)&1)<<2)|(((e>>10)&1)<<3);
        int b = ((e>>2)&1)|(((e>>5)&1)<<1)|(((e>>8)&1)<<2)|(((e>>11)&1)<<3);
        int c = ((e>>3)&1)|(((e>>6)&1)<<1)|(((e>>9)&1)<<2)|(((e>>12)&1)<<3);
        S[s0*4352 + (b*16+c)*17 + a] = psi[base + off];
    }
    __syncthreads();
    int s0 = tid>>8, t2 = tid&255;
    float* Sp = S + s0*4352;
    {
        float v[16], o[16];
        #pragma unroll
        for (int a=0;a<16;a++) v[a]=Sp[t2*17+a];
        #pragma unroll
        for (int ap=0;ap<16;ap++){
            float acc=0.f;
            #pragma unroll
            for (int a=0;a<16;a++) acc += Cs[ap*16+a]*v[a];
            o[ap]=acc;
        }
        #pragma unroll
        for (int a=0;a<16;a++) Sp[t2*17+a]=o[a];
    }
    __syncthreads();
    {
        int a=t2>>4, c=t2&15;
        float v[16], o[16];
        #pragma unroll
        for (int b=0;b<16;b++) v[b]=Sp[(b*16+c)*17 + a];
        #pragma unroll
        for (int bp=0;bp<16;bp++){
            float acc=0.f;
            #pragma unroll
            for (int b=0;b<16;b++) acc += Cs[bp*16+b]*v[b];
            o[bp]=acc;
        }
        #pragma unroll
        for (int b=0;b<16;b++) Sp[(b*16+c)*17 + a]=o[b];
    }
    __syncthreads();
    {
        int a=t2&15, b=t2>>4;
        float v[16], o[16];
        #pragma unroll
        for (int c=0;c<16;c++) v[c]=Sp[(b*16+c)*17 + a];
        #pragma unroll
        for (int cp=0;cp<16;cp++){
            float acc=0.f;
            #pragma unroll
            for (int c=0;c<16;c++) acc += Cs[cp*16+c]*v[c];
            o[cp]=acc;
        }
        #pragma unroll
        for (int c=0;c<16;c++) Sp[(b*16+c)*17 + a]=o[c];
    }
    __syncthreads();
    #pragma unroll
    for (int it=0; it<16; it++){
        unsigned e = (unsigned)tid | ((unsigned)it<<9);
        unsigned off = (e&1u) | (((e>>1)&7u)<<2) | (((e>>4)&7u)<<7)
                     | (((e>>7)&7u)<<12) | (((e>>10)&7u)<<17);
        int es0 = e&1;
        int a = ((e>>1)&1)|(((e>>4)&1)<<1)|(((e>>7)&1)<<2)|(((e>>10)&1)<<3);
        int b = ((e>>2)&1)|(((e>>5)&1)<<1)|(((e>>8)&1)<<2)|(((e>>11)&1)<<3);
        int c = ((e>>3)&1)|(((e>>6)&1)<<1)|(((e>>9)&1)<<2)|(((e>>12)&1)<<3);
        psi[base + off] = S[es0*4352 + (b*16+c)*17 + a];
    }
}

// ------------- v2: columns p=0,1, warp slab widened by bits 2,3; grid 128 -------------
__global__ __launch_bounds__(256) void v2_kernel(float* __restrict__ psi){
    __shared__ float Cs[256];
    __shared__ float Tsm[8][4][16][17];
    int tid=threadIdx.x;
    Cs[tid]=g_C16[tid];
    int w = tid>>5, l = tid&31;
    unsigned f = blockIdx.x*8u + (unsigned)w;
    unsigned tt = f<<4;
    tt = ((tt>>5)<<7)   | (tt & 31u);
    tt = ((tt>>10)<<12) | (tt & 1023u);
    tt = ((tt>>15)<<17) | (tt & 32767u);
    unsigned base=tt;
    __syncthreads();
    #pragma unroll
    for (int it=0; it<32; it++){
        unsigned e = (unsigned)l | ((unsigned)it<<5);
        unsigned off = (e&15u) | (((e>>4)&3u)<<5) | (((e>>6)&3u)<<10) | (((e>>8)&3u)<<15);
        int i0 = (e&1)|(((e>>4)&1)<<1)|(((e>>6)&1)<<2)|(((e>>8)&1)<<3);
        int i1 = ((e>>1)&1)|(((e>>5)&1)<<1)|(((e>>7)&1)<<2)|(((e>>9)&1)<<3);
        int q  = (e>>2)&3;
        Tsm[w][q][i1][i0] = psi[base+off];
    }
    __syncwarp();
    {
        int c = l&15, oh = l>>4;
        float u[4][8];
        #pragma unroll
        for (int q=0;q<4;q++){
            #pragma unroll
            for (int oo=0;oo<8;oo++){
                int o = oh*8+oo;
                float acc=0.f;
                #pragma unroll
                for (int k=0;k<16;k++) acc += Cs[o*16+k]*Tsm[w][q][k][c];
                u[q][oo]=acc;
            }
        }
        __syncwarp();
        #pragma unroll
        for (int q=0;q<4;q++)
            #pragma unroll
            for (int oo=0;oo<8;oo++) Tsm[w][q][oh*8+oo][c]=u[q][oo];
    }
    __syncwarp();
    {
        int r = l&15, half = l>>4;
        float u[4][8];
        #pragma unroll
        for (int q=0;q<4;q++){
            #pragma unroll
            for (int ii=0;ii<8;ii++){
                int i0p = half*8+ii;
                float acc=0.f;
                #pragma unroll
                for (int c=0;c<16;c++) acc += Cs[i0p*16+c]*Tsm[w][q][r][c];
                u[q][ii]=acc;
            }
        }
        __syncwarp();
        #pragma unroll
        for (int q=0;q<4;q++)
            #pragma unroll
            for (int ii=0;ii<8;ii++) Tsm[w][q][r][half*8+ii]=u[q][ii];
    }
    __syncwarp();
    #pragma unroll
    for (int it=0; it<32; it++){
        unsigned e = (unsigned)l | ((unsigned)it<<5);
        unsigned off = (e&15u) | (((e>>4)&3u)<<5) | (((e>>6)&3u)<<10) | (((e>>8)&3u)<<15);
        int i0 = (e&1)|(((e>>4)&1)<<1)|(((e>>6)&1)<<2)|(((e>>8)&1)<<3);
        int i1 = ((e>>1)&1)|(((e>>5)&1)<<1)|(((e>>7)&1)<<2)|(((e>>9)&1)<<3);
        int q  = (e>>2)&3;
        psi[base+off] = Tsm[w][q][i1][i0];
    }
}

// ------------- gather 64 amplitudes -------------
__global__ void gather_kernel(const int* __restrict__ x, const float* __restrict__ psi,
                              float* __restrict__ out){
    int b = threadIdx.x;
    unsigned idx=0;
    #pragma unroll
    for (int j=0;j<20;j++) idx = (idx<<1) | (unsigned)x[b*20+j];
    out[b]=psi[idx];
}

extern "C" void kernel_launch(void* const* d_in, const int* in_sizes, int n_in,
                              void* d_out, int out_size){
    const int*   x    = (const int*)d_in[0];
    const float* peps = (const float*)d_in[1];
    const float* gate = (const float*)d_in[2];
    float* out = (float*)d_out;

    float *psi;
    cudaGetSymbolAddress((void**)&psi,  g_psi);

    static int smem_set = 0;
    if (!smem_set){
        cudaFuncSetAttribute(mma_gemm_kernel,
                             cudaFuncAttributeMaxDynamicSharedMemorySize, SMEM_GEMM);
        smem_set = 1;
    }

    prep_kernel<<<11,256>>>(peps, gate);
    fold23_kernel<<<dim3(256,2),256>>>();
    fold4_kernel<<<dim3(256,2),256>>>();

    mma_gemm_kernel<<<dim3(16,8),256,SMEM_GEMM>>>(psi);

    for (int sweep=0; sweep<5; sweep++){
        hhigh_kernel<<<128,256>>>(psi);   // bits [15-19] and [10-14]
        hlow_kernel<<<1024,256>>>(psi);   // bits [5-9] and [0-4]
        v3_kernel<<<128,512>>>(psi);      // columns p=2,3,4 (+bit0 slab)
        v2_kernel<<<128,256>>>(psi);      // columns p=0,1 (+bits 2,3 slab)
    }

    gather_kernel<<<1,64>>>(x, psi, out);
}

// round 16
// speedup vs baseline: 2.7654x; 1.0966x over previous
#include <cuda_runtime.h>
#include <cuda_bf16.h>
#include <cstdint>

#define NS (1<<20)

// ---- device scratch (static, allocation-free) ----
__device__ float g_T0[NS];     // fold23 out pair0
__device__ float g_T1[NS];     // fold23 out pair1
__device__ float g_A[NS];      // bf16 A panels: hi[NS] | lo[NS]
__device__ float g_Cm[NS];     // bf16 B(Ct) panels: hi[NS] | lo[NS]
__device__ float g_psi[NS];    // statevector (in-place for sweeps)
__device__ float g_R[1024];    // 32x32 row-chain operator [out][in]
__device__ float g_C16[256];   // 16x16 column-chain operator
__device__ float g_K[10*4096]; // per-column pair tensors K_j

// ---- packed fp32x2 helpers ----
__device__ __forceinline__ unsigned long long pk2(float x, float y){
    unsigned long long r; asm("mov.b64 %0,{%1,%2};" : "=l"(r) : "f"(x), "f"(y)); return r;
}
__device__ __forceinline__ float2 upk2(unsigned long long v){
    float2 r; asm("mov.b64 {%0,%1},%2;" : "=f"(r.x), "=f"(r.y) : "l"(v)); return r;
}
__device__ __forceinline__ unsigned long long fma2(unsigned long long a,
        unsigned long long b, unsigned long long c){
    unsigned long long d;
    asm("fma.rn.f32x2 %0,%1,%2,%3;" : "=l"(d) : "l"(a), "l"(b), "l"(c));
    return d;
}

__device__ __forceinline__ float peps_el(const float* __restrict__ peps,
                                         int i,int j,int p,int u,int d,int l,int r){
    return peps[(((((i*5+j)*2+p)*4+u)*4+d)*4+l)*4+r];
}

__device__ __forceinline__ unsigned smem_u32(const void* p){
    unsigned a;
    asm("{ .reg .u64 t; cvta.to.shared.u64 t, %1; cvt.u32.u64 %0, t; }" : "=r"(a) : "l"(p));
    return a;
}

__device__ __forceinline__ void cvt4(float4 v, uint2& hp, uint2& lp){
    __nv_bfloat16 h0=__float2bfloat16(v.x), h1=__float2bfloat16(v.y);
    __nv_bfloat16 h2=__float2bfloat16(v.z), h3=__float2bfloat16(v.w);
    __nv_bfloat16 l0=__float2bfloat16(v.x-__bfloat162float(h0));
    __nv_bfloat16 l1=__float2bfloat16(v.y-__bfloat162float(h1));
    __nv_bfloat16 l2=__float2bfloat16(v.z-__bfloat162float(h2));
    __nv_bfloat16 l3=__float2bfloat16(v.w-__bfloat162float(h3));
    hp.x = ((unsigned)__bfloat16_as_ushort(h1)<<16) | (unsigned)__bfloat16_as_ushort(h0);
    hp.y = ((unsigned)__bfloat16_as_ushort(h3)<<16) | (unsigned)__bfloat16_as_ushort(h2);
    lp.x = ((unsigned)__bfloat16_as_ushort(l1)<<16) | (unsigned)__bfloat16_as_ushort(l0);
    lp.y = ((unsigned)__bfloat16_as_ushort(l3)<<16) | (unsigned)__bfloat16_as_ushort(l2);
}

#define LDSM4(R, addr) asm volatile( \
    "ldmatrix.sync.aligned.m8n8.x4.shared.b16 {%0,%1,%2,%3}, [%4];" \
    : "=r"((R)[0]),"=r"((R)[1]),"=r"((R)[2]),"=r"((R)[3]) : "r"(addr))

#define MMA_BF16(acc, a, b0, b1) asm volatile( \
    "mma.sync.aligned.m16n8k16.row.col.f32.bf16.bf16.f32 " \
    "{%0,%1,%2,%3},{%4,%5,%6,%7},{%8,%9},{%0,%1,%2,%3};" \
    : "+f"((acc)[0]),"+f"((acc)[1]),"+f"((acc)[2]),"+f"((acc)[3]) \
    : "r"((a)[0]),"r"((a)[1]),"r"((a)[2]),"r"((a)[3]), "r"(b0),"r"(b1))

#define CP16(dst, src) asm volatile( \
    "cp.async.cg.shared.global [%0], [%1], 16;" :: "r"(dst), "l"(src))
#define CP_COMMIT() asm volatile("cp.async.commit_group;" ::: "memory")
#define CP_WAIT1() asm volatile("cp.async.wait_group 1;" ::: "memory")
#define CP_WAIT0() asm volatile("cp.async.wait_group 0;" ::: "memory")

// ------------- prep: blocks 0..9 compute K_j; block 10 builds R and C16 -------------
__global__ void prep_kernel(const float* __restrict__ peps, const float* __restrict__ gate){
    int t = threadIdx.x;  // 256
    if (blockIdx.x < 10){
        int blk = blockIdx.x;
        int pair = blk/5, j = blk%5;
        int L = (j==0)?1:4, R = (j==4)?1:4;
        int nk = 16*L*L*R*R;
        float* Kg = g_K + blk*4096;
        for (int e=t; e<nk; e+=256){
            int tt=e;
            int rb=tt%R; tt/=R; int ra=tt%R; tt/=R;
            int lb=tt%L; tt/=L; int la=tt%L; tt/=L;
            int mid=tt&3; tt>>=2;
            int pb=tt&1; int pa=tt>>1;
            float s=0.f;
            if (pair==0){
                #pragma unroll
                for(int m=0;m<4;m++)
                    s += peps_el(peps,0,j,pa,0,m,la,ra)*peps_el(peps,1,j,pb,m,mid,lb,rb);
            } else {
                #pragma unroll
                for(int m=0;m<4;m++)
                    s += peps_el(peps,2,j,pa,mid,m,la,ra)*peps_el(peps,3,j,pb,m,0,lb,rb);
            }
            Kg[e]=s;
        }
        return;
    }
    __shared__ float g[16];
    __shared__ float A0[1024];
    __shared__ float A1[1024];
    if (t<16) g[t]=gate[t];
    for (int e=t;e<1024;e+=256) A0[e] = ((e>>5)==(e&31)) ? 1.0f : 0.0f;
    __syncthreads();
    #pragma unroll
    for (int k=0;k<4;k++){
        const float* cur = (k&1)? A1 : A0;
        float* nxt       = (k&1)? A0 : A1;
        int hb=4-k, lb=3-k;
        for (int e=t;e<1024;e+=256){
            int rp=e>>5, c=e&31;
            int i1p=(rp>>hb)&1, i2p=(rp>>lb)&1;
            int base = rp & ~((1<<hb)|(1<<lb));
            float acc=0.f;
            #pragma unroll
            for(int i1=0;i1<2;i1++)
            #pragma unroll
            for(int i2=0;i2<2;i2++)
                acc += g[(i1p*2+i2p)*4+(i1*2+i2)] * cur[(base|(i1<<hb)|(i2<<lb))*32 + c];
            nxt[e]=acc;
        }
        __syncthreads();
    }
    for (int e=t;e<1024;e+=256) g_R[e]=A0[e];
    __syncthreads();
    A0[t] = ((t>>4)==(t&15)) ? 1.0f : 0.0f;
    __syncthreads();
    #pragma unroll
    for (int k=0;k<3;k++){
        const float* cur=(k&1)?A1:A0;
        float* nxt      =(k&1)?A0:A1;
        int hb=3-k, lb=2-k;
        int rp=t>>4, c=t&15;
        int i1p=(rp>>hb)&1,i2p=(rp>>lb)&1;
        int base = rp & ~((1<<hb)|(1<<lb));
        float acc=0.f;
        #pragma unroll
        for(int i1=0;i1<2;i1++)
        #pragma unroll
        for(int i2=0;i2<2;i2++)
            acc += g[(i1p*2+i2p)*4+(i1*2+i2)]*cur[(base|(i1<<hb)|(i2<<lb))*16+c];
        __syncthreads();
        nxt[t]=acc;
        __syncthreads();
    }
    g_C16[t]=A1[t];
}

// ------------- fold23 (absorbs kkprep): grid (256, 2) -------------
__global__ __launch_bounds__(256) void fold23_kernel(){
    int t = threadIdx.x;
    int pb = blockIdx.x, pair = blockIdx.y;
    int pd = pb&15, pbb = (pb>>4)&3, pa = pb>>6;
    const float* Kbase = g_K + pair*5*4096;
    __shared__ float K0s[256];
    __shared__ float K1s[4096];
    __shared__ float K2s[256], K3s[256];
    __shared__ float Ts[256*20];
    __shared__ float Ks[256];
    K0s[t] = Kbase[t];
    for (int e=t;e<4096;e+=256) K1s[e]=Kbase[4096+e];
    int kb2 = ((pa>>1)*2+(pbb>>1))*4+(pd>>2);
    int kb3 = ((pa&1)*2+(pbb&1))*4+(pd&3);
    K2s[t] = Kbase[2*4096 + kb2*256 + t];
    K3s[t] = Kbase[3*4096 + kb3*256 + t];
    __syncthreads();
    {
        int abc=t;
        int a2=abc>>6, b2=(abc>>4)&3, c2=abc&15;
        int kb0 = ((a2>>1)*2+(b2>>1))*4 + (c2>>2);
        int kb1 = ((a2&1)*2+(b2&1))*4 + (c2&3);
        #pragma unroll
        for (int r=0;r<16;r++){
            float acc=0.f;
            #pragma unroll
            for (int m=0;m<16;m++) acc += K0s[kb0*16+m]*K1s[(kb1*16+m)*16+r];
            Ts[t*20+r]=acc;
        }
    }
    {
        int l=t>>4, r=t&15;
        float acc=0.f;
        #pragma unroll
        for (int m=0;m<16;m++) acc += K2s[l*16+m]*K3s[m*16+r];
        Ks[t]=acc;
    }
    __syncthreads();
    float* Tout = pair? g_T1 : g_T0;
    int a2=t>>6, b2=(t>>4)&3, c2=t&15;
    float tv[16];
    #pragma unroll
    for (int l=0;l<16;l++) tv[l]=Ts[t*20+l];
    long obase = ((((long)(a2*4+pa)*16 + b2*4+pbb)*256) + c2*16+pd)*16;
    #pragma unroll
    for (int r4=0;r4<4;r4++){
        float4 o; float* po=(float*)&o;
        #pragma unroll
        for (int q=0;q<4;q++){
            int r=r4*4+q;
            float acc=0.f;
            #pragma unroll
            for (int l=0;l<16;l++) acc += tv[l]*Ks[l*16+r];
            po[q]=acc;
        }
        *(float4*)&Tout[obase + r4*4] = o;
    }
}

// ------------- fold4: final column -> bf16 hi/lo panels ; grid (256, 2) -------------
__global__ __launch_bounds__(256) void fold4_kernel(){
    int c = threadIdx.x;
    int a = blockIdx.x >> 4, b = blockIdx.x & 15;
    int pair = blockIdx.y;
    __shared__ float K4s[256];
    K4s[c] = g_K[(pair*5+4)*4096 + c];
    __syncthreads();
    const float* Tin = pair? g_T1 : g_T0;
    const float* tp = &Tin[(((long)(a*16+b)*256)+c)*16];
    float tv[16];
    #pragma unroll
    for (int l4=0;l4<4;l4++){
        float4 v = *(const float4*)&tp[l4*4];
        tv[l4*4+0]=v.x; tv[l4*4+1]=v.y; tv[l4*4+2]=v.z; tv[l4*4+3]=v.w;
    }
    __nv_bfloat16* dH = (__nv_bfloat16*)(pair? g_Cm : g_A);
    __nv_bfloat16* dL = dH + NS;
    #pragma unroll
    for (int p0=0;p0<2;p0++)
    #pragma unroll
    for (int p1=0;p1<2;p1++){
        float4 o; float* po=(float*)&o;
        #pragma unroll
        for (int d1=0;d1<4;d1++){
            int kb=(p0*2+p1)*4+d1;
            float acc=0.f;
            #pragma unroll
            for (int l=0;l<16;l++) acc += tv[l]*K4s[kb*16+l];
            po[d1]=acc;
        }
        uint2 hp, lp;
        cvt4(o, hp, lp);
        long ei;
        if (pair==0)
            ei = (long)a*65536 + (long)b*2048 + c*4 + p0*32768 + p1*1024;
        else
            ei = (long)(a*64 + p0*32 + b*2 + p1)*1024 + c*4;
        *(uint2*)&dH[ei] = hp;
        *(uint2*)&dL[ei] = lp;
    }
}

// ------------- bf16-split HMMA GEMM, cp.async double-buffered; grid (16, 8) -------------
#define GB_AH 0
#define GB_AL 10240
#define GB_BH 20480
#define GB_BL 25600
#define GB_BUF 30720
#define SMEM_GEMM (2*GB_BUF)

__global__ __launch_bounds__(256) void mma_gemm_kernel(float* __restrict__ psi){
    extern __shared__ __align__(16) __nv_bfloat16 smg[];
    unsigned sb = smem_u32(smg);
    int tid = threadIdx.x, lane = tid&31, w = tid>>5;
    int mrow = (w&3)*32, ncol = (w>>2)*32;
    int m0 = blockIdx.y*128, n0 = blockIdx.x*64;
    const __nv_bfloat16* gAh = (const __nv_bfloat16*)g_A;
    const __nv_bfloat16* gAl = gAh + NS;
    const __nv_bfloat16* gBh = (const __nv_bfloat16*)g_Cm;
    const __nv_bfloat16* gBl = gBh + NS;

    float acc[2][4][4];
    #pragma unroll
    for (int i=0;i<2;i++)
      #pragma unroll
      for (int j=0;j<4;j++)
        #pragma unroll
        for (int q=0;q<4;q++) acc[i][j][q]=0.f;

    int rA0 = (tid)>>2,        kqA0 = (tid&3)*8;
    int rA1 = (tid+256)>>2,    kqA1 = (tid&3)*8;
    int rBt = tid>>2,          kqBt = (tid&3)*8;

    int rA = (lane&7) + ((lane>>3)&1)*8;
    int cAsel = ((lane>>4)&1)*8;
    int rB = (lane&7) + ((lane>>4)&1)*8;
    int cBsel = ((lane>>3)&1)*8;

    {
        unsigned b0 = sb;
        CP16(b0 + GB_AH + (unsigned)(rA0*40+kqA0)*2, gAh + (long)(m0+rA0)*1024 + kqA0);
        CP16(b0 + GB_AH + (unsigned)(rA1*40+kqA1)*2, gAh + (long)(m0+rA1)*1024 + kqA1);
        CP16(b0 + GB_AL + (unsigned)(rA0*40+kqA0)*2, gAl + (long)(m0+rA0)*1024 + kqA0);
        CP16(b0 + GB_AL + (unsigned)(rA1*40+kqA1)*2, gAl + (long)(m0+rA1)*1024 + kqA1);
        CP16(b0 + GB_BH + (unsigned)(rBt*40+kqBt)*2, gBh + (long)(n0+rBt)*1024 + kqBt);
        CP16(b0 + GB_BL + (unsigned)(rBt*40+kqBt)*2, gBl + (long)(n0+rBt)*1024 + kqBt);
        CP_COMMIT();
    }

    for (int ch=0; ch<32; ch++){
        if (ch<31){
            unsigned bn = sb + (unsigned)((ch+1)&1)*GB_BUF;
            int ko = (ch+1)*32;
            CP16(bn + GB_AH + (unsigned)(rA0*40+kqA0)*2, gAh + (long)(m0+rA0)*1024 + ko + kqA0);
            CP16(bn + GB_AH + (unsigned)(rA1*40+kqA1)*2, gAh + (long)(m0+rA1)*1024 + ko + kqA1);
            CP16(bn + GB_AL + (unsigned)(rA0*40+kqA0)*2, gAl + (long)(m0+rA0)*1024 + ko + kqA0);
            CP16(bn + GB_AL + (unsigned)(rA1*40+kqA1)*2, gAl + (long)(m0+rA1)*1024 + ko + kqA1);
            CP16(bn + GB_BH + (unsigned)(rBt*40+kqBt)*2, gBh + (long)(n0+rBt)*1024 + ko + kqBt);
            CP16(bn + GB_BL + (unsigned)(rBt*40+kqBt)*2, gBl + (long)(n0+rBt)*1024 + ko + kqBt);
            CP_COMMIT();
            CP_WAIT1();
        } else {
            CP_WAIT0();
        }
        __syncthreads();
        unsigned bc = sb + (unsigned)(ch&1)*GB_BUF;
        unsigned aH = bc + GB_AH, aL = bc + GB_AL;
        unsigned bH = bc + GB_BH, bL = bc + GB_BL;
        #pragma unroll
        for (int ks=0; ks<2; ks++){
            int colA = ks*16 + cAsel;
            int colB = ks*16 + cBsel;
            unsigned ah[2][4], al[2][4];
            #pragma unroll
            for (int mt=0;mt<2;mt++){
                unsigned offs = (unsigned)(((mrow + mt*16 + rA)*40 + colA)*2);
                LDSM4(ah[mt], aH + offs);
                LDSM4(al[mt], aL + offs);
            }
            unsigned bh[2][4], bl[2][4];
            #pragma unroll
            for (int p=0;p<2;p++){
                unsigned offs = (unsigned)(((ncol + p*16 + rB)*40 + colB)*2);
                LDSM4(bh[p], bH + offs);
                LDSM4(bl[p], bL + offs);
            }
            #pragma unroll
            for (int mt=0;mt<2;mt++)
                #pragma unroll
                for (int nt=0;nt<4;nt++){
                    int p = nt>>1, q = (nt&1)*2;
                    MMA_BF16(acc[mt][nt], ah[mt], bh[p][q], bh[p][q+1]);
                    MMA_BF16(acc[mt][nt], ah[mt], bl[p][q], bl[p][q+1]);
                    MMA_BF16(acc[mt][nt], al[mt], bh[p][q], bh[p][q+1]);
                }
        }
        __syncthreads();
    }
    #pragma unroll
    for (int mt=0;mt<2;mt++){
        #pragma unroll
        for (int nt=0;nt<4;nt++){
            int gr = m0 + mrow + mt*16 + (lane>>2);
            int gc = n0 + ncol + nt*8 + (lane&3)*2;
            *(float2*)&psi[(long)gr*1024 + gc] = make_float2(acc[mt][nt][0], acc[mt][nt][1]);
            *(float2*)&psi[(long)(gr+8)*1024 + gc] = make_float2(acc[mt][nt][2], acc[mt][nt][3]);
        }
    }
}

// ------------- hmode: HMMA hlow — bits [5-9],[0-4] per 1024-slab; grid 128 -------------
__global__ __launch_bounds__(256) void hmode_kernel(float* __restrict__ psi){
    __shared__ __align__(16) __nv_bfloat16 Rh[32*40];
    __shared__ __align__(16) __nv_bfloat16 Rl[32*40];
    __shared__ __align__(16) __nv_bfloat16 Th[8][32*40];
    __shared__ __align__(16) __nv_bfloat16 Tl[8][32*40];
    int tid = threadIdx.x, lane = tid&31, w = tid>>5;
    for (int e=tid;e<1024;e+=256){
        float v = g_R[e];
        __nv_bfloat16 h = __float2bfloat16(v);
        __nv_bfloat16 l = __float2bfloat16(v - __bfloat162float(h));
        Rh[(e>>5)*40 + (e&31)] = h;
        Rl[(e>>5)*40 + (e&31)] = l;
    }
    __syncthreads();
    int h = blockIdx.x*8 + w;
    float* tile = psi + (long)h*1024;
    // load+convert psi tile [i(32)][k(32)]
    #pragma unroll
    for (int q=0;q<8;q++){
        int idx4 = lane + q*32;
        int row = idx4>>3, c0 = (idx4&7)*4;
        float4 v = *(const float4*)&tile[row*32 + c0];
        uint2 hp, lp;
        cvt4(v, hp, lp);
        *(uint2*)&Th[w][row*40 + c0] = hp;
        *(uint2*)&Tl[w][row*40 + c0] = lp;
    }
    __syncwarp();
    unsigned uRh = smem_u32(Rh), uRl = smem_u32(Rl);
    unsigned uTh = smem_u32(&Th[w][0]), uTl = smem_u32(&Tl[w][0]);
    int rA = (lane&7) + ((lane>>3)&1)*8;
    int cAsel = ((lane>>4)&1)*8;
    int rB = (lane&7) + ((lane>>4)&1)*8;
    int cBsel = ((lane>>3)&1)*8;

    // stage 1: T1[i][l'] = tile . R^T   (A=tile rows i, B=R[l'][k])
    float acc[2][4][4];
    #pragma unroll
    for (int i=0;i<2;i++)
      #pragma unroll
      for (int j=0;j<4;j++)
        #pragma unroll
        for (int q=0;q<4;q++) acc[i][j][q]=0.f;
    #pragma unroll
    for (int ks=0; ks<2; ks++){
        int colA = ks*16 + cAsel;
        int colB = ks*16 + cBsel;
        unsigned ah[2][4], al[2][4];
        #pragma unroll
        for (int mt=0;mt<2;mt++){
            unsigned offs = (unsigned)(((mt*16 + rA)*40 + colA)*2);
            LDSM4(ah[mt], uTh + offs);
            LDSM4(al[mt], uTl + offs);
        }
        unsigned bh[2][4], bl[2][4];
        #pragma unroll
        for (int p=0;p<2;p++){
            unsigned offs = (unsigned)(((p*16 + rB)*40 + colB)*2);
            LDSM4(bh[p], uRh + offs);
            LDSM4(bl[p], uRl + offs);
        }
        #pragma unroll
        for (int mt=0;mt<2;mt++)
            #pragma unroll
            for (int nt=0;nt<4;nt++){
                int p = nt>>1, q = (nt&1)*2;
                MMA_BF16(acc[mt][nt], ah[mt], bh[p][q], bh[p][q+1]);
                MMA_BF16(acc[mt][nt], ah[mt], bl[p][q], bl[p][q+1]);
                MMA_BF16(acc[mt][nt], al[mt], bh[p][q], bh[p][q+1]);
            }
    }
    __syncwarp();
    // store T1 transposed [l'][i] as bf16 hi/lo into Th/Tl (reuse)
    #pragma unroll
    for (int mt=0;mt<2;mt++){
        #pragma unroll
        for (int nt=0;nt<4;nt++){
            int i0 = mt*16 + (lane>>2);
            int l0 = nt*8 + (lane&3)*2;
            #pragma unroll
            for (int q=0;q<4;q++){
                float v = acc[mt][nt][q];
                int ii = i0 + (q>>1)*8;
                int ll = l0 + (q&1);
                __nv_bfloat16 hh = __float2bfloat16(v);
                __nv_bfloat16 lo = __float2bfloat16(v - __bfloat162float(hh));
                Th[w][ll*40 + ii] = hh;
                Tl[w][ll*40 + ii] = lo;
            }
        }
    }
    __syncwarp();
    // stage 2: out[o][l'] = R . T1   (A=R[o][i], B=T1t[l'][i])
    #pragma unroll
    for (int i=0;i<2;i++)
      #pragma unroll
      for (int j=0;j<4;j++)
        #pragma unroll
        for (int q=0;q<4;q++) acc[i][j][q]=0.f;
    #pragma unroll
    for (int ks=0; ks<2; ks++){
        int colA = ks*16 + cAsel;
        int colB = ks*16 + cBsel;
        unsigned ah[2][4], al[2][4];
        #pragma unroll
        for (int mt=0;mt<2;mt++){
            unsigned offs = (unsigned)(((mt*16 + rA)*40 + colA)*2);
            LDSM4(ah[mt], uRh + offs);
            LDSM4(al[mt], uRl + offs);
        }
        unsigned bh[2][4], bl[2][4];
        #pragma unroll
        for (int p=0;p<2;p++){
            unsigned offs = (unsigned)(((p*16 + rB)*40 + colB)*2);
            LDSM4(bh[p], uTh + offs);
            LDSM4(bl[p], uTl + offs);
        }
        #pragma unroll
        for (int mt=0;mt<2;mt++)
            #pragma unroll
            for (int nt=0;nt<4;nt++){
                int p = nt>>1, q = (nt&1)*2;
                MMA_BF16(acc[mt][nt], ah[mt], bh[p][q], bh[p][q+1]);
                MMA_BF16(acc[mt][nt], ah[mt], bl[p][q], bl[p][q+1]);
                MMA_BF16(acc[mt][nt], al[mt], bh[p][q], bh[p][q+1]);
            }
    }
    // epilogue: out(o, l') -> psi[h*1024 + o*32 + l']
    #pragma unroll
    for (int mt=0;mt<2;mt++){
        #pragma unroll
        for (int nt=0;nt<4;nt++){
            int o0 = mt*16 + (lane>>2);
            int l0 = nt*8 + (lane&3)*2;
            *(float2*)&tile[o0*32 + l0]     = make_float2(acc[mt][nt][0], acc[mt][nt][1]);
            *(float2*)&tile[(o0+8)*32 + l0] = make_float2(acc[mt][nt][2], acc[mt][nt][3]);
        }
    }
}

// ------------- fused horizontal high: bits [15-19] and [10-14], packed f32x2 -------------
__global__ __launch_bounds__(256) void hhigh_kernel(float* __restrict__ psi){
    __shared__ __align__(16) float S[8][1036];
    __shared__ __align__(16) float Rs[1024];
    __shared__ float RsT[1024];
    int tid = threadIdx.x;
    for (int e=tid;e<1024;e+=256){
        float v = g_R[e];
        Rs[e]=v;
        RsT[(e&31)*32 + (e>>5)] = v;
    }
    unsigned lowbase = blockIdx.x * 8u;
    for (int it=0; it<32; it++){
        int idx = tid + it*256;
        int lo = idx & 7, k = idx >> 3;
        S[lo][k] = psi[(unsigned)k*1024u + lowbase + (unsigned)lo];
    }
    __syncthreads();
    int low = tid & 7, rp = tid >> 3;
    unsigned long long U2[16];
    #pragma unroll
    for (int e=0;e<16;e++) U2[e]=0ull;
    for (int r=0;r<32;r++){
        float rv = RsT[r*32+rp];
        unsigned long long rvp = pk2(rv, rv);
        const ulonglong2* row2 = (const ulonglong2*)&S[low][r*32];
        #pragma unroll
        for (int c2=0;c2<8;c2++){
            ulonglong2 tp = row2[c2];
            U2[c2*2+0] = fma2(rvp, tp.x, U2[c2*2+0]);
            U2[c2*2+1] = fma2(rvp, tp.y, U2[c2*2+1]);
        }
    }
    float W[32];
    #pragma unroll
    for (int cp=0;cp<32;cp++){
        const ulonglong2* Rp2 = (const ulonglong2*)&Rs[cp*32];
        unsigned long long s2 = 0ull;
        #pragma unroll
        for (int c2=0;c2<8;c2++){
            ulonglong2 rr = Rp2[c2];
            s2 = fma2(rr.x, U2[c2*2+0], s2);
            s2 = fma2(rr.y, U2[c2*2+1], s2);
        }
        float2 f = upk2(s2);
        W[cp] = f.x + f.y;
    }
    __syncthreads();
    #pragma unroll
    for (int cp=0;cp<32;cp++) S[low][rp*32+cp] = W[cp];
    __syncthreads();
    for (int it=0; it<32; it++){
        int idx = tid + it*256;
        int lo = idx & 7, k = idx >> 3;
        psi[(unsigned)k*1024u + lowbase + (unsigned)lo] = S[lo][k];
    }
}

// ------------- v_a: columns {0,1,2}; slab bits {0..2,5..7,10..12,15..17}; grid 256 -------------
__global__ __launch_bounds__(256) void va_kernel(float* __restrict__ psi){
    __shared__ float Cs[256];
    __shared__ float S[256*17];
    int t=threadIdx.x;
    Cs[t]=g_C16[t];
    unsigned f = blockIdx.x;   // 8 bits -> addr bits {3,4,8,9,13,14,18,19}
    unsigned base = ((f&3u)<<3) | (((f>>2)&3u)<<8) | (((f>>4)&3u)<<13) | (((f>>6)&3u)<<18);
    __syncthreads();
    #pragma unroll
    for (int it=0; it<16; it++){
        unsigned e = (unsigned)t | ((unsigned)it<<8);   // 12-bit slab idx
        unsigned off = (e&7u) | (((e>>3)&7u)<<5) | (((e>>6)&7u)<<10) | (((e>>9)&7u)<<15);
        int a = (e&1)|((e>>2)&2)|((e>>4)&4)|((e>>6)&8);
        int b = ((e>>1)&1)|((e>>3)&2)|((e>>5)&4)|((e>>7)&8);
        int c = ((e>>2)&1)|((e>>4)&2)|((e>>6)&4)|((e>>8)&8);
        S[(b*16+c)*17 + a] = psi[base + off];
    }
    __syncthreads();
    // stage A: transform a (col 0); thread owns (b*16+c) = t
    {
        float v[16], o[16];
        #pragma unroll
        for (int a=0;a<16;a++) v[a]=S[t*17+a];
        #pragma unroll
        for (int ap=0;ap<16;ap++){
            float acc=0.f;
            #pragma unroll
            for (int a=0;a<16;a++) acc += Cs[ap*16+a]*v[a];
            o[ap]=acc;
        }
        #pragma unroll
        for (int a=0;a<16;a++) S[t*17+a]=o[a];
    }
    __syncthreads();
    // stage B: transform b (col 1)
    {
        int a=t>>4, c=t&15;
        float v[16], o[16];
        #pragma unroll
        for (int b=0;b<16;b++) v[b]=S[(b*16+c)*17 + a];
        #pragma unroll
        for (int bp=0;bp<16;bp++){
            float acc=0.f;
            #pragma unroll
            for (int b=0;b<16;b++) acc += Cs[bp*16+b]*v[b];
            o[bp]=acc;
        }
        #pragma unroll
        for (int b=0;b<16;b++) S[(b*16+c)*17 + a]=o[b];
    }
    __syncthreads();
    // stage C: transform c (col 2)
    {
        int a=t&15, b=t>>4;
        float v[16], o[16];
        #pragma unroll
        for (int c=0;c<16;c++) v[c]=S[(b*16+c)*17 + a];
        #pragma unroll
        for (int cp=0;cp<16;cp++){
            float acc=0.f;
            #pragma unroll
            for (int c=0;c<16;c++) acc += Cs[cp*16+c]*v[c];
            o[cp]=acc;
        }
        #pragma unroll
        for (int c=0;c<16;c++) S[(b*16+c)*17 + a]=o[c];
    }
    __syncthreads();
    #pragma unroll
    for (int it=0; it<16; it++){
        unsigned e = (unsigned)t | ((unsigned)it<<8);
        unsigned off = (e&7u) | (((e>>3)&7u)<<5) | (((e>>6)&7u)<<10) | (((e>>9)&7u)<<15);
        int a = (e&1)|((e>>2)&2)|((e>>4)&4)|((e>>6)&8);
        int b = ((e>>1)&1)|((e>>3)&2)|((e>>5)&4)|((e>>7)&8);
        int c = ((e>>2)&1)|((e>>4)&2)|((e>>6)&4)|((e>>8)&8);
        psi[base + off] = S[(b*16+c)*17 + a];
    }
}

// ------------- v_b: columns {3,4} + spectator bits {0,1,2}; grid 512 -------------
__global__ __launch_bounds__(256) void vb_kernel(float* __restrict__ psi){
    __shared__ float Cs[256];
    __shared__ float S[128*17];
    int t=threadIdx.x;
    Cs[t]=g_C16[t];
    unsigned f = blockIdx.x;   // 9 bits -> addr bits {5,6,7,10,11,12,15,16,17}
    unsigned base = ((f&7u)<<5) | (((f>>3)&7u)<<10) | (((f>>6)&7u)<<15);
    __syncthreads();
    // slab idx e (11 bits): e0..2->addr0..2, e3->3,e4->8,e5->13,e6->18 (d), e7->4,e8->9,e9->14,e10->19 (g)
    #pragma unroll
    for (int it=0; it<8; it++){
        unsigned e = (unsigned)t | ((unsigned)it<<8);
        unsigned off = (e&15u) | (((e>>7)&1u)<<4) | (((e>>4)&1u)<<8) | (((e>>8)&1u)<<9)
                     | (((e>>5)&1u)<<13) | (((e>>9)&1u)<<14) | (((e>>6)&1u)<<18) | (((e>>10)&1u)<<19);
        int s = e&7;
        int d = (e>>3)&15;
        int g = (e>>7)&15;
        S[(g*8+s)*17 + d] = psi[base + off];
    }
    __syncthreads();
    // stage 1: transform d (col 3); fiber = (g,s), 2 threads per fiber
    {
        int fib = t>>1, ob = (t&1)*8;
        float v[16];
        #pragma unroll
        for (int d=0;d<16;d++) v[d]=S[fib*17+d];
        __syncwarp();
        #pragma unroll
        for (int oo=0;oo<8;oo++){
            int o = ob+oo;
            float acc=0.f;
            #pragma unroll
            for (int d=0;d<16;d++) acc += Cs[o*16+d]*v[d];
            S[fib*17+o]=acc;
        }
    }
    __syncthreads();
    // stage 2: transform g (col 4); fiber = (d,s): t = d*16 + s*2 + half
    {
        int d = t>>4, s = (t>>1)&7, half = t&1;
        int ob = half*8;
        float v[16];
        #pragma unroll
        for (int g=0;g<16;g++) v[g]=S[(g*8+s)*17 + d];
        __syncwarp();
        #pragma unroll
        for (int oo=0;oo<8;oo++){
            int go = ob+oo;
            float acc=0.f;
            #pragma unroll
            for (int g=0;g<16;g++) acc += Cs[go*16+g]*v[g];
            S[(go*8+s)*17 + d]=acc;
        }
    }
    __syncthreads();
    #pragma unroll
    for (int it=0; it<8; it++){
        unsigned e = (unsigned)t | ((unsigned)it<<8);
        unsigned off = (e&15u) | (((e>>7)&1u)<<4) | (((e>>4)&1u)<<8) | (((e>>8)&1u)<<9)
                     | (((e>>5)&1u)<<13) | (((e>>9)&1u)<<14) | (((e>>6)&1u)<<18) | (((e>>10)&1u)<<19);
        int s = e&7;
        int d = (e>>3)&15;
        int g = (e>>7)&15;
        psi[base + off] = S[(g*8+s)*17 + d];
    }
}

// ------------- gather 64 amplitudes -------------
__global__ void gather_kernel(const int* __restrict__ x, const float* __restrict__ psi,
                              float* __restrict__ out){
    int b = threadIdx.x;
    unsigned idx=0;
    #pragma unroll
    for (int j=0;j<20;j++) idx = (idx<<1) | (unsigned)x[b*20+j];
    out[b]=psi[idx];
}

extern "C" void kernel_launch(void* const* d_in, const int* in_sizes, int n_in,
                              void* d_out, int out_size){
    const int*   x    = (const int*)d_in[0];
    const float* peps = (const float*)d_in[1];
    const float* gate = (const float*)d_in[2];
    float* out = (float*)d_out;

    float *psi;
    cudaGetSymbolAddress((void**)&psi,  g_psi);

    static int smem_set = 0;
    if (!smem_set){
        cudaFuncSetAttribute(mma_gemm_kernel,
                             cudaFuncAttributeMaxDynamicSharedMemorySize, SMEM_GEMM);
        smem_set = 1;
    }

    prep_kernel<<<11,256>>>(peps, gate);
    fold23_kernel<<<dim3(256,2),256>>>();
    fold4_kernel<<<dim3(256,2),256>>>();

    mma_gemm_kernel<<<dim3(16,8),256,SMEM_GEMM>>>(psi);

    for (int sweep=0; sweep<5; sweep++){
        hhigh_kernel<<<128,256>>>(psi);   // bits [15-19] and [10-14]
        hmode_kernel<<<128,256>>>(psi);   // bits [5-9] and [0-4] on tensor cores
        va_kernel<<<256,256>>>(psi);      // columns 0,1,2
        vb_kernel<<<512,256>>>(psi);      // columns 3,4
    }

    gather_kernel<<<1,64>>>(x, psi, out);
}